// round 1
// baseline (speedup 1.0000x reference)
#include <cuda_runtime.h>
#include <math.h>

#define T_TOT 1154
#define C_DIM 768
#define NHEAD 12
#define NE (T_TOT * C_DIM)

// ---------------- device scratch (no allocations allowed) ----------------
__device__ float g_x[NE];
__device__ float g_loc[NE];
__device__ float g_h[NE];
__device__ float g_qkv[T_TOT * 3 * C_DIM];
__device__ float g_q[NHEAD * T_TOT * 64];
__device__ float g_k[NHEAD * T_TOT * 64];
__device__ float g_v[NHEAD * T_TOT * 64];
__device__ float g_att[NE];
__device__ float g_mlp[T_TOT * 4 * C_DIM];
__device__ float g_tmp[NE];

// ---------------- helpers ----------------
__device__ __forceinline__ float block_sum_256(float v, float* sh) {
    #pragma unroll
    for (int off = 16; off; off >>= 1) v += __shfl_xor_sync(0xffffffffu, v, off);
    __syncthreads();
    if ((threadIdx.x & 31) == 0) sh[threadIdx.x >> 5] = v;
    __syncthreads();
    float r = 0.f;
    #pragma unroll
    for (int i = 0; i < 8; i++) r += sh[i];
    return r;
}

// ---------------- init: copy x, insert camera token ----------------
__global__ void init_x_kernel(const float* __restrict__ xin, const float* __restrict__ cam) {
    int i = blockIdx.x * 256 + threadIdx.x;
    if (i >= NE) return;
    int t = i / C_DIM, c = i - t * C_DIM;
    float v;
    if (t == 0) v = cam[c];
    else if (t == 577) v = cam[C_DIM + c];
    else v = xin[i];
    g_x[i] = v;
}

// ---------------- LayerNorm over 768, block=256, grid=T ----------------
__global__ __launch_bounds__(256) void ln_kernel(const float* __restrict__ x, float* __restrict__ y,
                                                 const float* __restrict__ w, const float* __restrict__ b) {
    __shared__ float sh[8];
    int t = blockIdx.x, tid = threadIdx.x;
    const float* xr = x + (size_t)t * C_DIM;
    float v0 = xr[tid], v1 = xr[tid + 256], v2 = xr[tid + 512];
    float mean = block_sum_256(v0 + v1 + v2, sh) * (1.f / 768.f);
    float d0 = v0 - mean, d1 = v1 - mean, d2 = v2 - mean;
    float var = block_sum_256(d0 * d0 + d1 * d1 + d2 * d2, sh) * (1.f / 768.f);
    float rstd = rsqrtf(var + 1e-6f);
    float* yr = y + (size_t)t * C_DIM;
    yr[tid]       = d0 * rstd * w[tid]       + b[tid];
    yr[tid + 256] = d1 * rstd * w[tid + 256] + b[tid + 256];
    yr[tid + 512] = d2 * rstd * w[tid + 512] + b[tid + 512];
}

// ---------------- GEMM: out[M,Nn] = A[M,K] @ W[Nn,K]^T + bias ; act=1 -> exact GELU
__global__ __launch_bounds__(256) void gemm_kernel(
    const float* __restrict__ A, const float* __restrict__ W,
    const float* __restrict__ bias, float* __restrict__ Cd,
    int M, int Nn, int K, int act)
{
    __shared__ float As[16][132];
    __shared__ float Bs[16][68];
    int bm = blockIdx.y * 128, bn = blockIdx.x * 64;
    int tid = threadIdx.x;
    int tx = tid & 15, ty = tid >> 4;
    float acc[8][4];
    #pragma unroll
    for (int i = 0; i < 8; i++)
        #pragma unroll
        for (int j = 0; j < 4; j++) acc[i][j] = 0.f;

    for (int k0 = 0; k0 < K; k0 += 16) {
        #pragma unroll
        for (int i = 0; i < 2; i++) {
            int idx = tid + i * 256;
            int r = idx >> 2, c4 = (idx & 3) * 4;
            int gr = bm + r;
            float4 va = make_float4(0.f, 0.f, 0.f, 0.f);
            if (gr < M) va = *reinterpret_cast<const float4*>(A + (size_t)gr * K + k0 + c4);
            As[c4 + 0][r] = va.x; As[c4 + 1][r] = va.y; As[c4 + 2][r] = va.z; As[c4 + 3][r] = va.w;
        }
        {
            int r = tid >> 2, c4 = (tid & 3) * 4;
            float4 vb = *reinterpret_cast<const float4*>(W + (size_t)(bn + r) * K + k0 + c4);
            Bs[c4 + 0][r] = vb.x; Bs[c4 + 1][r] = vb.y; Bs[c4 + 2][r] = vb.z; Bs[c4 + 3][r] = vb.w;
        }
        __syncthreads();
        #pragma unroll
        for (int kk = 0; kk < 16; kk++) {
            float4 a0 = *reinterpret_cast<const float4*>(&As[kk][ty * 8]);
            float4 a1 = *reinterpret_cast<const float4*>(&As[kk][ty * 8 + 4]);
            float4 b0 = *reinterpret_cast<const float4*>(&Bs[kk][tx * 4]);
            float a[8] = {a0.x, a0.y, a0.z, a0.w, a1.x, a1.y, a1.z, a1.w};
            float b[4] = {b0.x, b0.y, b0.z, b0.w};
            #pragma unroll
            for (int i = 0; i < 8; i++)
                #pragma unroll
                for (int j = 0; j < 4; j++) acc[i][j] += a[i] * b[j];
        }
        __syncthreads();
    }
    #pragma unroll
    for (int i = 0; i < 8; i++) {
        int gr = bm + ty * 8 + i;
        if (gr >= M) continue;
        #pragma unroll
        for (int j = 0; j < 4; j++) {
            int gc = bn + tx * 4 + j;
            float v = acc[i][j] + bias[gc];
            if (act) v = v * normcdff(v);   // exact GELU: x * Phi(x)
            Cd[(size_t)gr * Nn + gc] = v;
        }
    }
}

// ---------------- QKV post: RMS norm (q,k) + RoPE + 1/sqrt(DH) fold; warp per (t,h)
__global__ void qkvpost_kernel(const float* __restrict__ qkv,
                               const float* __restrict__ qn, const float* __restrict__ kn,
                               const float* __restrict__ rc, const float* __restrict__ rs,
                               float* __restrict__ Q, float* __restrict__ K, float* __restrict__ V,
                               int posmod)
{
    int gw = (blockIdx.x * blockDim.x + threadIdx.x) >> 5;
    int lane = threadIdx.x & 31;
    int t = gw / NHEAD, h = gw - (gw / NHEAD) * NHEAD;
    if (t >= T_TOT) return;
    const float* row = qkv + (size_t)t * 2304 + h * 64;
    float q0 = row[lane],        q1 = row[lane + 32];
    float k0 = row[768 + lane],  k1 = row[768 + lane + 32];
    float v0 = row[1536 + lane], v1 = row[1536 + lane + 32];
    float sq = q0 * q0 + q1 * q1, sk = k0 * k0 + k1 * k1;
    #pragma unroll
    for (int off = 16; off; off >>= 1) {
        sq += __shfl_xor_sync(0xffffffffu, sq, off);
        sk += __shfl_xor_sync(0xffffffffu, sk, off);
    }
    float rq = rsqrtf(sq * (1.f / 64.f) + 1e-6f);
    float rk = rsqrtf(sk * (1.f / 64.f) + 1e-6f);
    q0 *= rq * qn[lane]; q1 *= rq * qn[lane + 32];
    k0 *= rk * kn[lane]; k1 *= rk * kn[lane + 32];
    int pos = t % posmod;
    const float* cr = rc + (size_t)pos * 64;
    const float* sr = rs + (size_t)pos * 64;
    float c0 = cr[lane], c1 = cr[lane + 32];
    float s0 = sr[lane], s1 = sr[lane + 32];
    // rot_half within each 32-half == shfl_xor(16) with sign -1 for lane<16
    float sgn = (lane < 16) ? -1.f : 1.f;
    float qp0 = __shfl_xor_sync(0xffffffffu, q0, 16);
    float qp1 = __shfl_xor_sync(0xffffffffu, q1, 16);
    float kp0 = __shfl_xor_sync(0xffffffffu, k0, 16);
    float kp1 = __shfl_xor_sync(0xffffffffu, k1, 16);
    float qo0 = (q0 * c0 + sgn * qp0 * s0) * 0.125f;  // fold 1/sqrt(64)
    float qo1 = (q1 * c1 + sgn * qp1 * s1) * 0.125f;
    float ko0 = k0 * c0 + sgn * kp0 * s0;
    float ko1 = k1 * c1 + sgn * kp1 * s1;
    size_t base = ((size_t)h * T_TOT + t) * 64;
    Q[base + lane] = qo0; Q[base + 32 + lane] = qo1;
    K[base + lane] = ko0; K[base + 32 + lane] = ko1;
    V[base + lane] = v0;  V[base + 32 + lane] = v1;
}

// ---------------- attention: warp per query, online softmax, 32-key smem tiles
__global__ __launch_bounds__(256) void attn_kernel(
    const float* __restrict__ Q, const float* __restrict__ K,
    const float* __restrict__ V, const float* __restrict__ kvmask,
    float* __restrict__ O, int nq)
{
    __shared__ float Ks[32][65];
    __shared__ float Vs[32][65];
    __shared__ float bS[32];
    int b = blockIdx.z, h = blockIdx.y;
    int warp = threadIdx.x >> 5, lane = threadIdx.x & 31;
    int qi = blockIdx.x * 8 + warp;
    bool active = qi < nq;
    int t0 = b * nq;
    int tq = t0 + (active ? qi : 0);
    size_t qbase = ((size_t)h * T_TOT + tq) * 64;
    float q0 = active ? Q[qbase + lane] : 0.f;
    float q1 = active ? Q[qbase + 32 + lane] : 0.f;
    const float* kvrow = kvmask + (size_t)b * nq;
    float m = -1e30f, l = 0.f, o0 = 0.f, o1 = 0.f;

    for (int j0 = 0; j0 < nq; j0 += 32) {
        for (int i = threadIdx.x; i < 2048; i += 256) {
            int j = i >> 6, d = i & 63;
            int key = j0 + j;
            float kvv = 0.f, vvv = 0.f;
            if (key < nq) {
                size_t kb = ((size_t)h * T_TOT + t0 + key) * 64 + d;
                kvv = K[kb]; vvv = V[kb];
            }
            Ks[j][d] = kvv; Vs[j][d] = vvv;
        }
        if (threadIdx.x < 32) {
            int key = j0 + threadIdx.x;
            bS[threadIdx.x] = (key < nq) ? (1.f - kvrow[key]) * -10000.f : -1e30f;
        }
        __syncthreads();

        float s = bS[lane];
        #pragma unroll
        for (int d = 0; d < 64; d++) {
            float qd = __shfl_sync(0xffffffffu, (d < 32) ? q0 : q1, d & 31);
            s += qd * Ks[lane][d];
        }
        float mt = s;
        #pragma unroll
        for (int off = 16; off; off >>= 1) mt = fmaxf(mt, __shfl_xor_sync(0xffffffffu, mt, off));
        float mnew = fmaxf(m, mt);
        float scale = __expf(m - mnew);
        float p = __expf(s - mnew);
        float ps = p;
        #pragma unroll
        for (int off = 16; off; off >>= 1) ps += __shfl_xor_sync(0xffffffffu, ps, off);
        l = l * scale + ps;
        o0 *= scale; o1 *= scale;
        #pragma unroll
        for (int j = 0; j < 32; j++) {
            float pj = __shfl_sync(0xffffffffu, p, j);
            o0 += pj * Vs[j][lane];
            o1 += pj * Vs[j][lane + 32];
        }
        m = mnew;
        __syncthreads();
    }
    if (active) {
        float inv = 1.f / l;
        size_t ob = (size_t)(t0 + qi) * C_DIM + h * 64;
        O[ob + lane] = o0 * inv;
        O[ob + 32 + lane] = o1 * inv;
    }
}

// ---------------- residual: x += gamma * d ----------------
__global__ void residual_kernel(float* __restrict__ x, const float* __restrict__ d,
                                const float* __restrict__ g) {
    int i = blockIdx.x * 256 + threadIdx.x;
    if (i >= NE) return;
    x[i] += g[i % C_DIM] * d[i];
}

__global__ void copy_kernel(float* __restrict__ dst, const float* __restrict__ src, int n) {
    int i = blockIdx.x * 256 + threadIdx.x;
    if (i < n) dst[i] = src[i];
}

// ---------------- emit output: [local_x | LN(x)] dropping token 0 ----------------
__global__ __launch_bounds__(256) void emit_kernel(const float* __restrict__ xloc, const float* __restrict__ xg,
                                                   const float* __restrict__ fw, const float* __restrict__ fb,
                                                   float* __restrict__ out)
{
    __shared__ float sh[8];
    int row = blockIdx.x;               // 0..1151 = s*576 + (n-1)
    int s = row / 576, n = row - s * 576 + 1;
    int t = s * 577 + n;
    int tid = threadIdx.x;
    const float* xr = xg + (size_t)t * C_DIM;
    float v0 = xr[tid], v1 = xr[tid + 256], v2 = xr[tid + 512];
    float mean = block_sum_256(v0 + v1 + v2, sh) * (1.f / 768.f);
    float d0 = v0 - mean, d1 = v1 - mean, d2 = v2 - mean;
    float var = block_sum_256(d0 * d0 + d1 * d1 + d2 * d2, sh) * (1.f / 768.f);
    float rstd = rsqrtf(var + 1e-6f);
    const float* lr = xloc + (size_t)t * C_DIM;
    float* orow = out + (size_t)row * 1536;
    orow[tid]       = lr[tid];
    orow[tid + 256] = lr[tid + 256];
    orow[tid + 512] = lr[tid + 512];
    orow[768 + tid]       = d0 * rstd * fw[tid]       + fb[tid];
    orow[768 + tid + 256] = d1 * rstd * fw[tid + 256] + fb[tid + 256];
    orow[768 + tid + 512] = d2 * rstd * fw[tid + 512] + fb[tid + 512];
}

// ---------------- cam token out (layer 11, token 0, NO final LN) ----------------
__global__ void cam_kernel(const float* __restrict__ xloc, const float* __restrict__ xg,
                           float* __restrict__ out) {
    int s = blockIdx.x;
    int t = s * 577;
    for (int c = threadIdx.x; c < C_DIM; c += 256) {
        out[s * 1536 + c]       = xloc[(size_t)t * C_DIM + c];
        out[s * 1536 + 768 + c] = xg[(size_t)t * C_DIM + c];
    }
}

// ---------------- host orchestration ----------------
extern "C" void kernel_launch(void* const* d_in, const int* in_sizes, int n_in,
                              void* d_out, int out_size)
{
    const float* x_in  = (const float*)d_in[0];
    const float* rc_l  = (const float*)d_in[1];
    const float* rs_l  = (const float*)d_in[2];
    const float* rc_g  = (const float*)d_in[3];
    const float* rs_g  = (const float*)d_in[4];
    const float* kv_l  = (const float*)d_in[5];
    const float* kv_g  = (const float*)d_in[6];
    const float* cam   = (const float*)d_in[7];
    const float* qkv_w = (const float*)d_in[8];
    const float* qkv_b = (const float*)d_in[9];
    const float* qn_w  = (const float*)d_in[10];
    const float* kn_w  = (const float*)d_in[11];
    const float* pw    = (const float*)d_in[12];
    const float* pb    = (const float*)d_in[13];
    const float* g1    = (const float*)d_in[14];
    const float* g2    = (const float*)d_in[15];
    const float* n1w   = (const float*)d_in[16];
    const float* n1b   = (const float*)d_in[17];
    const float* n2w   = (const float*)d_in[18];
    const float* n2b   = (const float*)d_in[19];
    const float* f1w   = (const float*)d_in[20];
    const float* f1b   = (const float*)d_in[21];
    const float* f2w   = (const float*)d_in[22];
    const float* f2b   = (const float*)d_in[23];
    const float* fnw   = (const float*)d_in[24];
    const float* fnb   = (const float*)d_in[25];
    float* out = (float*)d_out;

    float *p_x, *p_loc, *p_h, *p_qkv, *p_q, *p_k, *p_v, *p_att, *p_mlp, *p_tmp;
    cudaGetSymbolAddress((void**)&p_x,   g_x);
    cudaGetSymbolAddress((void**)&p_loc, g_loc);
    cudaGetSymbolAddress((void**)&p_h,   g_h);
    cudaGetSymbolAddress((void**)&p_qkv, g_qkv);
    cudaGetSymbolAddress((void**)&p_q,   g_q);
    cudaGetSymbolAddress((void**)&p_k,   g_k);
    cudaGetSymbolAddress((void**)&p_v,   g_v);
    cudaGetSymbolAddress((void**)&p_att, g_att);
    cudaGetSymbolAddress((void**)&p_mlp, g_mlp);
    cudaGetSymbolAddress((void**)&p_tmp, g_tmp);

    const int eb = (NE + 255) / 256;
    init_x_kernel<<<eb, 256>>>(x_in, cam);

    int outidx = 0;
    for (int i = 0; i < 12; i++) {
        bool isg = (i & 1);
        int nb = isg ? 1 : 2;
        int nq = isg ? 1154 : 577;
        const float* rc = isg ? rc_g : rc_l;
        const float* rs = isg ? rs_g : rs_l;
        const float* kv = isg ? kv_g : kv_l;

        ln_kernel<<<T_TOT, 256>>>(p_x, p_h, n1w + i * 768, n1b + i * 768);
        gemm_kernel<<<dim3(36, 10), 256>>>(p_h, qkv_w + (size_t)i * 2304 * 768,
                                           qkv_b + (size_t)i * 2304, p_qkv,
                                           T_TOT, 2304, 768, 0);
        qkvpost_kernel<<<(T_TOT * NHEAD * 32 + 127) / 128, 128>>>(
            p_qkv, qn_w + i * 64, kn_w + i * 64, rc, rs, p_q, p_k, p_v, nq);
        attn_kernel<<<dim3((nq + 7) / 8, NHEAD, nb), 256>>>(p_q, p_k, p_v, kv, p_att, nq);
        gemm_kernel<<<dim3(12, 10), 256>>>(p_att, pw + (size_t)i * 768 * 768,
                                           pb + (size_t)i * 768, p_tmp,
                                           T_TOT, 768, 768, 0);
        residual_kernel<<<eb, 256>>>(p_x, p_tmp, g1 + i * 768);

        ln_kernel<<<T_TOT, 256>>>(p_x, p_h, n2w + i * 768, n2b + i * 768);
        gemm_kernel<<<dim3(48, 10), 256>>>(p_h, f1w + (size_t)i * 3072 * 768,
                                           f1b + (size_t)i * 3072, p_mlp,
                                           T_TOT, 3072, 768, 1);
        gemm_kernel<<<dim3(12, 10), 256>>>(p_mlp, f2w + (size_t)i * 768 * 3072,
                                           f2b + (size_t)i * 768, p_tmp,
                                           T_TOT, 768, 3072, 0);
        residual_kernel<<<eb, 256>>>(p_x, p_tmp, g2 + i * 768);

        if (i == 4 || i == 10) copy_kernel<<<eb, 256>>>(p_loc, p_x, NE);

        if (i == 2 || i == 5 || i == 8 || i == 11) {
            const float* loc = (i == 5 || i == 11) ? p_loc : p_x;
            emit_kernel<<<1152, 256>>>(loc, p_x, fnw, fnb, out + (size_t)outidx * 1769472);
            if (i == 11) cam_kernel<<<2, 256>>>(loc, p_x, out + 4ull * 1769472);
            outidx++;
        }
    }
}

// round 3
// speedup vs baseline: 1.1891x; 1.1891x over previous
#include <cuda_runtime.h>
#include <cuda_bf16.h>
#include <math.h>
#include <stdint.h>

#define T_TOT 1154
#define C_DIM 768
#define NHEAD 12
#define NE (T_TOT * C_DIM)

// ---------------- device scratch (no allocations allowed) ----------------
__device__ float g_x[NE];
__device__ float g_loc[NE];
__device__ float g_h[NE];
__device__ float g_qkv[T_TOT * 3 * C_DIM];
__device__ float g_q[NHEAD * T_TOT * 64];
__device__ float g_k[NHEAD * T_TOT * 64];
__device__ float g_v[NHEAD * T_TOT * 64];
__device__ float g_att[NE];
__device__ float g_mlp[T_TOT * 4 * C_DIM];
__device__ float g_tmp[NE];

// ---------------- helpers ----------------
__device__ __forceinline__ float block_sum_256(float v, float* sh) {
    #pragma unroll
    for (int off = 16; off; off >>= 1) v += __shfl_xor_sync(0xffffffffu, v, off);
    __syncthreads();
    if ((threadIdx.x & 31) == 0) sh[threadIdx.x >> 5] = v;
    __syncthreads();
    float r = 0.f;
    #pragma unroll
    for (int i = 0; i < 8; i++) r += sh[i];
    return r;
}

__device__ __forceinline__ uint32_t smem_u32(const void* p) {
    uint32_t a;
    asm("{ .reg .u64 t; cvta.to.shared.u64 t, %1; cvt.u32.u64 %0, t; }" : "=r"(a) : "l"(p));
    return a;
}

__device__ __forceinline__ void ldm4(uint32_t* r, uint32_t addr) {
    asm volatile("ldmatrix.sync.aligned.m8n8.x4.shared.b16 {%0,%1,%2,%3}, [%4];"
                 : "=r"(r[0]), "=r"(r[1]), "=r"(r[2]), "=r"(r[3]) : "r"(addr));
}

__device__ __forceinline__ void mma16816(float* d, const uint32_t* a, uint32_t b0, uint32_t b1) {
    asm volatile(
        "mma.sync.aligned.m16n8k16.row.col.f32.bf16.bf16.f32 "
        "{%0,%1,%2,%3}, {%4,%5,%6,%7}, {%8,%9}, {%0,%1,%2,%3};"
        : "+f"(d[0]), "+f"(d[1]), "+f"(d[2]), "+f"(d[3])
        : "r"(a[0]), "r"(a[1]), "r"(a[2]), "r"(a[3]), "r"(b0), "r"(b1));
}

__device__ __forceinline__ void split4(float4 x, uint2& hv, uint2& lv) {
    __nv_bfloat16 h0 = __float2bfloat16_rn(x.x);
    __nv_bfloat16 h1 = __float2bfloat16_rn(x.y);
    __nv_bfloat16 h2 = __float2bfloat16_rn(x.z);
    __nv_bfloat16 h3 = __float2bfloat16_rn(x.w);
    __nv_bfloat16 l0 = __float2bfloat16_rn(x.x - __bfloat162float(h0));
    __nv_bfloat16 l1 = __float2bfloat16_rn(x.y - __bfloat162float(h1));
    __nv_bfloat16 l2 = __float2bfloat16_rn(x.z - __bfloat162float(h2));
    __nv_bfloat16 l3 = __float2bfloat16_rn(x.w - __bfloat162float(h3));
    hv.x = (uint32_t)__bfloat16_as_ushort(h0) | ((uint32_t)__bfloat16_as_ushort(h1) << 16);
    hv.y = (uint32_t)__bfloat16_as_ushort(h2) | ((uint32_t)__bfloat16_as_ushort(h3) << 16);
    lv.x = (uint32_t)__bfloat16_as_ushort(l0) | ((uint32_t)__bfloat16_as_ushort(l1) << 16);
    lv.y = (uint32_t)__bfloat16_as_ushort(l2) | ((uint32_t)__bfloat16_as_ushort(l3) << 16);
}

// ---------------- init: copy x, insert camera token ----------------
__global__ void init_x_kernel(const float* __restrict__ xin, const float* __restrict__ cam) {
    int i = blockIdx.x * 256 + threadIdx.x;
    if (i >= NE) return;
    int t = i / C_DIM, c = i - t * C_DIM;
    float v;
    if (t == 0) v = cam[c];
    else if (t == 577) v = cam[C_DIM + c];
    else v = xin[i];
    g_x[i] = v;
}

// ---------------- LayerNorm over 768 ----------------
__global__ __launch_bounds__(256) void ln_kernel(const float* __restrict__ x, float* __restrict__ y,
                                                 const float* __restrict__ w, const float* __restrict__ b) {
    __shared__ float sh[8];
    int t = blockIdx.x, tid = threadIdx.x;
    const float* xr = x + (size_t)t * C_DIM;
    float v0 = xr[tid], v1 = xr[tid + 256], v2 = xr[tid + 512];
    float mean = block_sum_256(v0 + v1 + v2, sh) * (1.f / 768.f);
    float d0 = v0 - mean, d1 = v1 - mean, d2 = v2 - mean;
    float var = block_sum_256(d0 * d0 + d1 * d1 + d2 * d2, sh) * (1.f / 768.f);
    float rstd = rsqrtf(var + 1e-6f);
    float* yr = y + (size_t)t * C_DIM;
    yr[tid]       = d0 * rstd * w[tid]       + b[tid];
    yr[tid + 256] = d1 * rstd * w[tid + 256] + b[tid + 256];
    yr[tid + 512] = d2 * rstd * w[tid + 512] + b[tid + 512];
}

// ---------------- mma.sync split-bf16 GEMM ----------------
// out[M,Nn] = A[M,K] @ W[Nn,K]^T + bias ; act=1 -> exact GELU.
// CTA tile 128x128, K chunks of 32. 3-term bf16 split (hi*hi + hi*lo + lo*hi), fp32 accum.
// Smem tiles have 40-element (80B) row stride -> conflict-free ldmatrix.
#define SM_STRIDE 40
#define AH_OFF 0
#define AL_OFF 5120
#define BH_OFF 10240
#define BL_OFF 15360

__global__ __launch_bounds__(256) void gemm_mma(
    const float* __restrict__ A, const float* __restrict__ W,
    const float* __restrict__ bias, float* __restrict__ Cd,
    int M, int Nn, int K, int act)
{
    __shared__ __align__(16) uint16_t sm[20480];   // 40KB
    const int tid = threadIdx.x;
    const int wid = tid >> 5, lane = tid & 31;
    const int warpM = wid >> 1, warpN = wid & 1;
    const int bm = blockIdx.y * 128, bn = blockIdx.x * 128;
    const uint32_t sbase = smem_u32(sm);

    float acc[2][8][4];
    #pragma unroll
    for (int i = 0; i < 2; i++)
        #pragma unroll
        for (int j = 0; j < 8; j++)
            #pragma unroll
            for (int k = 0; k < 4; k++) acc[i][j][k] = 0.f;

    // per-lane ldmatrix address components
    const int a_row = warpM * 32 + (lane & 15);         // + mt*16
    const int a_kc  = (lane >> 4) * 8;                  // + ks*16
    const int b_row = warpN * 64 + ((lane >> 4) & 1) * 8 + (lane & 7);  // + bt*16
    const int b_kc  = ((lane >> 3) & 1) * 8;            // + ks*16

    const int NC = K >> 5;
    for (int c = 0; c < NC; c++) {
        const int k0 = c << 5;
        // load + split A tile (128 x 32 floats = 1024 float4)
        #pragma unroll
        for (int i = 0; i < 4; i++) {
            int idx = tid + (i << 8);
            int r = idx >> 3, c4 = idx & 7;
            int gr = bm + r;
            float4 x = make_float4(0.f, 0.f, 0.f, 0.f);
            if (gr < M) x = *(const float4*)(A + (size_t)gr * K + k0 + (c4 << 2));
            uint2 hv, lv;
            split4(x, hv, lv);
            int off = r * SM_STRIDE + (c4 << 2);
            *(uint2*)(sm + AH_OFF + off) = hv;
            *(uint2*)(sm + AL_OFF + off) = lv;
        }
        // load + split B tile (128 x 32 floats)
        #pragma unroll
        for (int i = 0; i < 4; i++) {
            int idx = tid + (i << 8);
            int r = idx >> 3, c4 = idx & 7;
            float4 x = *(const float4*)(W + (size_t)(bn + r) * K + k0 + (c4 << 2));
            uint2 hv, lv;
            split4(x, hv, lv);
            int off = r * SM_STRIDE + (c4 << 2);
            *(uint2*)(sm + BH_OFF + off) = hv;
            *(uint2*)(sm + BL_OFF + off) = lv;
        }
        __syncthreads();

        #pragma unroll
        for (int ks = 0; ks < 2; ks++) {
            uint32_t ah[2][4], al[2][4], bb[4][4];
            #pragma unroll
            for (int mt = 0; mt < 2; mt++) {
                uint32_t off = (uint32_t)((a_row + mt * 16) * SM_STRIDE + ks * 16 + a_kc) * 2;
                ldm4(ah[mt], sbase + AH_OFF * 2 + off);
                ldm4(al[mt], sbase + AL_OFF * 2 + off);
            }
            // term 1+2: (Ah,Bh) and (Al,Bh)
            #pragma unroll
            for (int bt = 0; bt < 4; bt++) {
                uint32_t off = (uint32_t)((b_row + bt * 16) * SM_STRIDE + ks * 16 + b_kc) * 2;
                ldm4(bb[bt], sbase + BH_OFF * 2 + off);
            }
            #pragma unroll
            for (int mt = 0; mt < 2; mt++)
                #pragma unroll
                for (int nt = 0; nt < 8; nt++) {
                    mma16816(acc[mt][nt], ah[mt], bb[nt >> 1][(nt & 1) * 2], bb[nt >> 1][(nt & 1) * 2 + 1]);
                    mma16816(acc[mt][nt], al[mt], bb[nt >> 1][(nt & 1) * 2], bb[nt >> 1][(nt & 1) * 2 + 1]);
                }
            // term 3: (Ah,Bl)
            #pragma unroll
            for (int bt = 0; bt < 4; bt++) {
                uint32_t off = (uint32_t)((b_row + bt * 16) * SM_STRIDE + ks * 16 + b_kc) * 2;
                ldm4(bb[bt], sbase + BL_OFF * 2 + off);
            }
            #pragma unroll
            for (int mt = 0; mt < 2; mt++)
                #pragma unroll
                for (int nt = 0; nt < 8; nt++)
                    mma16816(acc[mt][nt], ah[mt], bb[nt >> 1][(nt & 1) * 2], bb[nt >> 1][(nt & 1) * 2 + 1]);
        }
        __syncthreads();
    }

    // epilogue: direct stores with bias (+ optional exact GELU)
    #pragma unroll
    for (int mt = 0; mt < 2; mt++) {
        int r0 = bm + warpM * 32 + mt * 16 + (lane >> 2);
        int r1 = r0 + 8;
        #pragma unroll
        for (int nt = 0; nt < 8; nt++) {
            int col = bn + warpN * 64 + nt * 8 + ((lane & 3) << 1);
            float b0 = bias[col], b1 = bias[col + 1];
            if (r0 < M) {
                float v0 = acc[mt][nt][0] + b0;
                float v1 = acc[mt][nt][1] + b1;
                if (act) { v0 = v0 * normcdff(v0); v1 = v1 * normcdff(v1); }
                Cd[(size_t)r0 * Nn + col]     = v0;
                Cd[(size_t)r0 * Nn + col + 1] = v1;
            }
            if (r1 < M) {
                float v2 = acc[mt][nt][2] + b0;
                float v3 = acc[mt][nt][3] + b1;
                if (act) { v2 = v2 * normcdff(v2); v3 = v3 * normcdff(v3); }
                Cd[(size_t)r1 * Nn + col]     = v2;
                Cd[(size_t)r1 * Nn + col + 1] = v3;
            }
        }
    }
}

// ---------------- QKV post: RMS norm (q,k) + RoPE + 1/sqrt(DH) fold ----------------
__global__ void qkvpost_kernel(const float* __restrict__ qkv,
                               const float* __restrict__ qn, const float* __restrict__ kn,
                               const float* __restrict__ rc, const float* __restrict__ rs,
                               float* __restrict__ Q, float* __restrict__ K, float* __restrict__ V,
                               int posmod)
{
    int gw = (blockIdx.x * blockDim.x + threadIdx.x) >> 5;
    int lane = threadIdx.x & 31;
    int t = gw / NHEAD, h = gw - (gw / NHEAD) * NHEAD;
    if (t >= T_TOT) return;
    const float* row = qkv + (size_t)t * 2304 + h * 64;
    float q0 = row[lane],        q1 = row[lane + 32];
    float k0 = row[768 + lane],  k1 = row[768 + lane + 32];
    float v0 = row[1536 + lane], v1 = row[1536 + lane + 32];
    float sq = q0 * q0 + q1 * q1, sk = k0 * k0 + k1 * k1;
    #pragma unroll
    for (int off = 16; off; off >>= 1) {
        sq += __shfl_xor_sync(0xffffffffu, sq, off);
        sk += __shfl_xor_sync(0xffffffffu, sk, off);
    }
    float rq = rsqrtf(sq * (1.f / 64.f) + 1e-6f);
    float rk = rsqrtf(sk * (1.f / 64.f) + 1e-6f);
    q0 *= rq * qn[lane]; q1 *= rq * qn[lane + 32];
    k0 *= rk * kn[lane]; k1 *= rk * kn[lane + 32];
    int pos = t % posmod;
    const float* cr = rc + (size_t)pos * 64;
    const float* sr = rs + (size_t)pos * 64;
    float c0 = cr[lane], c1 = cr[lane + 32];
    float s0 = sr[lane], s1 = sr[lane + 32];
    float sgn = (lane < 16) ? -1.f : 1.f;
    float qp0 = __shfl_xor_sync(0xffffffffu, q0, 16);
    float qp1 = __shfl_xor_sync(0xffffffffu, q1, 16);
    float kp0 = __shfl_xor_sync(0xffffffffu, k0, 16);
    float kp1 = __shfl_xor_sync(0xffffffffu, k1, 16);
    float qo0 = (q0 * c0 + sgn * qp0 * s0) * 0.125f;
    float qo1 = (q1 * c1 + sgn * qp1 * s1) * 0.125f;
    float ko0 = k0 * c0 + sgn * kp0 * s0;
    float ko1 = k1 * c1 + sgn * kp1 * s1;
    size_t base = ((size_t)h * T_TOT + t) * 64;
    Q[base + lane] = qo0; Q[base + 32 + lane] = qo1;
    K[base + lane] = ko0; K[base + 32 + lane] = ko1;
    V[base + lane] = v0;  V[base + 32 + lane] = v1;
}

// ---------------- attention: warp per query, online softmax ----------------
__global__ __launch_bounds__(256) void attn_kernel(
    const float* __restrict__ Q, const float* __restrict__ K,
    const float* __restrict__ V, const float* __restrict__ kvmask,
    float* __restrict__ O, int nq)
{
    __shared__ float Ks[32][65];
    __shared__ float Vs[32][65];
    __shared__ float bS[32];
    int b = blockIdx.z, h = blockIdx.y;
    int warp = threadIdx.x >> 5, lane = threadIdx.x & 31;
    int qi = blockIdx.x * 8 + warp;
    bool active = qi < nq;
    int t0 = b * nq;
    int tq = t0 + (active ? qi : 0);
    size_t qbase = ((size_t)h * T_TOT + tq) * 64;
    float q0 = active ? Q[qbase + lane] : 0.f;
    float q1 = active ? Q[qbase + 32 + lane] : 0.f;
    const float* kvrow = kvmask + (size_t)b * nq;
    float m = -1e30f, l = 0.f, o0 = 0.f, o1 = 0.f;

    for (int j0 = 0; j0 < nq; j0 += 32) {
        for (int i = threadIdx.x; i < 2048; i += 256) {
            int j = i >> 6, d = i & 63;
            int key = j0 + j;
            float kvv = 0.f, vvv = 0.f;
            if (key < nq) {
                size_t kb = ((size_t)h * T_TOT + t0 + key) * 64 + d;
                kvv = K[kb]; vvv = V[kb];
            }
            Ks[j][d] = kvv; Vs[j][d] = vvv;
        }
        if (threadIdx.x < 32) {
            int key = j0 + threadIdx.x;
            bS[threadIdx.x] = (key < nq) ? (1.f - kvrow[key]) * -10000.f : -1e30f;
        }
        __syncthreads();

        float s = bS[lane];
        #pragma unroll
        for (int d = 0; d < 64; d++) {
            float qd = __shfl_sync(0xffffffffu, (d < 32) ? q0 : q1, d & 31);
            s += qd * Ks[lane][d];
        }
        float mt = s;
        #pragma unroll
        for (int off = 16; off; off >>= 1) mt = fmaxf(mt, __shfl_xor_sync(0xffffffffu, mt, off));
        float mnew = fmaxf(m, mt);
        float scale = __expf(m - mnew);
        float p = __expf(s - mnew);
        float ps = p;
        #pragma unroll
        for (int off = 16; off; off >>= 1) ps += __shfl_xor_sync(0xffffffffu, ps, off);
        l = l * scale + ps;
        o0 *= scale; o1 *= scale;
        #pragma unroll
        for (int j = 0; j < 32; j++) {
            float pj = __shfl_sync(0xffffffffu, p, j);
            o0 += pj * Vs[j][lane];
            o1 += pj * Vs[j][lane + 32];
        }
        m = mnew;
        __syncthreads();
    }
    if (active) {
        float inv = 1.f / l;
        size_t ob = (size_t)(t0 + qi) * C_DIM + h * 64;
        O[ob + lane] = o0 * inv;
        O[ob + 32 + lane] = o1 * inv;
    }
}

// ---------------- residual: x += gamma * d ----------------
__global__ void residual_kernel(float* __restrict__ x, const float* __restrict__ d,
                                const float* __restrict__ g) {
    int i = blockIdx.x * 256 + threadIdx.x;
    if (i >= NE) return;
    x[i] += g[i % C_DIM] * d[i];
}

__global__ void copy_kernel(float* __restrict__ dst, const float* __restrict__ src, int n) {
    int i = blockIdx.x * 256 + threadIdx.x;
    if (i < n) dst[i] = src[i];
}

// ---------------- emit output: [local_x | LN(x)] dropping token 0 ----------------
__global__ __launch_bounds__(256) void emit_kernel(const float* __restrict__ xloc, const float* __restrict__ xg,
                                                   const float* __restrict__ fw, const float* __restrict__ fb,
                                                   float* __restrict__ out)
{
    __shared__ float sh[8];
    int row = blockIdx.x;
    int s = row / 576, n = row - s * 576 + 1;
    int t = s * 577 + n;
    int tid = threadIdx.x;
    const float* xr = xg + (size_t)t * C_DIM;
    float v0 = xr[tid], v1 = xr[tid + 256], v2 = xr[tid + 512];
    float mean = block_sum_256(v0 + v1 + v2, sh) * (1.f / 768.f);
    float d0 = v0 - mean, d1 = v1 - mean, d2 = v2 - mean;
    float var = block_sum_256(d0 * d0 + d1 * d1 + d2 * d2, sh) * (1.f / 768.f);
    float rstd = rsqrtf(var + 1e-6f);
    const float* lr = xloc + (size_t)t * C_DIM;
    float* orow = out + (size_t)row * 1536;
    orow[tid]       = lr[tid];
    orow[tid + 256] = lr[tid + 256];
    orow[tid + 512] = lr[tid + 512];
    orow[768 + tid]       = d0 * rstd * fw[tid]       + fb[tid];
    orow[768 + tid + 256] = d1 * rstd * fw[tid + 256] + fb[tid + 256];
    orow[768 + tid + 512] = d2 * rstd * fw[tid + 512] + fb[tid + 512];
}

// ---------------- cam token out ----------------
__global__ void cam_kernel(const float* __restrict__ xloc, const float* __restrict__ xg,
                           float* __restrict__ out) {
    int s = blockIdx.x;
    int t = s * 577;
    for (int c = threadIdx.x; c < C_DIM; c += 256) {
        out[s * 1536 + c]       = xloc[(size_t)t * C_DIM + c];
        out[s * 1536 + 768 + c] = xg[(size_t)t * C_DIM + c];
    }
}

// ---------------- host orchestration ----------------
extern "C" void kernel_launch(void* const* d_in, const int* in_sizes, int n_in,
                              void* d_out, int out_size)
{
    const float* x_in  = (const float*)d_in[0];
    const float* rc_l  = (const float*)d_in[1];
    const float* rs_l  = (const float*)d_in[2];
    const float* rc_g  = (const float*)d_in[3];
    const float* rs_g  = (const float*)d_in[4];
    const float* kv_l  = (const float*)d_in[5];
    const float* kv_g  = (const float*)d_in[6];
    const float* cam   = (const float*)d_in[7];
    const float* qkv_w = (const float*)d_in[8];
    const float* qkv_b = (const float*)d_in[9];
    const float* qn_w  = (const float*)d_in[10];
    const float* kn_w  = (const float*)d_in[11];
    const float* pw    = (const float*)d_in[12];
    const float* pb    = (const float*)d_in[13];
    const float* g1    = (const float*)d_in[14];
    const float* g2    = (const float*)d_in[15];
    const float* n1w   = (const float*)d_in[16];
    const float* n1b   = (const float*)d_in[17];
    const float* n2w   = (const float*)d_in[18];
    const float* n2b   = (const float*)d_in[19];
    const float* f1w   = (const float*)d_in[20];
    const float* f1b   = (const float*)d_in[21];
    const float* f2w   = (const float*)d_in[22];
    const float* f2b   = (const float*)d_in[23];
    const float* fnw   = (const float*)d_in[24];
    const float* fnb   = (const float*)d_in[25];
    float* out = (float*)d_out;

    float *p_x, *p_loc, *p_h, *p_qkv, *p_q, *p_k, *p_v, *p_att, *p_mlp, *p_tmp;
    cudaGetSymbolAddress((void**)&p_x,   g_x);
    cudaGetSymbolAddress((void**)&p_loc, g_loc);
    cudaGetSymbolAddress((void**)&p_h,   g_h);
    cudaGetSymbolAddress((void**)&p_qkv, g_qkv);
    cudaGetSymbolAddress((void**)&p_q,   g_q);
    cudaGetSymbolAddress((void**)&p_k,   g_k);
    cudaGetSymbolAddress((void**)&p_v,   g_v);
    cudaGetSymbolAddress((void**)&p_att, g_att);
    cudaGetSymbolAddress((void**)&p_mlp, g_mlp);
    cudaGetSymbolAddress((void**)&p_tmp, g_tmp);

    const int eb = (NE + 255) / 256;
    init_x_kernel<<<eb, 256>>>(x_in, cam);

    int outidx = 0;
    for (int i = 0; i < 12; i++) {
        bool isg = (i & 1);
        int nb = isg ? 1 : 2;
        int nq = isg ? 1154 : 577;
        const float* rc = isg ? rc_g : rc_l;
        const float* rs = isg ? rs_g : rs_l;
        const float* kv = isg ? kv_g : kv_l;

        ln_kernel<<<T_TOT, 256>>>(p_x, p_h, n1w + i * 768, n1b + i * 768);
        gemm_mma<<<dim3(18, 10), 256>>>(p_h, qkv_w + (size_t)i * 2304 * 768,
                                        qkv_b + (size_t)i * 2304, p_qkv,
                                        T_TOT, 2304, 768, 0);
        qkvpost_kernel<<<(T_TOT * NHEAD * 32 + 127) / 128, 128>>>(
            p_qkv, qn_w + i * 64, kn_w + i * 64, rc, rs, p_q, p_k, p_v, nq);
        attn_kernel<<<dim3((nq + 7) / 8, NHEAD, nb), 256>>>(p_q, p_k, p_v, kv, p_att, nq);
        gemm_mma<<<dim3(6, 10), 256>>>(p_att, pw + (size_t)i * 768 * 768,
                                       pb + (size_t)i * 768, p_tmp,
                                       T_TOT, 768, 768, 0);
        residual_kernel<<<eb, 256>>>(p_x, p_tmp, g1 + i * 768);

        ln_kernel<<<T_TOT, 256>>>(p_x, p_h, n2w + i * 768, n2b + i * 768);
        gemm_mma<<<dim3(24, 10), 256>>>(p_h, f1w + (size_t)i * 3072 * 768,
                                        f1b + (size_t)i * 3072, p_mlp,
                                        T_TOT, 3072, 768, 1);
        gemm_mma<<<dim3(6, 10), 256>>>(p_mlp, f2w + (size_t)i * 768 * 3072,
                                       f2b + (size_t)i * 768, p_tmp,
                                       T_TOT, 768, 3072, 0);
        residual_kernel<<<eb, 256>>>(p_x, p_tmp, g2 + i * 768);

        if (i == 4 || i == 10) copy_kernel<<<eb, 256>>>(p_loc, p_x, NE);

        if (i == 2 || i == 5 || i == 8 || i == 11) {
            const float* loc = (i == 5 || i == 11) ? p_loc : p_x;
            emit_kernel<<<1152, 256>>>(loc, p_x, fnw, fnb, out + (size_t)outidx * 1769472);
            if (i == 11) cam_kernel<<<2, 256>>>(loc, p_x, out + 4ull * 1769472);
            outidx++;
        }
    }
}

// round 4
// speedup vs baseline: 1.4001x; 1.1775x over previous
#include <cuda_runtime.h>
#include <cuda_bf16.h>
#include <math.h>
#include <stdint.h>

#define T_TOT 1154
#define C_DIM 768
#define NHEAD 12
#define NE (T_TOT * C_DIM)

// weight split offsets (elements)
#define W_QKV_OFF 0
#define W_PROJ_OFF 21233664         // 12*2304*768
#define W_FC1_OFF  28311552         // + 12*768*768
#define W_FC2_OFF  56623104         // + 12*3072*768
#define W_TOTAL    84934656         // + 12*768*3072

// ---------------- device scratch (no allocations allowed) ----------------
__device__ float g_x[NE];
__device__ float g_loc[NE];
__device__ float g_qkv[T_TOT * 3 * C_DIM];
__device__ float g_q[NHEAD * T_TOT * 64];
__device__ float g_k[NHEAD * T_TOT * 64];
__device__ float g_v[NHEAD * T_TOT * 64];
__device__ __nv_bfloat16 g_wh[W_TOTAL];
__device__ __nv_bfloat16 g_wl[W_TOTAL];
__device__ __nv_bfloat16 g_sh[NE];
__device__ __nv_bfloat16 g_sl[NE];
__device__ __nv_bfloat16 g_mh[NE * 4];
__device__ __nv_bfloat16 g_ml[NE * 4];

// ---------------- helpers ----------------
__device__ __forceinline__ float block_sum_256(float v, float* sh) {
    #pragma unroll
    for (int off = 16; off; off >>= 1) v += __shfl_xor_sync(0xffffffffu, v, off);
    __syncthreads();
    if ((threadIdx.x & 31) == 0) sh[threadIdx.x >> 5] = v;
    __syncthreads();
    float r = 0.f;
    #pragma unroll
    for (int i = 0; i < 8; i++) r += sh[i];
    return r;
}

__device__ __forceinline__ uint32_t smem_u32(const void* p) {
    uint32_t a;
    asm("{ .reg .u64 t; cvta.to.shared.u64 t, %1; cvt.u32.u64 %0, t; }" : "=r"(a) : "l"(p));
    return a;
}

__device__ __forceinline__ void ldm4(uint32_t* r, uint32_t addr) {
    asm volatile("ldmatrix.sync.aligned.m8n8.x4.shared.b16 {%0,%1,%2,%3}, [%4];"
                 : "=r"(r[0]), "=r"(r[1]), "=r"(r[2]), "=r"(r[3]) : "r"(addr));
}

__device__ __forceinline__ void mma16816(float* d, const uint32_t* a, uint32_t b0, uint32_t b1) {
    asm volatile(
        "mma.sync.aligned.m16n8k16.row.col.f32.bf16.bf16.f32 "
        "{%0,%1,%2,%3}, {%4,%5,%6,%7}, {%8,%9}, {%0,%1,%2,%3};"
        : "+f"(d[0]), "+f"(d[1]), "+f"(d[2]), "+f"(d[3])
        : "r"(a[0]), "r"(a[1]), "r"(a[2]), "r"(a[3]), "r"(b0), "r"(b1));
}

__device__ __forceinline__ uint32_t pack_bf2(float a, float b) {
    __nv_bfloat16 ha = __float2bfloat16_rn(a), hb = __float2bfloat16_rn(b);
    return (uint32_t)__bfloat16_as_ushort(ha) | ((uint32_t)__bfloat16_as_ushort(hb) << 16);
}

// ---------------- weight/activation split conversion ----------------
__global__ void conv_kernel(const float* __restrict__ src,
                            __nv_bfloat16* __restrict__ dh, __nv_bfloat16* __restrict__ dl, int n4) {
    int i = blockIdx.x * 256 + threadIdx.x;
    if (i >= n4) return;
    float4 x = ((const float4*)src)[i];
    __nv_bfloat16 h0 = __float2bfloat16_rn(x.x), h1 = __float2bfloat16_rn(x.y);
    __nv_bfloat16 h2 = __float2bfloat16_rn(x.z), h3 = __float2bfloat16_rn(x.w);
    uint2 hv, lv;
    hv.x = (uint32_t)__bfloat16_as_ushort(h0) | ((uint32_t)__bfloat16_as_ushort(h1) << 16);
    hv.y = (uint32_t)__bfloat16_as_ushort(h2) | ((uint32_t)__bfloat16_as_ushort(h3) << 16);
    lv.x = pack_bf2(x.x - __bfloat162float(h0), x.y - __bfloat162float(h1));
    lv.y = pack_bf2(x.z - __bfloat162float(h2), x.w - __bfloat162float(h3));
    ((uint2*)dh)[i] = hv;
    ((uint2*)dl)[i] = lv;
}

// ---------------- init: copy x, insert camera token ----------------
__global__ void init_x_kernel(const float* __restrict__ xin, const float* __restrict__ cam) {
    int i = blockIdx.x * 256 + threadIdx.x;
    if (i >= NE) return;
    int t = i / C_DIM, c = i - t * C_DIM;
    float v;
    if (t == 0) v = cam[c];
    else if (t == 577) v = cam[C_DIM + c];
    else v = xin[i];
    g_x[i] = v;
}

// ---------------- LayerNorm over 768, emits split bf16 ----------------
__global__ __launch_bounds__(256) void ln_kernel(const float* __restrict__ x,
                                                 __nv_bfloat16* __restrict__ yh, __nv_bfloat16* __restrict__ yl,
                                                 const float* __restrict__ w, const float* __restrict__ b) {
    __shared__ float sh[8];
    int t = blockIdx.x, tid = threadIdx.x;
    const float* xr = x + (size_t)t * C_DIM;
    float v0 = xr[tid], v1 = xr[tid + 256], v2 = xr[tid + 512];
    float mean = block_sum_256(v0 + v1 + v2, sh) * (1.f / 768.f);
    float d0 = v0 - mean, d1 = v1 - mean, d2 = v2 - mean;
    float var = block_sum_256(d0 * d0 + d1 * d1 + d2 * d2, sh) * (1.f / 768.f);
    float rstd = rsqrtf(var + 1e-6f);
    float o0 = d0 * rstd * w[tid]       + b[tid];
    float o1 = d1 * rstd * w[tid + 256] + b[tid + 256];
    float o2 = d2 * rstd * w[tid + 512] + b[tid + 512];
    size_t base = (size_t)t * C_DIM + tid;
    __nv_bfloat16 h0 = __float2bfloat16_rn(o0);
    __nv_bfloat16 h1 = __float2bfloat16_rn(o1);
    __nv_bfloat16 h2 = __float2bfloat16_rn(o2);
    yh[base] = h0;       yl[base]       = __float2bfloat16_rn(o0 - __bfloat162float(h0));
    yh[base + 256] = h1; yl[base + 256] = __float2bfloat16_rn(o1 - __bfloat162float(h1));
    yh[base + 512] = h2; yl[base + 512] = __float2bfloat16_rn(o2 - __bfloat162float(h2));
}

// ---------------- mma.sync split-bf16 GEMM, cp.async double-buffered ----------------
// out[M,Nn] = A[M,K] @ W[Nn,K]^T + bias
// inputs pre-split bf16 (hi/lo). 3 terms: Ah*Bh + Al*Bh + Ah*Bl, fp32 accum.
// modes: Ch!=0 -> split bf16 out (with optional GELU); gamma!=0 -> xres += gamma*(acc+bias); else fp32 Cf.
#define SM_STRIDE 40
#define STAGE_ELE 20480    // 4 matrices * 5120 elems
#define GEMM_SMEM 81920    // 2 stages * 20480 * 2B

__global__ __launch_bounds__(256) void gemm_mma(
    const __nv_bfloat16* __restrict__ Ah, const __nv_bfloat16* __restrict__ Al,
    const __nv_bfloat16* __restrict__ Wh, const __nv_bfloat16* __restrict__ Wl,
    const float* __restrict__ bias,
    float* __restrict__ Cf, __nv_bfloat16* __restrict__ Ch, __nv_bfloat16* __restrict__ Cl,
    const float* __restrict__ gamma, float* __restrict__ xres,
    int M, int Nn, int K, int act)
{
    extern __shared__ __align__(16) uint16_t sm[];
    const int tid = threadIdx.x;
    const int wid = tid >> 5, lane = tid & 31;
    const int warpM = wid >> 1, warpN = wid & 1;
    const int bm = blockIdx.y * 128, bn = blockIdx.x * 128;
    const uint32_t sbase = smem_u32(sm);

    float acc[2][8][4];
    #pragma unroll
    for (int i = 0; i < 2; i++)
        #pragma unroll
        for (int j = 0; j < 8; j++)
            #pragma unroll
            for (int k = 0; k < 4; k++) acc[i][j][k] = 0.f;

    const int a_row = warpM * 32 + (lane & 15);
    const int a_kc  = (lane >> 4) * 8;
    const int b_row = warpN * 64 + ((lane >> 4) & 1) * 8 + (lane & 7);
    const int b_kc  = ((lane >> 3) & 1) * 8;

    const int NC = K >> 5;

    // async loader for chunk c into stage c&1
    auto issue = [&](int c) {
        const int s = c & 1, k0 = c << 5;
        const uint32_t sb = sbase + (uint32_t)s * (STAGE_ELE * 2);
        #pragma unroll
        for (int it = 0; it < 8; it++) {
            int tsk = tid + (it << 8);
            int mat = tsk >> 9;
            int v = tsk & 511;
            int r = v >> 2, seg = (v & 3) << 3;
            uint32_t sa = sb + (uint32_t)(mat * 5120 + r * SM_STRIDE + seg) * 2;
            const __nv_bfloat16* gp;
            int sz = 16;
            if (mat < 2) {
                int gr = bm + r;
                gp = (mat == 0 ? Ah : Al) + (size_t)gr * K + k0 + seg;
                if (gr >= M) sz = 0;
            } else {
                gp = (mat == 2 ? Wh : Wl) + (size_t)(bn + r) * K + k0 + seg;
            }
            asm volatile("cp.async.cg.shared.global [%0], [%1], 16, %2;"
                         :: "r"(sa), "l"(gp), "r"(sz));
        }
        asm volatile("cp.async.commit_group;" ::: "memory");
    };

    issue(0);
    for (int c = 0; c < NC; c++) {
        if (c + 1 < NC) {
            issue(c + 1);
            asm volatile("cp.async.wait_group 1;" ::: "memory");
        } else {
            asm volatile("cp.async.wait_group 0;" ::: "memory");
        }
        __syncthreads();

        const uint32_t st = sbase + (uint32_t)(c & 1) * (STAGE_ELE * 2);
        #pragma unroll
        for (int ks = 0; ks < 2; ks++) {
            uint32_t ah[2][4], al[2][4], bb[4][4];
            #pragma unroll
            for (int mt = 0; mt < 2; mt++) {
                uint32_t off = (uint32_t)((a_row + mt * 16) * SM_STRIDE + ks * 16 + a_kc) * 2;
                ldm4(ah[mt], st + off);
                ldm4(al[mt], st + 10240 + off);
            }
            #pragma unroll
            for (int bt = 0; bt < 4; bt++) {
                uint32_t off = (uint32_t)((b_row + bt * 16) * SM_STRIDE + ks * 16 + b_kc) * 2;
                ldm4(bb[bt], st + 20480 + off);
            }
            #pragma unroll
            for (int mt = 0; mt < 2; mt++)
                #pragma unroll
                for (int nt = 0; nt < 8; nt++) {
                    mma16816(acc[mt][nt], ah[mt], bb[nt >> 1][(nt & 1) * 2], bb[nt >> 1][(nt & 1) * 2 + 1]);
                    mma16816(acc[mt][nt], al[mt], bb[nt >> 1][(nt & 1) * 2], bb[nt >> 1][(nt & 1) * 2 + 1]);
                }
            #pragma unroll
            for (int bt = 0; bt < 4; bt++) {
                uint32_t off = (uint32_t)((b_row + bt * 16) * SM_STRIDE + ks * 16 + b_kc) * 2;
                ldm4(bb[bt], st + 30720 + off);
            }
            #pragma unroll
            for (int mt = 0; mt < 2; mt++)
                #pragma unroll
                for (int nt = 0; nt < 8; nt++)
                    mma16816(acc[mt][nt], ah[mt], bb[nt >> 1][(nt & 1) * 2], bb[nt >> 1][(nt & 1) * 2 + 1]);
        }
        __syncthreads();
    }

    // epilogue
    #pragma unroll
    for (int mt = 0; mt < 2; mt++) {
        int rb = bm + warpM * 32 + mt * 16 + (lane >> 2);
        #pragma unroll
        for (int half = 0; half < 2; half++) {
            int rr = rb + half * 8;
            if (rr >= M) continue;
            #pragma unroll
            for (int nt = 0; nt < 8; nt++) {
                int col = bn + warpN * 64 + nt * 8 + ((lane & 3) << 1);
                float v0 = acc[mt][nt][half * 2 + 0] + bias[col];
                float v1 = acc[mt][nt][half * 2 + 1] + bias[col + 1];
                if (act) { v0 = v0 * normcdff(v0); v1 = v1 * normcdff(v1); }
                size_t o = (size_t)rr * Nn + col;
                if (Ch) {
                    __nv_bfloat16 h0 = __float2bfloat16_rn(v0), h1 = __float2bfloat16_rn(v1);
                    uint32_t hp = (uint32_t)__bfloat16_as_ushort(h0) | ((uint32_t)__bfloat16_as_ushort(h1) << 16);
                    uint32_t lp = pack_bf2(v0 - __bfloat162float(h0), v1 - __bfloat162float(h1));
                    *(uint32_t*)(Ch + o) = hp;
                    *(uint32_t*)(Cl + o) = lp;
                } else if (gamma) {
                    float2* xp = (float2*)(xres + o);
                    float2 xo = *xp;
                    xo.x += gamma[col] * v0;
                    xo.y += gamma[col + 1] * v1;
                    *xp = xo;
                } else {
                    *(float2*)(Cf + o) = make_float2(v0, v1);
                }
            }
        }
    }
}

// ---------------- QKV post: RMS norm (q,k) + RoPE + 1/sqrt(DH) fold ----------------
__global__ void qkvpost_kernel(const float* __restrict__ qkv,
                               const float* __restrict__ qn, const float* __restrict__ kn,
                               const float* __restrict__ rc, const float* __restrict__ rs,
                               float* __restrict__ Q, float* __restrict__ K, float* __restrict__ V,
                               int posmod)
{
    int gw = (blockIdx.x * blockDim.x + threadIdx.x) >> 5;
    int lane = threadIdx.x & 31;
    int t = gw / NHEAD, h = gw - (gw / NHEAD) * NHEAD;
    if (t >= T_TOT) return;
    const float* row = qkv + (size_t)t * 2304 + h * 64;
    float q0 = row[lane],        q1 = row[lane + 32];
    float k0 = row[768 + lane],  k1 = row[768 + lane + 32];
    float v0 = row[1536 + lane], v1 = row[1536 + lane + 32];
    float sq = q0 * q0 + q1 * q1, sk = k0 * k0 + k1 * k1;
    #pragma unroll
    for (int off = 16; off; off >>= 1) {
        sq += __shfl_xor_sync(0xffffffffu, sq, off);
        sk += __shfl_xor_sync(0xffffffffu, sk, off);
    }
    float rq = rsqrtf(sq * (1.f / 64.f) + 1e-6f);
    float rk = rsqrtf(sk * (1.f / 64.f) + 1e-6f);
    q0 *= rq * qn[lane]; q1 *= rq * qn[lane + 32];
    k0 *= rk * kn[lane]; k1 *= rk * kn[lane + 32];
    int pos = t % posmod;
    const float* cr = rc + (size_t)pos * 64;
    const float* sr = rs + (size_t)pos * 64;
    float c0 = cr[lane], c1 = cr[lane + 32];
    float s0 = sr[lane], s1 = sr[lane + 32];
    float sgn = (lane < 16) ? -1.f : 1.f;
    float qp0 = __shfl_xor_sync(0xffffffffu, q0, 16);
    float qp1 = __shfl_xor_sync(0xffffffffu, q1, 16);
    float kp0 = __shfl_xor_sync(0xffffffffu, k0, 16);
    float kp1 = __shfl_xor_sync(0xffffffffu, k1, 16);
    float qo0 = (q0 * c0 + sgn * qp0 * s0) * 0.125f;
    float qo1 = (q1 * c1 + sgn * qp1 * s1) * 0.125f;
    float ko0 = k0 * c0 + sgn * kp0 * s0;
    float ko1 = k1 * c1 + sgn * kp1 * s1;
    size_t base = ((size_t)h * T_TOT + t) * 64;
    Q[base + lane] = qo0; Q[base + 32 + lane] = qo1;
    K[base + lane] = ko0; K[base + 32 + lane] = ko1;
    V[base + lane] = v0;  V[base + 32 + lane] = v1;
}

// ---------------- attention: warp per query, online softmax; split bf16 output ----------------
__global__ __launch_bounds__(256) void attn_kernel(
    const float* __restrict__ Q, const float* __restrict__ K,
    const float* __restrict__ V, const float* __restrict__ kvmask,
    __nv_bfloat16* __restrict__ Oh, __nv_bfloat16* __restrict__ Ol, int nq)
{
    __shared__ float Ks[32][65];
    __shared__ float Vs[32][65];
    __shared__ float bS[32];
    int b = blockIdx.z, h = blockIdx.y;
    int warp = threadIdx.x >> 5, lane = threadIdx.x & 31;
    int qi = blockIdx.x * 8 + warp;
    bool active = qi < nq;
    int t0 = b * nq;
    int tq = t0 + (active ? qi : 0);
    size_t qbase = ((size_t)h * T_TOT + tq) * 64;
    float q0 = active ? Q[qbase + lane] : 0.f;
    float q1 = active ? Q[qbase + 32 + lane] : 0.f;
    const float* kvrow = kvmask + (size_t)b * nq;
    float m = -1e30f, l = 0.f, o0 = 0.f, o1 = 0.f;

    for (int j0 = 0; j0 < nq; j0 += 32) {
        for (int i = threadIdx.x; i < 2048; i += 256) {
            int j = i >> 6, d = i & 63;
            int key = j0 + j;
            float kvv = 0.f, vvv = 0.f;
            if (key < nq) {
                size_t kb = ((size_t)h * T_TOT + t0 + key) * 64 + d;
                kvv = K[kb]; vvv = V[kb];
            }
            Ks[j][d] = kvv; Vs[j][d] = vvv;
        }
        if (threadIdx.x < 32) {
            int key = j0 + threadIdx.x;
            bS[threadIdx.x] = (key < nq) ? (1.f - kvrow[key]) * -10000.f : -1e30f;
        }
        __syncthreads();

        float s = bS[lane];
        #pragma unroll
        for (int d = 0; d < 64; d++) {
            float qd = __shfl_sync(0xffffffffu, (d < 32) ? q0 : q1, d & 31);
            s += qd * Ks[lane][d];
        }
        float mt = s;
        #pragma unroll
        for (int off = 16; off; off >>= 1) mt = fmaxf(mt, __shfl_xor_sync(0xffffffffu, mt, off));
        float mnew = fmaxf(m, mt);
        float scale = __expf(m - mnew);
        float p = __expf(s - mnew);
        float ps = p;
        #pragma unroll
        for (int off = 16; off; off >>= 1) ps += __shfl_xor_sync(0xffffffffu, ps, off);
        l = l * scale + ps;
        o0 *= scale; o1 *= scale;
        #pragma unroll
        for (int j = 0; j < 32; j++) {
            float pj = __shfl_sync(0xffffffffu, p, j);
            o0 += pj * Vs[j][lane];
            o1 += pj * Vs[j][lane + 32];
        }
        m = mnew;
        __syncthreads();
    }
    if (active) {
        float inv = 1.f / l;
        float v0 = o0 * inv, v1 = o1 * inv;
        size_t ob = (size_t)(t0 + qi) * C_DIM + h * 64;
        __nv_bfloat16 h0 = __float2bfloat16_rn(v0);
        __nv_bfloat16 h1 = __float2bfloat16_rn(v1);
        Oh[ob + lane]      = h0;
        Oh[ob + 32 + lane] = h1;
        Ol[ob + lane]      = __float2bfloat16_rn(v0 - __bfloat162float(h0));
        Ol[ob + 32 + lane] = __float2bfloat16_rn(v1 - __bfloat162float(h1));
    }
}

__global__ void copy_kernel(float* __restrict__ dst, const float* __restrict__ src, int n) {
    int i = blockIdx.x * 256 + threadIdx.x;
    if (i < n) dst[i] = src[i];
}

// ---------------- emit output: [local_x | LN(x)] dropping token 0 ----------------
__global__ __launch_bounds__(256) void emit_kernel(const float* __restrict__ xloc, const float* __restrict__ xg,
                                                   const float* __restrict__ fw, const float* __restrict__ fb,
                                                   float* __restrict__ out)
{
    __shared__ float sh[8];
    int row = blockIdx.x;
    int s = row / 576, n = row - s * 576 + 1;
    int t = s * 577 + n;
    int tid = threadIdx.x;
    const float* xr = xg + (size_t)t * C_DIM;
    float v0 = xr[tid], v1 = xr[tid + 256], v2 = xr[tid + 512];
    float mean = block_sum_256(v0 + v1 + v2, sh) * (1.f / 768.f);
    float d0 = v0 - mean, d1 = v1 - mean, d2 = v2 - mean;
    float var = block_sum_256(d0 * d0 + d1 * d1 + d2 * d2, sh) * (1.f / 768.f);
    float rstd = rsqrtf(var + 1e-6f);
    const float* lr = xloc + (size_t)t * C_DIM;
    float* orow = out + (size_t)row * 1536;
    orow[tid]       = lr[tid];
    orow[tid + 256] = lr[tid + 256];
    orow[tid + 512] = lr[tid + 512];
    orow[768 + tid]       = d0 * rstd * fw[tid]       + fb[tid];
    orow[768 + tid + 256] = d1 * rstd * fw[tid + 256] + fb[tid + 256];
    orow[768 + tid + 512] = d2 * rstd * fw[tid + 512] + fb[tid + 512];
}

// ---------------- cam token out ----------------
__global__ void cam_kernel(const float* __restrict__ xloc, const float* __restrict__ xg,
                           float* __restrict__ out) {
    int s = blockIdx.x;
    int t = s * 577;
    for (int c = threadIdx.x; c < C_DIM; c += 256) {
        out[s * 1536 + c]       = xloc[(size_t)t * C_DIM + c];
        out[s * 1536 + 768 + c] = xg[(size_t)t * C_DIM + c];
    }
}

// ---------------- host orchestration ----------------
extern "C" void kernel_launch(void* const* d_in, const int* in_sizes, int n_in,
                              void* d_out, int out_size)
{
    const float* x_in  = (const float*)d_in[0];
    const float* rc_l  = (const float*)d_in[1];
    const float* rs_l  = (const float*)d_in[2];
    const float* rc_g  = (const float*)d_in[3];
    const float* rs_g  = (const float*)d_in[4];
    const float* kv_l  = (const float*)d_in[5];
    const float* kv_g  = (const float*)d_in[6];
    const float* cam   = (const float*)d_in[7];
    const float* qkv_w = (const float*)d_in[8];
    const float* qkv_b = (const float*)d_in[9];
    const float* qn_w  = (const float*)d_in[10];
    const float* kn_w  = (const float*)d_in[11];
    const float* pw    = (const float*)d_in[12];
    const float* pb    = (const float*)d_in[13];
    const float* g1    = (const float*)d_in[14];
    const float* g2    = (const float*)d_in[15];
    const float* n1w   = (const float*)d_in[16];
    const float* n1b   = (const float*)d_in[17];
    const float* n2w   = (const float*)d_in[18];
    const float* n2b   = (const float*)d_in[19];
    const float* f1w   = (const float*)d_in[20];
    const float* f1b   = (const float*)d_in[21];
    const float* f2w   = (const float*)d_in[22];
    const float* f2b   = (const float*)d_in[23];
    const float* fnw   = (const float*)d_in[24];
    const float* fnb   = (const float*)d_in[25];
    float* out = (float*)d_out;

    float *p_x, *p_loc, *p_qkv, *p_q, *p_k, *p_v;
    __nv_bfloat16 *p_wh, *p_wl, *p_sh, *p_sl, *p_mh, *p_ml;
    cudaGetSymbolAddress((void**)&p_x,   g_x);
    cudaGetSymbolAddress((void**)&p_loc, g_loc);
    cudaGetSymbolAddress((void**)&p_qkv, g_qkv);
    cudaGetSymbolAddress((void**)&p_q,   g_q);
    cudaGetSymbolAddress((void**)&p_k,   g_k);
    cudaGetSymbolAddress((void**)&p_v,   g_v);
    cudaGetSymbolAddress((void**)&p_wh,  g_wh);
    cudaGetSymbolAddress((void**)&p_wl,  g_wl);
    cudaGetSymbolAddress((void**)&p_sh,  g_sh);
    cudaGetSymbolAddress((void**)&p_sl,  g_sl);
    cudaGetSymbolAddress((void**)&p_mh,  g_mh);
    cudaGetSymbolAddress((void**)&p_ml,  g_ml);

    cudaFuncSetAttribute(gemm_mma, cudaFuncAttributeMaxDynamicSharedMemorySize, GEMM_SMEM);

    // pre-split weights (hi/lo bf16)
    conv_kernel<<<(21233664 / 4 + 255) / 256, 256>>>(qkv_w, p_wh + W_QKV_OFF,  p_wl + W_QKV_OFF,  21233664 / 4);
    conv_kernel<<<(7077888  / 4 + 255) / 256, 256>>>(pw,    p_wh + W_PROJ_OFF, p_wl + W_PROJ_OFF, 7077888 / 4);
    conv_kernel<<<(28311552 / 4 + 255) / 256, 256>>>(f1w,   p_wh + W_FC1_OFF,  p_wl + W_FC1_OFF,  28311552 / 4);
    conv_kernel<<<(28311552 / 4 + 255) / 256, 256>>>(f2w,   p_wh + W_FC2_OFF,  p_wl + W_FC2_OFF,  28311552 / 4);

    const int eb = (NE + 255) / 256;
    init_x_kernel<<<eb, 256>>>(x_in, cam);

    int outidx = 0;
    for (int i = 0; i < 12; i++) {
        bool isg = (i & 1);
        int nb = isg ? 1 : 2;
        int nq = isg ? 1154 : 577;
        const float* rc = isg ? rc_g : rc_l;
        const float* rs = isg ? rs_g : rs_l;
        const float* kv = isg ? kv_g : kv_l;

        ln_kernel<<<T_TOT, 256>>>(p_x, p_sh, p_sl, n1w + i * 768, n1b + i * 768);
        gemm_mma<<<dim3(18, 10), 256, GEMM_SMEM>>>(
            p_sh, p_sl, p_wh + W_QKV_OFF + (size_t)i * 2304 * 768, p_wl + W_QKV_OFF + (size_t)i * 2304 * 768,
            qkv_b + i * 2304, p_qkv, nullptr, nullptr, nullptr, nullptr, T_TOT, 2304, 768, 0);
        qkvpost_kernel<<<(T_TOT * NHEAD * 32 + 127) / 128, 128>>>(
            p_qkv, qn_w + i * 64, kn_w + i * 64, rc, rs, p_q, p_k, p_v, nq);
        attn_kernel<<<dim3((nq + 7) / 8, NHEAD, nb), 256>>>(p_q, p_k, p_v, kv, p_sh, p_sl, nq);
        gemm_mma<<<dim3(6, 10), 256, GEMM_SMEM>>>(
            p_sh, p_sl, p_wh + W_PROJ_OFF + (size_t)i * 768 * 768, p_wl + W_PROJ_OFF + (size_t)i * 768 * 768,
            pb + i * 768, nullptr, nullptr, nullptr, g1 + i * 768, p_x, T_TOT, 768, 768, 0);

        ln_kernel<<<T_TOT, 256>>>(p_x, p_sh, p_sl, n2w + i * 768, n2b + i * 768);
        gemm_mma<<<dim3(24, 10), 256, GEMM_SMEM>>>(
            p_sh, p_sl, p_wh + W_FC1_OFF + (size_t)i * 3072 * 768, p_wl + W_FC1_OFF + (size_t)i * 3072 * 768,
            f1b + i * 3072, nullptr, p_mh, p_ml, nullptr, nullptr, T_TOT, 3072, 768, 1);
        gemm_mma<<<dim3(6, 10), 256, GEMM_SMEM>>>(
            p_mh, p_ml, p_wh + W_FC2_OFF + (size_t)i * 768 * 3072, p_wl + W_FC2_OFF + (size_t)i * 768 * 3072,
            f2b + i * 768, nullptr, nullptr, nullptr, g2 + i * 768, p_x, T_TOT, 768, 3072, 0);

        if (i == 4 || i == 10) copy_kernel<<<eb, 256>>>(p_loc, p_x, NE);

        if (i == 2 || i == 5 || i == 8 || i == 11) {
            const float* loc = (i == 5 || i == 11) ? p_loc : p_x;
            emit_kernel<<<1152, 256>>>(loc, p_x, fnw, fnb, out + (size_t)outidx * 1769472);
            if (i == 11) cam_kernel<<<2, 256>>>(loc, p_x, out + 4ull * 1769472);
            outidx++;
        }
    }
}

// round 5
// speedup vs baseline: 1.6103x; 1.1501x over previous
#include <cuda_runtime.h>
#include <cuda_bf16.h>
#include <math.h>
#include <stdint.h>

#define T_TOT 1154
#define C_DIM 768
#define NHEAD 12
#define NE (T_TOT * C_DIM)

// weight split offsets (elements)
#define W_QKV_OFF 0
#define W_PROJ_OFF 21233664         // 12*2304*768
#define W_FC1_OFF  28311552         // + 12*768*768
#define W_FC2_OFF  56623104         // + 12*3072*768
#define W_TOTAL    84934656         // + 12*768*3072

// ---------------- device scratch (no allocations allowed) ----------------
__device__ float g_x[NE];
__device__ float g_loc[NE];
__device__ float g_qkv[T_TOT * 3 * C_DIM];
__device__ float g_q[NHEAD * T_TOT * 64];
__device__ float g_k[NHEAD * T_TOT * 64];
__device__ float g_v[NHEAD * T_TOT * 64];
__device__ float g_part[4 * NE];
__device__ __nv_bfloat16 g_wh[W_TOTAL];
__device__ __nv_bfloat16 g_wl[W_TOTAL];
__device__ __nv_bfloat16 g_sh[NE];
__device__ __nv_bfloat16 g_sl[NE];
__device__ __nv_bfloat16 g_mh[NE * 4];
__device__ __nv_bfloat16 g_ml[NE * 4];

// ---------------- helpers ----------------
__device__ __forceinline__ float block_sum_256(float v, float* sh) {
    #pragma unroll
    for (int off = 16; off; off >>= 1) v += __shfl_xor_sync(0xffffffffu, v, off);
    __syncthreads();
    if ((threadIdx.x & 31) == 0) sh[threadIdx.x >> 5] = v;
    __syncthreads();
    float r = 0.f;
    #pragma unroll
    for (int i = 0; i < 8; i++) r += sh[i];
    return r;
}

__device__ __forceinline__ uint32_t smem_u32(const void* p) {
    uint32_t a;
    asm("{ .reg .u64 t; cvta.to.shared.u64 t, %1; cvt.u32.u64 %0, t; }" : "=r"(a) : "l"(p));
    return a;
}

__device__ __forceinline__ void ldm4(uint32_t* r, uint32_t addr) {
    asm volatile("ldmatrix.sync.aligned.m8n8.x4.shared.b16 {%0,%1,%2,%3}, [%4];"
                 : "=r"(r[0]), "=r"(r[1]), "=r"(r[2]), "=r"(r[3]) : "r"(addr));
}

__device__ __forceinline__ void mma16816(float* d, const uint32_t* a, uint32_t b0, uint32_t b1) {
    asm volatile(
        "mma.sync.aligned.m16n8k16.row.col.f32.bf16.bf16.f32 "
        "{%0,%1,%2,%3}, {%4,%5,%6,%7}, {%8,%9}, {%0,%1,%2,%3};"
        : "+f"(d[0]), "+f"(d[1]), "+f"(d[2]), "+f"(d[3])
        : "r"(a[0]), "r"(a[1]), "r"(a[2]), "r"(a[3]), "r"(b0), "r"(b1));
}

__device__ __forceinline__ uint32_t pack_bf2(float a, float b) {
    __nv_bfloat16 ha = __float2bfloat16_rn(a), hb = __float2bfloat16_rn(b);
    return (uint32_t)__bfloat16_as_ushort(ha) | ((uint32_t)__bfloat16_as_ushort(hb) << 16);
}

// ---------------- weight/activation split conversion ----------------
__global__ void conv_kernel(const float* __restrict__ src,
                            __nv_bfloat16* __restrict__ dh, __nv_bfloat16* __restrict__ dl, int n4) {
    int i = blockIdx.x * 256 + threadIdx.x;
    if (i >= n4) return;
    float4 x = ((const float4*)src)[i];
    __nv_bfloat16 h0 = __float2bfloat16_rn(x.x), h1 = __float2bfloat16_rn(x.y);
    __nv_bfloat16 h2 = __float2bfloat16_rn(x.z), h3 = __float2bfloat16_rn(x.w);
    uint2 hv, lv;
    hv.x = (uint32_t)__bfloat16_as_ushort(h0) | ((uint32_t)__bfloat16_as_ushort(h1) << 16);
    hv.y = (uint32_t)__bfloat16_as_ushort(h2) | ((uint32_t)__bfloat16_as_ushort(h3) << 16);
    lv.x = pack_bf2(x.x - __bfloat162float(h0), x.y - __bfloat162float(h1));
    lv.y = pack_bf2(x.z - __bfloat162float(h2), x.w - __bfloat162float(h3));
    ((uint2*)dh)[i] = hv;
    ((uint2*)dl)[i] = lv;
}

// ---------------- init: copy x, insert camera token ----------------
__global__ void init_x_kernel(const float* __restrict__ xin, const float* __restrict__ cam) {
    int i = blockIdx.x * 256 + threadIdx.x;
    if (i >= NE) return;
    int t = i / C_DIM, c = i - t * C_DIM;
    float v;
    if (t == 0) v = cam[c];
    else if (t == 577) v = cam[C_DIM + c];
    else v = xin[i];
    g_x[i] = v;
}

// ---------------- LayerNorm over 768, emits split bf16 ----------------
__global__ __launch_bounds__(256) void ln_kernel(const float* __restrict__ x,
                                                 __nv_bfloat16* __restrict__ yh, __nv_bfloat16* __restrict__ yl,
                                                 const float* __restrict__ w, const float* __restrict__ b) {
    __shared__ float sh[8];
    int t = blockIdx.x, tid = threadIdx.x;
    const float* xr = x + (size_t)t * C_DIM;
    float v0 = xr[tid], v1 = xr[tid + 256], v2 = xr[tid + 512];
    float mean = block_sum_256(v0 + v1 + v2, sh) * (1.f / 768.f);
    float d0 = v0 - mean, d1 = v1 - mean, d2 = v2 - mean;
    float var = block_sum_256(d0 * d0 + d1 * d1 + d2 * d2, sh) * (1.f / 768.f);
    float rstd = rsqrtf(var + 1e-6f);
    float o0 = d0 * rstd * w[tid]       + b[tid];
    float o1 = d1 * rstd * w[tid + 256] + b[tid + 256];
    float o2 = d2 * rstd * w[tid + 512] + b[tid + 512];
    size_t base = (size_t)t * C_DIM + tid;
    __nv_bfloat16 h0 = __float2bfloat16_rn(o0);
    __nv_bfloat16 h1 = __float2bfloat16_rn(o1);
    __nv_bfloat16 h2 = __float2bfloat16_rn(o2);
    yh[base] = h0;       yl[base]       = __float2bfloat16_rn(o0 - __bfloat162float(h0));
    yh[base + 256] = h1; yl[base + 256] = __float2bfloat16_rn(o1 - __bfloat162float(h1));
    yh[base + 512] = h2; yl[base + 512] = __float2bfloat16_rn(o2 - __bfloat162float(h2));
}

// ---------------- mma.sync split-bf16 GEMM, cp.async double-buffered, optional split-K ----------------
#define SM_STRIDE 40
#define STAGE_ELE 20480    // 4 matrices * 5120 elems
#define GEMM_SMEM 81920    // 2 stages * 20480 * 2B

__global__ __launch_bounds__(256, 2) void gemm_mma(
    const __nv_bfloat16* __restrict__ Ah, const __nv_bfloat16* __restrict__ Al,
    const __nv_bfloat16* __restrict__ Wh, const __nv_bfloat16* __restrict__ Wl,
    const float* __restrict__ bias,
    float* __restrict__ Cf, __nv_bfloat16* __restrict__ Ch, __nv_bfloat16* __restrict__ Cl,
    float* __restrict__ part,
    int M, int Nn, int K, int act, int nsplit)
{
    extern __shared__ __align__(16) uint16_t sm[];
    const int tid = threadIdx.x;
    const int wid = tid >> 5, lane = tid & 31;
    const int warpM = wid >> 1, warpN = wid & 1;
    const int bm = blockIdx.y * 128, bn = blockIdx.x * 128;
    const int kz = blockIdx.z;
    const int Kp = K / nsplit;          // per-partial K
    const int kz0 = kz * Kp;
    const uint32_t sbase = smem_u32(sm);

    float acc[2][8][4];
    #pragma unroll
    for (int i = 0; i < 2; i++)
        #pragma unroll
        for (int j = 0; j < 8; j++)
            #pragma unroll
            for (int k = 0; k < 4; k++) acc[i][j][k] = 0.f;

    const int a_row = warpM * 32 + (lane & 15);
    const int a_kc  = (lane >> 4) * 8;
    const int b_row = warpN * 64 + ((lane >> 4) & 1) * 8 + (lane & 7);
    const int b_kc  = ((lane >> 3) & 1) * 8;

    const int NC = Kp >> 5;

    auto issue = [&](int c) {
        const int s = c & 1, k0 = kz0 + (c << 5);
        const uint32_t sb = sbase + (uint32_t)s * (STAGE_ELE * 2);
        #pragma unroll
        for (int it = 0; it < 8; it++) {
            int tsk = tid + (it << 8);
            int mat = tsk >> 9;
            int v = tsk & 511;
            int r = v >> 2, seg = (v & 3) << 3;
            uint32_t sa = sb + (uint32_t)(mat * 5120 + r * SM_STRIDE + seg) * 2;
            const __nv_bfloat16* gp;
            int sz = 16;
            if (mat < 2) {
                int gr = bm + r;
                gp = (mat == 0 ? Ah : Al) + (size_t)gr * K + k0 + seg;
                if (gr >= M) sz = 0;
            } else {
                gp = (mat == 2 ? Wh : Wl) + (size_t)(bn + r) * K + k0 + seg;
            }
            asm volatile("cp.async.cg.shared.global [%0], [%1], 16, %2;"
                         :: "r"(sa), "l"(gp), "r"(sz));
        }
        asm volatile("cp.async.commit_group;" ::: "memory");
    };

    issue(0);
    for (int c = 0; c < NC; c++) {
        if (c + 1 < NC) {
            issue(c + 1);
            asm volatile("cp.async.wait_group 1;" ::: "memory");
        } else {
            asm volatile("cp.async.wait_group 0;" ::: "memory");
        }
        __syncthreads();

        const uint32_t st = sbase + (uint32_t)(c & 1) * (STAGE_ELE * 2);
        #pragma unroll
        for (int ks = 0; ks < 2; ks++) {
            uint32_t ah[2][4], al[2][4], bb[4][4];
            #pragma unroll
            for (int mt = 0; mt < 2; mt++) {
                uint32_t off = (uint32_t)((a_row + mt * 16) * SM_STRIDE + ks * 16 + a_kc) * 2;
                ldm4(ah[mt], st + off);
                ldm4(al[mt], st + 10240 + off);
            }
            #pragma unroll
            for (int bt = 0; bt < 4; bt++) {
                uint32_t off = (uint32_t)((b_row + bt * 16) * SM_STRIDE + ks * 16 + b_kc) * 2;
                ldm4(bb[bt], st + 20480 + off);
            }
            #pragma unroll
            for (int mt = 0; mt < 2; mt++)
                #pragma unroll
                for (int nt = 0; nt < 8; nt++) {
                    mma16816(acc[mt][nt], ah[mt], bb[nt >> 1][(nt & 1) * 2], bb[nt >> 1][(nt & 1) * 2 + 1]);
                    mma16816(acc[mt][nt], al[mt], bb[nt >> 1][(nt & 1) * 2], bb[nt >> 1][(nt & 1) * 2 + 1]);
                }
            #pragma unroll
            for (int bt = 0; bt < 4; bt++) {
                uint32_t off = (uint32_t)((b_row + bt * 16) * SM_STRIDE + ks * 16 + b_kc) * 2;
                ldm4(bb[bt], st + 30720 + off);
            }
            #pragma unroll
            for (int mt = 0; mt < 2; mt++)
                #pragma unroll
                for (int nt = 0; nt < 8; nt++)
                    mma16816(acc[mt][nt], ah[mt], bb[nt >> 1][(nt & 1) * 2], bb[nt >> 1][(nt & 1) * 2 + 1]);
        }
        __syncthreads();
    }

    // epilogue
    #pragma unroll
    for (int mt = 0; mt < 2; mt++) {
        int rb = bm + warpM * 32 + mt * 16 + (lane >> 2);
        #pragma unroll
        for (int half = 0; half < 2; half++) {
            int rr = rb + half * 8;
            if (rr >= M) continue;
            #pragma unroll
            for (int nt = 0; nt < 8; nt++) {
                int col = bn + warpN * 64 + nt * 8 + ((lane & 3) << 1);
                size_t o = (size_t)rr * Nn + col;
                if (nsplit > 1) {
                    *(float2*)(part + (size_t)kz * NE + o) =
                        make_float2(acc[mt][nt][half * 2 + 0], acc[mt][nt][half * 2 + 1]);
                    continue;
                }
                float v0 = acc[mt][nt][half * 2 + 0] + bias[col];
                float v1 = acc[mt][nt][half * 2 + 1] + bias[col + 1];
                if (act) { v0 = v0 * normcdff(v0); v1 = v1 * normcdff(v1); }
                if (Ch) {
                    __nv_bfloat16 h0 = __float2bfloat16_rn(v0), h1 = __float2bfloat16_rn(v1);
                    uint32_t hp = (uint32_t)__bfloat16_as_ushort(h0) | ((uint32_t)__bfloat16_as_ushort(h1) << 16);
                    uint32_t lp = pack_bf2(v0 - __bfloat162float(h0), v1 - __bfloat162float(h1));
                    *(uint32_t*)(Ch + o) = hp;
                    *(uint32_t*)(Cl + o) = lp;
                } else {
                    *(float2*)(Cf + o) = make_float2(v0, v1);
                }
            }
        }
    }
}

// ---------------- combine split-K partials + bias + gamma residual ----------------
__global__ void combine_kernel(float* __restrict__ x, const float* __restrict__ part,
                               const float* __restrict__ bias, const float* __restrict__ gamma,
                               int ns) {
    int i = blockIdx.x * 256 + threadIdx.x;
    if (i >= NE) return;
    int c = i % C_DIM;
    float s = part[i];
    if (ns > 1) s += part[NE + i];
    if (ns > 2) s += part[2 * NE + i] + part[3 * NE + i];
    x[i] += gamma[c] * (s + bias[c]);
}

// ---------------- QKV post: RMS norm (q,k) + RoPE + 1/sqrt(DH) fold ----------------
__global__ void qkvpost_kernel(const float* __restrict__ qkv,
                               const float* __restrict__ qn, const float* __restrict__ kn,
                               const float* __restrict__ rc, const float* __restrict__ rs,
                               float* __restrict__ Q, float* __restrict__ K, float* __restrict__ V,
                               int posmod)
{
    int gw = (blockIdx.x * blockDim.x + threadIdx.x) >> 5;
    int lane = threadIdx.x & 31;
    int t = gw / NHEAD, h = gw - (gw / NHEAD) * NHEAD;
    if (t >= T_TOT) return;
    const float* row = qkv + (size_t)t * 2304 + h * 64;
    float q0 = row[lane],        q1 = row[lane + 32];
    float k0 = row[768 + lane],  k1 = row[768 + lane + 32];
    float v0 = row[1536 + lane], v1 = row[1536 + lane + 32];
    float sq = q0 * q0 + q1 * q1, sk = k0 * k0 + k1 * k1;
    #pragma unroll
    for (int off = 16; off; off >>= 1) {
        sq += __shfl_xor_sync(0xffffffffu, sq, off);
        sk += __shfl_xor_sync(0xffffffffu, sk, off);
    }
    float rq = rsqrtf(sq * (1.f / 64.f) + 1e-6f);
    float rk = rsqrtf(sk * (1.f / 64.f) + 1e-6f);
    q0 *= rq * qn[lane]; q1 *= rq * qn[lane + 32];
    k0 *= rk * kn[lane]; k1 *= rk * kn[lane + 32];
    int pos = t % posmod;
    const float* cr = rc + (size_t)pos * 64;
    const float* sr = rs + (size_t)pos * 64;
    float c0 = cr[lane], c1 = cr[lane + 32];
    float s0 = sr[lane], s1 = sr[lane + 32];
    float sgn = (lane < 16) ? -1.f : 1.f;
    float qp0 = __shfl_xor_sync(0xffffffffu, q0, 16);
    float qp1 = __shfl_xor_sync(0xffffffffu, q1, 16);
    float kp0 = __shfl_xor_sync(0xffffffffu, k0, 16);
    float kp1 = __shfl_xor_sync(0xffffffffu, k1, 16);
    float qo0 = (q0 * c0 + sgn * qp0 * s0) * 0.125f;
    float qo1 = (q1 * c1 + sgn * qp1 * s1) * 0.125f;
    float ko0 = k0 * c0 + sgn * kp0 * s0;
    float ko1 = k1 * c1 + sgn * kp1 * s1;
    size_t base = ((size_t)h * T_TOT + t) * 64;
    Q[base + lane] = qo0; Q[base + 32 + lane] = qo1;
    K[base + lane] = ko0; K[base + 32 + lane] = ko1;
    V[base + lane] = v0;  V[base + 32 + lane] = v1;
}

// ---------------- attention: warp per query, online softmax; split bf16 output ----------------
__global__ __launch_bounds__(256) void attn_kernel(
    const float* __restrict__ Q, const float* __restrict__ K,
    const float* __restrict__ V, const float* __restrict__ kvmask,
    __nv_bfloat16* __restrict__ Oh, __nv_bfloat16* __restrict__ Ol, int nq)
{
    __shared__ float Ks[32][65];
    __shared__ float Vs[32][65];
    __shared__ float bS[32];
    int b = blockIdx.z, h = blockIdx.y;
    int warp = threadIdx.x >> 5, lane = threadIdx.x & 31;
    int qi = blockIdx.x * 8 + warp;
    bool active = qi < nq;
    int t0 = b * nq;
    int tq = t0 + (active ? qi : 0);
    size_t qbase = ((size_t)h * T_TOT + tq) * 64;
    float q0 = active ? Q[qbase + lane] : 0.f;
    float q1 = active ? Q[qbase + 32 + lane] : 0.f;
    const float* kvrow = kvmask + (size_t)b * nq;
    float m = -1e30f, l = 0.f, o0 = 0.f, o1 = 0.f;

    for (int j0 = 0; j0 < nq; j0 += 32) {
        for (int i = threadIdx.x; i < 2048; i += 256) {
            int j = i >> 6, d = i & 63;
            int key = j0 + j;
            float kvv = 0.f, vvv = 0.f;
            if (key < nq) {
                size_t kb = ((size_t)h * T_TOT + t0 + key) * 64 + d;
                kvv = K[kb]; vvv = V[kb];
            }
            Ks[j][d] = kvv; Vs[j][d] = vvv;
        }
        if (threadIdx.x < 32) {
            int key = j0 + threadIdx.x;
            bS[threadIdx.x] = (key < nq) ? (1.f - kvrow[key]) * -10000.f : -1e30f;
        }
        __syncthreads();

        float s = bS[lane];
        #pragma unroll
        for (int d = 0; d < 64; d++) {
            float qd = __shfl_sync(0xffffffffu, (d < 32) ? q0 : q1, d & 31);
            s += qd * Ks[lane][d];
        }
        float mt = s;
        #pragma unroll
        for (int off = 16; off; off >>= 1) mt = fmaxf(mt, __shfl_xor_sync(0xffffffffu, mt, off));
        float mnew = fmaxf(m, mt);
        float scale = __expf(m - mnew);
        float p = __expf(s - mnew);
        float ps = p;
        #pragma unroll
        for (int off = 16; off; off >>= 1) ps += __shfl_xor_sync(0xffffffffu, ps, off);
        l = l * scale + ps;
        o0 *= scale; o1 *= scale;
        #pragma unroll
        for (int j = 0; j < 32; j++) {
            float pj = __shfl_sync(0xffffffffu, p, j);
            o0 += pj * Vs[j][lane];
            o1 += pj * Vs[j][lane + 32];
        }
        m = mnew;
        __syncthreads();
    }
    if (active) {
        float inv = 1.f / l;
        float v0 = o0 * inv, v1 = o1 * inv;
        size_t ob = (size_t)(t0 + qi) * C_DIM + h * 64;
        __nv_bfloat16 h0 = __float2bfloat16_rn(v0);
        __nv_bfloat16 h1 = __float2bfloat16_rn(v1);
        Oh[ob + lane]      = h0;
        Oh[ob + 32 + lane] = h1;
        Ol[ob + lane]      = __float2bfloat16_rn(v0 - __bfloat162float(h0));
        Ol[ob + 32 + lane] = __float2bfloat16_rn(v1 - __bfloat162float(h1));
    }
}

__global__ void copy_kernel(float* __restrict__ dst, const float* __restrict__ src, int n) {
    int i = blockIdx.x * 256 + threadIdx.x;
    if (i < n) dst[i] = src[i];
}

// ---------------- emit output: [local_x | LN(x)] dropping token 0 ----------------
__global__ __launch_bounds__(256) void emit_kernel(const float* __restrict__ xloc, const float* __restrict__ xg,
                                                   const float* __restrict__ fw, const float* __restrict__ fb,
                                                   float* __restrict__ out)
{
    __shared__ float sh[8];
    int row = blockIdx.x;
    int s = row / 576, n = row - s * 576 + 1;
    int t = s * 577 + n;
    int tid = threadIdx.x;
    const float* xr = xg + (size_t)t * C_DIM;
    float v0 = xr[tid], v1 = xr[tid + 256], v2 = xr[tid + 512];
    float mean = block_sum_256(v0 + v1 + v2, sh) * (1.f / 768.f);
    float d0 = v0 - mean, d1 = v1 - mean, d2 = v2 - mean;
    float var = block_sum_256(d0 * d0 + d1 * d1 + d2 * d2, sh) * (1.f / 768.f);
    float rstd = rsqrtf(var + 1e-6f);
    const float* lr = xloc + (size_t)t * C_DIM;
    float* orow = out + (size_t)row * 1536;
    orow[tid]       = lr[tid];
    orow[tid + 256] = lr[tid + 256];
    orow[tid + 512] = lr[tid + 512];
    orow[768 + tid]       = d0 * rstd * fw[tid]       + fb[tid];
    orow[768 + tid + 256] = d1 * rstd * fw[tid + 256] + fb[tid + 256];
    orow[768 + tid + 512] = d2 * rstd * fw[tid + 512] + fb[tid + 512];
}

// ---------------- cam token out ----------------
__global__ void cam_kernel(const float* __restrict__ xloc, const float* __restrict__ xg,
                           float* __restrict__ out) {
    int s = blockIdx.x;
    int t = s * 577;
    for (int c = threadIdx.x; c < C_DIM; c += 256) {
        out[s * 1536 + c]       = xloc[(size_t)t * C_DIM + c];
        out[s * 1536 + 768 + c] = xg[(size_t)t * C_DIM + c];
    }
}

// ---------------- host orchestration ----------------
extern "C" void kernel_launch(void* const* d_in, const int* in_sizes, int n_in,
                              void* d_out, int out_size)
{
    const float* x_in  = (const float*)d_in[0];
    const float* rc_l  = (const float*)d_in[1];
    const float* rs_l  = (const float*)d_in[2];
    const float* rc_g  = (const float*)d_in[3];
    const float* rs_g  = (const float*)d_in[4];
    const float* kv_l  = (const float*)d_in[5];
    const float* kv_g  = (const float*)d_in[6];
    const float* cam   = (const float*)d_in[7];
    const float* qkv_w = (const float*)d_in[8];
    const float* qkv_b = (const float*)d_in[9];
    const float* qn_w  = (const float*)d_in[10];
    const float* kn_w  = (const float*)d_in[11];
    const float* pw    = (const float*)d_in[12];
    const float* pb    = (const float*)d_in[13];
    const float* g1    = (const float*)d_in[14];
    const float* g2    = (const float*)d_in[15];
    const float* n1w   = (const float*)d_in[16];
    const float* n1b   = (const float*)d_in[17];
    const float* n2w   = (const float*)d_in[18];
    const float* n2b   = (const float*)d_in[19];
    const float* f1w   = (const float*)d_in[20];
    const float* f1b   = (const float*)d_in[21];
    const float* f2w   = (const float*)d_in[22];
    const float* f2b   = (const float*)d_in[23];
    const float* fnw   = (const float*)d_in[24];
    const float* fnb   = (const float*)d_in[25];
    float* out = (float*)d_out;

    float *p_x, *p_loc, *p_qkv, *p_q, *p_k, *p_v, *p_part;
    __nv_bfloat16 *p_wh, *p_wl, *p_sh, *p_sl, *p_mh, *p_ml;
    cudaGetSymbolAddress((void**)&p_x,   g_x);
    cudaGetSymbolAddress((void**)&p_loc, g_loc);
    cudaGetSymbolAddress((void**)&p_qkv, g_qkv);
    cudaGetSymbolAddress((void**)&p_q,   g_q);
    cudaGetSymbolAddress((void**)&p_k,   g_k);
    cudaGetSymbolAddress((void**)&p_v,   g_v);
    cudaGetSymbolAddress((void**)&p_part, g_part);
    cudaGetSymbolAddress((void**)&p_wh,  g_wh);
    cudaGetSymbolAddress((void**)&p_wl,  g_wl);
    cudaGetSymbolAddress((void**)&p_sh,  g_sh);
    cudaGetSymbolAddress((void**)&p_sl,  g_sl);
    cudaGetSymbolAddress((void**)&p_mh,  g_mh);
    cudaGetSymbolAddress((void**)&p_ml,  g_ml);

    cudaFuncSetAttribute(gemm_mma, cudaFuncAttributeMaxDynamicSharedMemorySize, GEMM_SMEM);

    // pre-split weights (hi/lo bf16)
    conv_kernel<<<(21233664 / 4 + 255) / 256, 256>>>(qkv_w, p_wh + W_QKV_OFF,  p_wl + W_QKV_OFF,  21233664 / 4);
    conv_kernel<<<(7077888  / 4 + 255) / 256, 256>>>(pw,    p_wh + W_PROJ_OFF, p_wl + W_PROJ_OFF, 7077888 / 4);
    conv_kernel<<<(28311552 / 4 + 255) / 256, 256>>>(f1w,   p_wh + W_FC1_OFF,  p_wl + W_FC1_OFF,  28311552 / 4);
    conv_kernel<<<(28311552 / 4 + 255) / 256, 256>>>(f2w,   p_wh + W_FC2_OFF,  p_wl + W_FC2_OFF,  28311552 / 4);

    const int eb = (NE + 255) / 256;
    init_x_kernel<<<eb, 256>>>(x_in, cam);

    int outidx = 0;
    for (int i = 0; i < 12; i++) {
        bool isg = (i & 1);
        int nb = isg ? 1 : 2;
        int nq = isg ? 1154 : 577;
        const float* rc = isg ? rc_g : rc_l;
        const float* rs = isg ? rs_g : rs_l;
        const float* kv = isg ? kv_g : kv_l;

        ln_kernel<<<T_TOT, 256>>>(p_x, p_sh, p_sl, n1w + i * 768, n1b + i * 768);
        gemm_mma<<<dim3(18, 10, 1), 256, GEMM_SMEM>>>(
            p_sh, p_sl, p_wh + W_QKV_OFF + (size_t)i * 2304 * 768, p_wl + W_QKV_OFF + (size_t)i * 2304 * 768,
            qkv_b + i * 2304, p_qkv, nullptr, nullptr, nullptr, T_TOT, 2304, 768, 0, 1);
        qkvpost_kernel<<<(T_TOT * NHEAD * 32 + 127) / 128, 128>>>(
            p_qkv, qn_w + i * 64, kn_w + i * 64, rc, rs, p_q, p_k, p_v, nq);
        attn_kernel<<<dim3((nq + 7) / 8, NHEAD, nb), 256>>>(p_q, p_k, p_v, kv, p_sh, p_sl, nq);
        // proj: split-K=2, combine applies bias + gamma residual
        gemm_mma<<<dim3(6, 10, 2), 256, GEMM_SMEM>>>(
            p_sh, p_sl, p_wh + W_PROJ_OFF + (size_t)i * 768 * 768, p_wl + W_PROJ_OFF + (size_t)i * 768 * 768,
            nullptr, nullptr, nullptr, nullptr, p_part, T_TOT, 768, 768, 0, 2);
        combine_kernel<<<eb, 256>>>(p_x, p_part, pb + i * 768, g1 + i * 768, 2);

        ln_kernel<<<T_TOT, 256>>>(p_x, p_sh, p_sl, n2w + i * 768, n2b + i * 768);
        gemm_mma<<<dim3(24, 10, 1), 256, GEMM_SMEM>>>(
            p_sh, p_sl, p_wh + W_FC1_OFF + (size_t)i * 3072 * 768, p_wl + W_FC1_OFF + (size_t)i * 3072 * 768,
            f1b + i * 3072, nullptr, p_mh, p_ml, nullptr, T_TOT, 3072, 768, 1, 1);
        // fc2: split-K=4
        gemm_mma<<<dim3(6, 10, 4), 256, GEMM_SMEM>>>(
            p_mh, p_ml, p_wh + W_FC2_OFF + (size_t)i * 768 * 3072, p_wl + W_FC2_OFF + (size_t)i * 768 * 3072,
            nullptr, nullptr, nullptr, nullptr, p_part, T_TOT, 768, 3072, 0, 4);
        combine_kernel<<<eb, 256>>>(p_x, p_part, f2b + i * 768, g2 + i * 768, 4);

        if (i == 4 || i == 10) copy_kernel<<<eb, 256>>>(p_loc, p_x, NE);

        if (i == 2 || i == 5 || i == 8 || i == 11) {
            const float* loc = (i == 5 || i == 11) ? p_loc : p_x;
            emit_kernel<<<1152, 256>>>(loc, p_x, fnw, fnb, out + (size_t)outidx * 1769472);
            if (i == 11) cam_kernel<<<2, 256>>>(loc, p_x, out + 4ull * 1769472);
            outidx++;
        }
    }
}

// round 7
// speedup vs baseline: 3.5009x; 2.1741x over previous
#include <cuda_runtime.h>
#include <cuda_bf16.h>
#include <math.h>
#include <stdint.h>

#define T_TOT 1154
#define C_DIM 768
#define NHEAD 12
#define NE (T_TOT * C_DIM)

// weight split offsets (elements)
#define W_QKV_OFF 0
#define W_PROJ_OFF 21233664         // 12*2304*768
#define W_FC1_OFF  28311552         // + 12*768*768
#define W_FC2_OFF  56623104         // + 12*3072*768
#define W_TOTAL    84934656         // + 12*768*3072

// ---------------- device scratch (no allocations allowed) ----------------
__device__ float g_x[NE];
__device__ float g_loc[NE];
__device__ float g_qkv[T_TOT * 3 * C_DIM];
__device__ float g_part[4 * NE];
__device__ __nv_bfloat16 g_wh[W_TOTAL];
__device__ __nv_bfloat16 g_wl[W_TOTAL];
__device__ __nv_bfloat16 g_sh[NE];
__device__ __nv_bfloat16 g_sl[NE];
__device__ __nv_bfloat16 g_mh[NE * 4];
__device__ __nv_bfloat16 g_ml[NE * 4];
__device__ __nv_bfloat16 g_qh[NHEAD * T_TOT * 64];
__device__ __nv_bfloat16 g_ql[NHEAD * T_TOT * 64];
__device__ __nv_bfloat16 g_kh[NHEAD * T_TOT * 64];
__device__ __nv_bfloat16 g_kl[NHEAD * T_TOT * 64];
__device__ __nv_bfloat16 g_vh[NHEAD * T_TOT * 64];
__device__ __nv_bfloat16 g_vl[NHEAD * T_TOT * 64];

// ---------------- helpers ----------------
__device__ __forceinline__ float block_sum_256(float v, float* sh) {
    #pragma unroll
    for (int off = 16; off; off >>= 1) v += __shfl_xor_sync(0xffffffffu, v, off);
    __syncthreads();
    if ((threadIdx.x & 31) == 0) sh[threadIdx.x >> 5] = v;
    __syncthreads();
    float r = 0.f;
    #pragma unroll
    for (int i = 0; i < 8; i++) r += sh[i];
    return r;
}

__device__ __forceinline__ uint32_t smem_u32(const void* p) {
    uint32_t a;
    asm("{ .reg .u64 t; cvta.to.shared.u64 t, %1; cvt.u32.u64 %0, t; }" : "=r"(a) : "l"(p));
    return a;
}

__device__ __forceinline__ void ldm4(uint32_t* r, uint32_t addr) {
    asm volatile("ldmatrix.sync.aligned.m8n8.x4.shared.b16 {%0,%1,%2,%3}, [%4];"
                 : "=r"(r[0]), "=r"(r[1]), "=r"(r[2]), "=r"(r[3]) : "r"(addr));
}

__device__ __forceinline__ void ldm4t(uint32_t* r, uint32_t addr) {
    asm volatile("ldmatrix.sync.aligned.m8n8.x4.trans.shared.b16 {%0,%1,%2,%3}, [%4];"
                 : "=r"(r[0]), "=r"(r[1]), "=r"(r[2]), "=r"(r[3]) : "r"(addr));
}

__device__ __forceinline__ void mma16816(float* d, const uint32_t* a, uint32_t b0, uint32_t b1) {
    asm volatile(
        "mma.sync.aligned.m16n8k16.row.col.f32.bf16.bf16.f32 "
        "{%0,%1,%2,%3}, {%4,%5,%6,%7}, {%8,%9}, {%0,%1,%2,%3};"
        : "+f"(d[0]), "+f"(d[1]), "+f"(d[2]), "+f"(d[3])
        : "r"(a[0]), "r"(a[1]), "r"(a[2]), "r"(a[3]), "r"(b0), "r"(b1));
}

__device__ __forceinline__ uint32_t pack_bf2(float a, float b) {
    __nv_bfloat16 ha = __float2bfloat16_rn(a), hb = __float2bfloat16_rn(b);
    return (uint32_t)__bfloat16_as_ushort(ha) | ((uint32_t)__bfloat16_as_ushort(hb) << 16);
}

// ---------------- weight split conversion (all 4 weight groups in one launch) ----------------
__global__ void convall_kernel(const float* __restrict__ qkv_w, const float* __restrict__ pw,
                               const float* __restrict__ f1w, const float* __restrict__ f2w,
                               __nv_bfloat16* __restrict__ dh, __nv_bfloat16* __restrict__ dl) {
    int i = blockIdx.x * 256 + threadIdx.x;            // float4 index
    if (i >= W_TOTAL / 4) return;
    const float* src;
    int local;
    if (i < W_PROJ_OFF / 4)      { src = qkv_w; local = i; }
    else if (i < W_FC1_OFF / 4)  { src = pw;    local = i - W_PROJ_OFF / 4; }
    else if (i < W_FC2_OFF / 4)  { src = f1w;   local = i - W_FC1_OFF / 4; }
    else                         { src = f2w;   local = i - W_FC2_OFF / 4; }
    float4 x = ((const float4*)src)[local];
    __nv_bfloat16 h0 = __float2bfloat16_rn(x.x), h1 = __float2bfloat16_rn(x.y);
    __nv_bfloat16 h2 = __float2bfloat16_rn(x.z), h3 = __float2bfloat16_rn(x.w);
    uint2 hv, lv;
    hv.x = (uint32_t)__bfloat16_as_ushort(h0) | ((uint32_t)__bfloat16_as_ushort(h1) << 16);
    hv.y = (uint32_t)__bfloat16_as_ushort(h2) | ((uint32_t)__bfloat16_as_ushort(h3) << 16);
    lv.x = pack_bf2(x.x - __bfloat162float(h0), x.y - __bfloat162float(h1));
    lv.y = pack_bf2(x.z - __bfloat162float(h2), x.w - __bfloat162float(h3));
    ((uint2*)dh)[i] = hv;
    ((uint2*)dl)[i] = lv;
}

__global__ void dummy_kernel(float* p) { if (threadIdx.x == 0 && blockIdx.x == 0) p[0] = 0.f; }

// ---------------- init: copy x, insert camera token ----------------
__global__ void init_x_kernel(const float* __restrict__ xin, const float* __restrict__ cam) {
    int i = blockIdx.x * 256 + threadIdx.x;
    if (i >= NE) return;
    int t = i / C_DIM, c = i - t * C_DIM;
    float v;
    if (t == 0) v = cam[c];
    else if (t == 577) v = cam[C_DIM + c];
    else v = xin[i];
    g_x[i] = v;
}

// ---------------- LayerNorm over 768, emits split bf16 ----------------
__global__ __launch_bounds__(256) void ln_kernel(const float* __restrict__ x,
                                                 __nv_bfloat16* __restrict__ yh, __nv_bfloat16* __restrict__ yl,
                                                 const float* __restrict__ w, const float* __restrict__ b) {
    __shared__ float sh[8];
    int t = blockIdx.x, tid = threadIdx.x;
    const float* xr = x + (size_t)t * C_DIM;
    float v0 = xr[tid], v1 = xr[tid + 256], v2 = xr[tid + 512];
    float mean = block_sum_256(v0 + v1 + v2, sh) * (1.f / 768.f);
    float d0 = v0 - mean, d1 = v1 - mean, d2 = v2 - mean;
    float var = block_sum_256(d0 * d0 + d1 * d1 + d2 * d2, sh) * (1.f / 768.f);
    float rstd = rsqrtf(var + 1e-6f);
    float o0 = d0 * rstd * w[tid]       + b[tid];
    float o1 = d1 * rstd * w[tid + 256] + b[tid + 256];
    float o2 = d2 * rstd * w[tid + 512] + b[tid + 512];
    size_t base = (size_t)t * C_DIM + tid;
    __nv_bfloat16 h0 = __float2bfloat16_rn(o0);
    __nv_bfloat16 h1 = __float2bfloat16_rn(o1);
    __nv_bfloat16 h2 = __float2bfloat16_rn(o2);
    yh[base] = h0;       yl[base]       = __float2bfloat16_rn(o0 - __bfloat162float(h0));
    yh[base + 256] = h1; yl[base + 256] = __float2bfloat16_rn(o1 - __bfloat162float(h1));
    yh[base + 512] = h2; yl[base + 512] = __float2bfloat16_rn(o2 - __bfloat162float(h2));
}

// ---------------- mma.sync split-bf16 GEMM, cp.async double-buffered, optional split-K ----------------
#define SM_STRIDE 40
#define STAGE_ELE 20480
#define GEMM_SMEM 81920

__global__ __launch_bounds__(256, 2) void gemm_mma(
    const __nv_bfloat16* __restrict__ Ah, const __nv_bfloat16* __restrict__ Al,
    const __nv_bfloat16* __restrict__ Wh, const __nv_bfloat16* __restrict__ Wl,
    const float* __restrict__ bias,
    float* __restrict__ Cf, __nv_bfloat16* __restrict__ Ch, __nv_bfloat16* __restrict__ Cl,
    float* __restrict__ part,
    int M, int Nn, int K, int act, int nsplit)
{
    extern __shared__ __align__(16) uint16_t sm[];
    const int tid = threadIdx.x;
    const int wid = tid >> 5, lane = tid & 31;
    const int warpM = wid >> 1, warpN = wid & 1;
    const int bm = blockIdx.y * 128, bn = blockIdx.x * 128;
    const int kz = blockIdx.z;
    const int Kp = K / nsplit;
    const int kz0 = kz * Kp;
    const uint32_t sbase = smem_u32(sm);

    float acc[2][8][4];
    #pragma unroll
    for (int i = 0; i < 2; i++)
        #pragma unroll
        for (int j = 0; j < 8; j++)
            #pragma unroll
            for (int k = 0; k < 4; k++) acc[i][j][k] = 0.f;

    const int a_row = warpM * 32 + (lane & 15);
    const int a_kc  = (lane >> 4) * 8;
    const int b_row = warpN * 64 + ((lane >> 4) & 1) * 8 + (lane & 7);
    const int b_kc  = ((lane >> 3) & 1) * 8;

    const int NC = Kp >> 5;

    auto issue = [&](int c) {
        const int s = c & 1, k0 = kz0 + (c << 5);
        const uint32_t sb = sbase + (uint32_t)s * (STAGE_ELE * 2);
        #pragma unroll
        for (int it = 0; it < 8; it++) {
            int tsk = tid + (it << 8);
            int mat = tsk >> 9;
            int v = tsk & 511;
            int r = v >> 2, seg = (v & 3) << 3;
            uint32_t sa = sb + (uint32_t)(mat * 5120 + r * SM_STRIDE + seg) * 2;
            const __nv_bfloat16* gp;
            int sz = 16;
            if (mat < 2) {
                int gr = bm + r;
                if (gr >= M) { sz = 0; gr = M - 1; }    // clamp: valid address even when zfill
                gp = (mat == 0 ? Ah : Al) + (size_t)gr * K + k0 + seg;
            } else {
                gp = (mat == 2 ? Wh : Wl) + (size_t)(bn + r) * K + k0 + seg;
            }
            asm volatile("cp.async.cg.shared.global [%0], [%1], 16, %2;"
                         :: "r"(sa), "l"(gp), "r"(sz));
        }
        asm volatile("cp.async.commit_group;" ::: "memory");
    };

    issue(0);
    for (int c = 0; c < NC; c++) {
        if (c + 1 < NC) {
            issue(c + 1);
            asm volatile("cp.async.wait_group 1;" ::: "memory");
        } else {
            asm volatile("cp.async.wait_group 0;" ::: "memory");
        }
        __syncthreads();

        const uint32_t st = sbase + (uint32_t)(c & 1) * (STAGE_ELE * 2);
        #pragma unroll
        for (int ks = 0; ks < 2; ks++) {
            uint32_t ah[2][4], al[2][4], bb[4][4];
            #pragma unroll
            for (int mt = 0; mt < 2; mt++) {
                uint32_t off = (uint32_t)((a_row + mt * 16) * SM_STRIDE + ks * 16 + a_kc) * 2;
                ldm4(ah[mt], st + off);
                ldm4(al[mt], st + 10240 + off);
            }
            #pragma unroll
            for (int bt = 0; bt < 4; bt++) {
                uint32_t off = (uint32_t)((b_row + bt * 16) * SM_STRIDE + ks * 16 + b_kc) * 2;
                ldm4(bb[bt], st + 20480 + off);
            }
            #pragma unroll
            for (int mt = 0; mt < 2; mt++)
                #pragma unroll
                for (int nt = 0; nt < 8; nt++) {
                    mma16816(acc[mt][nt], ah[mt], bb[nt >> 1][(nt & 1) * 2], bb[nt >> 1][(nt & 1) * 2 + 1]);
                    mma16816(acc[mt][nt], al[mt], bb[nt >> 1][(nt & 1) * 2], bb[nt >> 1][(nt & 1) * 2 + 1]);
                }
            #pragma unroll
            for (int bt = 0; bt < 4; bt++) {
                uint32_t off = (uint32_t)((b_row + bt * 16) * SM_STRIDE + ks * 16 + b_kc) * 2;
                ldm4(bb[bt], st + 30720 + off);
            }
            #pragma unroll
            for (int mt = 0; mt < 2; mt++)
                #pragma unroll
                for (int nt = 0; nt < 8; nt++)
                    mma16816(acc[mt][nt], ah[mt], bb[nt >> 1][(nt & 1) * 2], bb[nt >> 1][(nt & 1) * 2 + 1]);
        }
        __syncthreads();
    }

    #pragma unroll
    for (int mt = 0; mt < 2; mt++) {
        int rb = bm + warpM * 32 + mt * 16 + (lane >> 2);
        #pragma unroll
        for (int half = 0; half < 2; half++) {
            int rr = rb + half * 8;
            if (rr >= M) continue;
            #pragma unroll
            for (int nt = 0; nt < 8; nt++) {
                int col = bn + warpN * 64 + nt * 8 + ((lane & 3) << 1);
                size_t o = (size_t)rr * Nn + col;
                if (nsplit > 1) {
                    *(float2*)(part + (size_t)kz * NE + o) =
                        make_float2(acc[mt][nt][half * 2 + 0], acc[mt][nt][half * 2 + 1]);
                    continue;
                }
                float v0 = acc[mt][nt][half * 2 + 0] + bias[col];
                float v1 = acc[mt][nt][half * 2 + 1] + bias[col + 1];
                if (act) { v0 = v0 * normcdff(v0); v1 = v1 * normcdff(v1); }
                if (Ch) {
                    __nv_bfloat16 h0 = __float2bfloat16_rn(v0), h1 = __float2bfloat16_rn(v1);
                    uint32_t hp = (uint32_t)__bfloat16_as_ushort(h0) | ((uint32_t)__bfloat16_as_ushort(h1) << 16);
                    uint32_t lp = pack_bf2(v0 - __bfloat162float(h0), v1 - __bfloat162float(h1));
                    *(uint32_t*)(Ch + o) = hp;
                    *(uint32_t*)(Cl + o) = lp;
                } else {
                    *(float2*)(Cf + o) = make_float2(v0, v1);
                }
            }
        }
    }
}

// ---------------- combine split-K partials + bias + gamma residual ----------------
__global__ void combine_kernel(float* __restrict__ x, const float* __restrict__ part,
                               const float* __restrict__ bias, const float* __restrict__ gamma,
                               int ns) {
    int i = blockIdx.x * 256 + threadIdx.x;
    if (i >= NE) return;
    int c = i % C_DIM;
    float s = part[i];
    if (ns > 1) s += part[NE + i];
    if (ns > 2) s += part[2 * NE + i] + part[3 * NE + i];
    x[i] += gamma[c] * (s + bias[c]);
}

// ---------------- QKV post: RMS norm (q,k) + RoPE + 1/sqrt(DH) fold; emits split bf16 ----------------
__global__ void qkvpost_kernel(const float* __restrict__ qkv,
                               const float* __restrict__ qn, const float* __restrict__ kn,
                               const float* __restrict__ rc, const float* __restrict__ rs,
                               __nv_bfloat16* __restrict__ Qh, __nv_bfloat16* __restrict__ Ql,
                               __nv_bfloat16* __restrict__ Kh, __nv_bfloat16* __restrict__ Kl,
                               __nv_bfloat16* __restrict__ Vh, __nv_bfloat16* __restrict__ Vl,
                               int posmod)
{
    int gw = (blockIdx.x * blockDim.x + threadIdx.x) >> 5;
    int lane = threadIdx.x & 31;
    int t = gw / NHEAD, h = gw - (gw / NHEAD) * NHEAD;
    if (t >= T_TOT) return;
    const float* row = qkv + (size_t)t * 2304 + h * 64;
    float q0 = row[lane],        q1 = row[lane + 32];
    float k0 = row[768 + lane],  k1 = row[768 + lane + 32];
    float v0 = row[1536 + lane], v1 = row[1536 + lane + 32];
    float sq = q0 * q0 + q1 * q1, sk = k0 * k0 + k1 * k1;
    #pragma unroll
    for (int off = 16; off; off >>= 1) {
        sq += __shfl_xor_sync(0xffffffffu, sq, off);
        sk += __shfl_xor_sync(0xffffffffu, sk, off);
    }
    float rq = rsqrtf(sq * (1.f / 64.f) + 1e-6f);
    float rk = rsqrtf(sk * (1.f / 64.f) + 1e-6f);
    q0 *= rq * qn[lane]; q1 *= rq * qn[lane + 32];
    k0 *= rk * kn[lane]; k1 *= rk * kn[lane + 32];
    int pos = t % posmod;
    const float* cr = rc + (size_t)pos * 64;
    const float* sr = rs + (size_t)pos * 64;
    float c0 = cr[lane], c1 = cr[lane + 32];
    float s0 = sr[lane], s1 = sr[lane + 32];
    float sgn = (lane < 16) ? -1.f : 1.f;
    float qp0 = __shfl_xor_sync(0xffffffffu, q0, 16);
    float qp1 = __shfl_xor_sync(0xffffffffu, q1, 16);
    float kp0 = __shfl_xor_sync(0xffffffffu, k0, 16);
    float kp1 = __shfl_xor_sync(0xffffffffu, k1, 16);
    float qo0 = (q0 * c0 + sgn * qp0 * s0) * 0.125f;
    float qo1 = (q1 * c1 + sgn * qp1 * s1) * 0.125f;
    float ko0 = k0 * c0 + sgn * kp0 * s0;
    float ko1 = k1 * c1 + sgn * kp1 * s1;
    size_t base = ((size_t)h * T_TOT + t) * 64;
    __nv_bfloat16 hh;
    hh = __float2bfloat16_rn(qo0); Qh[base + lane] = hh;       Ql[base + lane]      = __float2bfloat16_rn(qo0 - __bfloat162float(hh));
    hh = __float2bfloat16_rn(qo1); Qh[base + 32 + lane] = hh;  Ql[base + 32 + lane] = __float2bfloat16_rn(qo1 - __bfloat162float(hh));
    hh = __float2bfloat16_rn(ko0); Kh[base + lane] = hh;       Kl[base + lane]      = __float2bfloat16_rn(ko0 - __bfloat162float(hh));
    hh = __float2bfloat16_rn(ko1); Kh[base + 32 + lane] = hh;  Kl[base + 32 + lane] = __float2bfloat16_rn(ko1 - __bfloat162float(hh));
    hh = __float2bfloat16_rn(v0);  Vh[base + lane] = hh;       Vl[base + lane]      = __float2bfloat16_rn(v0 - __bfloat162float(hh));
    hh = __float2bfloat16_rn(v1);  Vh[base + 32 + lane] = hh;  Vl[base + 32 + lane] = __float2bfloat16_rn(v1 - __bfloat162float(hh));
}

// ---------------- tensor-core flash attention ----------------
// CTA: 64 queries x 1 head x 1 segment; 4 warps x 16 q. 64-key tiles, double-buffered.
#define ATT_STRIDE 72
#define ATT_QH 0
#define ATT_QL 4608
#define ATT_STG 9216
#define ATT_STG_SZ 18432
#define ATT_SMEM ((9216 + 2 * 18432) * 2)   // 92160 bytes

__global__ __launch_bounds__(128) void attn_mma(
    const __nv_bfloat16* __restrict__ Qh, const __nv_bfloat16* __restrict__ Ql,
    const __nv_bfloat16* __restrict__ Kh, const __nv_bfloat16* __restrict__ Kl,
    const __nv_bfloat16* __restrict__ Vh, const __nv_bfloat16* __restrict__ Vl,
    const float* __restrict__ kvmask,
    __nv_bfloat16* __restrict__ Oh, __nv_bfloat16* __restrict__ Ol, int nq)
{
    extern __shared__ __align__(16) uint16_t smA[];
    const int tid = threadIdx.x, wid = tid >> 5, lane = tid & 31;
    const int qt = blockIdx.x, h = blockIdx.y, z = blockIdx.z;
    const int t0 = z * nq;
    const size_t hb = (size_t)h * T_TOT * 64;
    const uint32_t sbase = smem_u32(smA);
    const float* kvrow = kvmask + (size_t)z * nq;

    // load Q tile (hi/lo) into smem
    for (int i = tid; i < 512; i += 128) {
        int r = i >> 3, sg = i & 7;
        int qrow = qt * 64 + r;
        uint4 vh = make_uint4(0, 0, 0, 0), vl = make_uint4(0, 0, 0, 0);
        if (qrow < nq) {
            size_t go = hb + (size_t)(t0 + qrow) * 64 + sg * 8;
            vh = *(const uint4*)(Qh + go);
            vl = *(const uint4*)(Ql + go);
        }
        *(uint4*)((char*)smA + (ATT_QH + r * ATT_STRIDE + sg * 8) * 2) = vh;
        *(uint4*)((char*)smA + (ATT_QL + r * ATT_STRIDE + sg * 8) * 2) = vl;
    }
    __syncthreads();

    // Q fragments (held for whole K loop)
    uint32_t qhf[4][4], qlf[4][4];
    {
        int arow = wid * 16 + (lane & 15);
        int akc = (lane >> 4) * 8;
        #pragma unroll
        for (int kc = 0; kc < 4; kc++) {
            uint32_t off = (uint32_t)(arow * ATT_STRIDE + kc * 16 + akc) * 2;
            ldm4(qhf[kc], sbase + ATT_QH * 2 + off);
            ldm4(qlf[kc], sbase + ATT_QL * 2 + off);
        }
    }

    auto stage_load = [&](int kt) {
        int s = kt & 1;
        uint32_t sb = sbase + (uint32_t)(ATT_STG + s * ATT_STG_SZ) * 2;
        int kbase = kt * 64;
        #pragma unroll
        for (int it = 0; it < 16; it++) {
            int i = tid + it * 128;
            int m = i >> 9, v = i & 511, r = v >> 3, sg = v & 7;
            int key = kbase + r;
            int sz = 16;
            if (key >= nq) { sz = 0; key = nq - 1; }   // clamp: address stays in-bounds
            const __nv_bfloat16* gp =
                (m == 0 ? Kh : m == 1 ? Kl : m == 2 ? Vh : Vl) + hb + (size_t)(t0 + key) * 64 + sg * 8;
            uint32_t da = sb + (uint32_t)(m * 4608 + r * ATT_STRIDE + sg * 8) * 2;
            asm volatile("cp.async.cg.shared.global [%0], [%1], 16, %2;"
                         :: "r"(da), "l"(gp), "r"(sz));
        }
        asm volatile("cp.async.commit_group;" ::: "memory");
    };

    float o[8][4];
    #pragma unroll
    for (int i = 0; i < 8; i++)
        #pragma unroll
        for (int j = 0; j < 4; j++) o[i][j] = 0.f;
    float m0 = -1e30f, m1 = -1e30f, l0 = 0.f, l1 = 0.f;

    const int nkt = (nq + 63) >> 6;
    const int brow = ((lane >> 4) & 1) * 8 + (lane & 7);
    const int bkc = ((lane >> 3) & 1) * 8;
    const int vr0 = ((lane >> 3) & 1) * 8 + (lane & 7);
    const int vc0 = (lane >> 4) * 8;

    stage_load(0);
    for (int kt = 0; kt < nkt; kt++) {
        if (kt + 1 < nkt) {
            stage_load(kt + 1);
            asm volatile("cp.async.wait_group 1;" ::: "memory");
        } else {
            asm volatile("cp.async.wait_group 0;" ::: "memory");
        }
        __syncthreads();
        uint32_t sb = sbase + (uint32_t)(ATT_STG + (kt & 1) * ATT_STG_SZ) * 2;
        int kbase = kt * 64;

        // scores init = bias
        float s_[8][4];
        #pragma unroll
        for (int nt = 0; nt < 8; nt++) {
            int key = kbase + nt * 8 + ((lane & 3) << 1);
            float b0 = (key < nq) ? (1.f - kvrow[key]) * -10000.f : -1e30f;
            float b1 = (key + 1 < nq) ? (1.f - kvrow[key + 1]) * -10000.f : -1e30f;
            s_[nt][0] = b0; s_[nt][1] = b1; s_[nt][2] = b0; s_[nt][3] = b1;
        }
        // QK^T, 3 terms
        #pragma unroll
        for (int np = 0; np < 4; np++) {
            #pragma unroll
            for (int kc = 0; kc < 4; kc++) {
                uint32_t off = (uint32_t)((np * 16 + brow) * ATT_STRIDE + kc * 16 + bkc) * 2;
                uint32_t kh4[4], kl4[4];
                ldm4(kh4, sb + off);
                ldm4(kl4, sb + 4608 * 2 + off);
                mma16816(s_[2 * np],     qhf[kc], kh4[0], kh4[1]);
                mma16816(s_[2 * np + 1], qhf[kc], kh4[2], kh4[3]);
                mma16816(s_[2 * np],     qlf[kc], kh4[0], kh4[1]);
                mma16816(s_[2 * np + 1], qlf[kc], kh4[2], kh4[3]);
                mma16816(s_[2 * np],     qhf[kc], kl4[0], kl4[1]);
                mma16816(s_[2 * np + 1], qhf[kc], kl4[2], kl4[3]);
            }
        }
        // online softmax
        float mx0 = -1e30f, mx1 = -1e30f;
        #pragma unroll
        for (int nt = 0; nt < 8; nt++) {
            mx0 = fmaxf(mx0, fmaxf(s_[nt][0], s_[nt][1]));
            mx1 = fmaxf(mx1, fmaxf(s_[nt][2], s_[nt][3]));
        }
        mx0 = fmaxf(mx0, __shfl_xor_sync(0xffffffffu, mx0, 1));
        mx0 = fmaxf(mx0, __shfl_xor_sync(0xffffffffu, mx0, 2));
        mx1 = fmaxf(mx1, __shfl_xor_sync(0xffffffffu, mx1, 1));
        mx1 = fmaxf(mx1, __shfl_xor_sync(0xffffffffu, mx1, 2));
        float mn0 = fmaxf(m0, mx0), mn1 = fmaxf(m1, mx1);
        float sc0 = __expf(m0 - mn0), sc1 = __expf(m1 - mn1);
        m0 = mn0; m1 = mn1;
        float ps0 = 0.f, ps1 = 0.f;
        #pragma unroll
        for (int nt = 0; nt < 8; nt++) {
            s_[nt][0] = __expf(s_[nt][0] - mn0); ps0 += s_[nt][0];
            s_[nt][1] = __expf(s_[nt][1] - mn0); ps0 += s_[nt][1];
            s_[nt][2] = __expf(s_[nt][2] - mn1); ps1 += s_[nt][2];
            s_[nt][3] = __expf(s_[nt][3] - mn1); ps1 += s_[nt][3];
        }
        ps0 += __shfl_xor_sync(0xffffffffu, ps0, 1);
        ps0 += __shfl_xor_sync(0xffffffffu, ps0, 2);
        ps1 += __shfl_xor_sync(0xffffffffu, ps1, 1);
        ps1 += __shfl_xor_sync(0xffffffffu, ps1, 2);
        l0 = l0 * sc0 + ps0;
        l1 = l1 * sc1 + ps1;
        #pragma unroll
        for (int nt = 0; nt < 8; nt++) {
            o[nt][0] *= sc0; o[nt][1] *= sc0; o[nt][2] *= sc1; o[nt][3] *= sc1;
        }
        // P fragments (hi/lo)
        uint32_t pfh[4][4], pfl[4][4];
        #pragma unroll
        for (int kc = 0; kc < 4; kc++) {
            #pragma unroll
            for (int q = 0; q < 4; q++) {
                float a = s_[2 * kc + (q >> 1)][(q & 1) * 2];
                float b = s_[2 * kc + (q >> 1)][(q & 1) * 2 + 1];
                __nv_bfloat16 ha = __float2bfloat16_rn(a), hb2 = __float2bfloat16_rn(b);
                pfh[kc][q] = (uint32_t)__bfloat16_as_ushort(ha) | ((uint32_t)__bfloat16_as_ushort(hb2) << 16);
                pfl[kc][q] = pack_bf2(a - __bfloat162float(ha), b - __bfloat162float(hb2));
            }
        }
        // P·V, 3 terms
        #pragma unroll
        for (int kc = 0; kc < 4; kc++) {
            #pragma unroll
            for (int dp = 0; dp < 4; dp++) {
                uint32_t off = (uint32_t)((kc * 16 + vr0) * ATT_STRIDE + dp * 16 + vc0) * 2;
                uint32_t vh4[4], vl4[4];
                ldm4t(vh4, sb + 9216 * 2 + off);
                ldm4t(vl4, sb + 13824 * 2 + off);
                mma16816(o[2 * dp],     pfh[kc], vh4[0], vh4[1]);
                mma16816(o[2 * dp + 1], pfh[kc], vh4[2], vh4[3]);
                mma16816(o[2 * dp],     pfl[kc], vh4[0], vh4[1]);
                mma16816(o[2 * dp + 1], pfl[kc], vh4[2], vh4[3]);
                mma16816(o[2 * dp],     pfh[kc], vl4[0], vl4[1]);
                mma16816(o[2 * dp + 1], pfh[kc], vl4[2], vl4[3]);
            }
        }
        __syncthreads();   // protect stage being re-filled next iteration
    }

    // store: split bf16 into proj input
    float inv0 = 1.f / l0, inv1 = 1.f / l1;
    int r = lane >> 2;
    int q0row = qt * 64 + wid * 16 + r;
    int q1row = q0row + 8;
    #pragma unroll
    for (int nt = 0; nt < 8; nt++) {
        int d = nt * 8 + ((lane & 3) << 1);
        if (q0row < nq) {
            float a = o[nt][0] * inv0, b = o[nt][1] * inv0;
            size_t ob = (size_t)(t0 + q0row) * C_DIM + h * 64 + d;
            __nv_bfloat16 ha = __float2bfloat16_rn(a), hb2 = __float2bfloat16_rn(b);
            *(uint32_t*)(Oh + ob) = (uint32_t)__bfloat16_as_ushort(ha) | ((uint32_t)__bfloat16_as_ushort(hb2) << 16);
            *(uint32_t*)(Ol + ob) = pack_bf2(a - __bfloat162float(ha), b - __bfloat162float(hb2));
        }
        if (q1row < nq) {
            float a = o[nt][2] * inv1, b = o[nt][3] * inv1;
            size_t ob = (size_t)(t0 + q1row) * C_DIM + h * 64 + d;
            __nv_bfloat16 ha = __float2bfloat16_rn(a), hb2 = __float2bfloat16_rn(b);
            *(uint32_t*)(Oh + ob) = (uint32_t)__bfloat16_as_ushort(ha) | ((uint32_t)__bfloat16_as_ushort(hb2) << 16);
            *(uint32_t*)(Ol + ob) = pack_bf2(a - __bfloat162float(ha), b - __bfloat162float(hb2));
        }
    }
}

__global__ void copy_kernel(float* __restrict__ dst, const float* __restrict__ src, int n) {
    int i = blockIdx.x * 256 + threadIdx.x;
    if (i < n) dst[i] = src[i];
}

// ---------------- emit output: [local_x | LN(x)] dropping token 0 ----------------
__global__ __launch_bounds__(256) void emit_kernel(const float* __restrict__ xloc, const float* __restrict__ xg,
                                                   const float* __restrict__ fw, const float* __restrict__ fb,
                                                   float* __restrict__ out)
{
    __shared__ float sh[8];
    int row = blockIdx.x;
    int s = row / 576, n = row - s * 576 + 1;
    int t = s * 577 + n;
    int tid = threadIdx.x;
    const float* xr = xg + (size_t)t * C_DIM;
    float v0 = xr[tid], v1 = xr[tid + 256], v2 = xr[tid + 512];
    float mean = block_sum_256(v0 + v1 + v2, sh) * (1.f / 768.f);
    float d0 = v0 - mean, d1 = v1 - mean, d2 = v2 - mean;
    float var = block_sum_256(d0 * d0 + d1 * d1 + d2 * d2, sh) * (1.f / 768.f);
    float rstd = rsqrtf(var + 1e-6f);
    const float* lr = xloc + (size_t)t * C_DIM;
    float* orow = out + (size_t)row * 1536;
    orow[tid]       = lr[tid];
    orow[tid + 256] = lr[tid + 256];
    orow[tid + 512] = lr[tid + 512];
    orow[768 + tid]       = d0 * rstd * fw[tid]       + fb[tid];
    orow[768 + tid + 256] = d1 * rstd * fw[tid + 256] + fb[tid + 256];
    orow[768 + tid + 512] = d2 * rstd * fw[tid + 512] + fb[tid + 512];
}

// ---------------- cam token out ----------------
__global__ void cam_kernel(const float* __restrict__ xloc, const float* __restrict__ xg,
                           float* __restrict__ out) {
    int s = blockIdx.x;
    int t = s * 577;
    for (int c = threadIdx.x; c < C_DIM; c += 256) {
        out[s * 1536 + c]       = xloc[(size_t)t * C_DIM + c];
        out[s * 1536 + 768 + c] = xg[(size_t)t * C_DIM + c];
    }
}

// ---------------- host orchestration ----------------
extern "C" void kernel_launch(void* const* d_in, const int* in_sizes, int n_in,
                              void* d_out, int out_size)
{
    const float* x_in  = (const float*)d_in[0];
    const float* rc_l  = (const float*)d_in[1];
    const float* rs_l  = (const float*)d_in[2];
    const float* rc_g  = (const float*)d_in[3];
    const float* rs_g  = (const float*)d_in[4];
    const float* kv_l  = (const float*)d_in[5];
    const float* kv_g  = (const float*)d_in[6];
    const float* cam   = (const float*)d_in[7];
    const float* qkv_w = (const float*)d_in[8];
    const float* qkv_b = (const float*)d_in[9];
    const float* qn_w  = (const float*)d_in[10];
    const float* kn_w  = (const float*)d_in[11];
    const float* pw    = (const float*)d_in[12];
    const float* pb    = (const float*)d_in[13];
    const float* g1    = (const float*)d_in[14];
    const float* g2    = (const float*)d_in[15];
    const float* n1w   = (const float*)d_in[16];
    const float* n1b   = (const float*)d_in[17];
    const float* n2w   = (const float*)d_in[18];
    const float* n2b   = (const float*)d_in[19];
    const float* f1w   = (const float*)d_in[20];
    const float* f1b   = (const float*)d_in[21];
    const float* f2w   = (const float*)d_in[22];
    const float* f2b   = (const float*)d_in[23];
    const float* fnw   = (const float*)d_in[24];
    const float* fnb   = (const float*)d_in[25];
    float* out = (float*)d_out;

    float *p_x, *p_loc, *p_qkv, *p_part;
    __nv_bfloat16 *p_wh, *p_wl, *p_sh, *p_sl, *p_mh, *p_ml;
    __nv_bfloat16 *p_qh, *p_ql, *p_kh, *p_kl, *p_vh, *p_vl;
    cudaGetSymbolAddress((void**)&p_x,   g_x);
    cudaGetSymbolAddress((void**)&p_loc, g_loc);
    cudaGetSymbolAddress((void**)&p_qkv, g_qkv);
    cudaGetSymbolAddress((void**)&p_part, g_part);
    cudaGetSymbolAddress((void**)&p_wh,  g_wh);
    cudaGetSymbolAddress((void**)&p_wl,  g_wl);
    cudaGetSymbolAddress((void**)&p_sh,  g_sh);
    cudaGetSymbolAddress((void**)&p_sl,  g_sl);
    cudaGetSymbolAddress((void**)&p_mh,  g_mh);
    cudaGetSymbolAddress((void**)&p_ml,  g_ml);
    cudaGetSymbolAddress((void**)&p_qh,  g_qh);
    cudaGetSymbolAddress((void**)&p_ql,  g_ql);
    cudaGetSymbolAddress((void**)&p_kh,  g_kh);
    cudaGetSymbolAddress((void**)&p_kl,  g_kl);
    cudaGetSymbolAddress((void**)&p_vh,  g_vh);
    cudaGetSymbolAddress((void**)&p_vl,  g_vl);

    cudaFuncSetAttribute(gemm_mma, cudaFuncAttributeMaxDynamicSharedMemorySize, GEMM_SMEM);
    cudaFuncSetAttribute(attn_mma, cudaFuncAttributeMaxDynamicSharedMemorySize, ATT_SMEM);

    const int eb = (NE + 255) / 256;
    convall_kernel<<<(W_TOTAL / 4 + 255) / 256, 256>>>(qkv_w, pw, f1w, f2w, p_wh, p_wl);
    init_x_kernel<<<eb, 256>>>(x_in, cam);

    int outidx = 0;
    for (int i = 0; i < 12; i++) {
        bool isg = (i & 1);
        int nb = isg ? 1 : 2;
        int nq = isg ? 1154 : 577;
        const float* rc = isg ? rc_g : rc_l;
        const float* rs = isg ? rs_g : rs_l;
        const float* kv = isg ? kv_g : kv_l;

        ln_kernel<<<T_TOT, 256>>>(p_x, p_sh, p_sl, n1w + i * 768, n1b + i * 768);
        if (i == 0) {   // position gemm_mma at launch #6 for the ncu window
            dummy_kernel<<<1, 32>>>(p_part);
            dummy_kernel<<<1, 32>>>(p_part);
        }
        gemm_mma<<<dim3(18, 10, 1), 256, GEMM_SMEM>>>(
            p_sh, p_sl, p_wh + W_QKV_OFF + (size_t)i * 2304 * 768, p_wl + W_QKV_OFF + (size_t)i * 2304 * 768,
            qkv_b + i * 2304, p_qkv, nullptr, nullptr, nullptr, T_TOT, 2304, 768, 0, 1);
        qkvpost_kernel<<<(T_TOT * NHEAD * 32 + 127) / 128, 128>>>(
            p_qkv, qn_w + i * 64, kn_w + i * 64, rc, rs,
            p_qh, p_ql, p_kh, p_kl, p_vh, p_vl, nq);
        attn_mma<<<dim3((nq + 63) / 64, NHEAD, nb), 128, ATT_SMEM>>>(
            p_qh, p_ql, p_kh, p_kl, p_vh, p_vl, kv, p_sh, p_sl, nq);
        gemm_mma<<<dim3(6, 10, 2), 256, GEMM_SMEM>>>(
            p_sh, p_sl, p_wh + W_PROJ_OFF + (size_t)i * 768 * 768, p_wl + W_PROJ_OFF + (size_t)i * 768 * 768,
            nullptr, nullptr, nullptr, nullptr, p_part, T_TOT, 768, 768, 0, 2);
        combine_kernel<<<eb, 256>>>(p_x, p_part, pb + i * 768, g1 + i * 768, 2);

        ln_kernel<<<T_TOT, 256>>>(p_x, p_sh, p_sl, n2w + i * 768, n2b + i * 768);
        gemm_mma<<<dim3(24, 10, 1), 256, GEMM_SMEM>>>(
            p_sh, p_sl, p_wh + W_FC1_OFF + (size_t)i * 3072 * 768, p_wl + W_FC1_OFF + (size_t)i * 3072 * 768,
            f1b + i * 3072, nullptr, p_mh, p_ml, nullptr, T_TOT, 3072, 768, 1, 1);
        gemm_mma<<<dim3(6, 10, 4), 256, GEMM_SMEM>>>(
            p_mh, p_ml, p_wh + W_FC2_OFF + (size_t)i * 768 * 3072, p_wl + W_FC2_OFF + (size_t)i * 768 * 3072,
            nullptr, nullptr, nullptr, nullptr, p_part, T_TOT, 768, 3072, 0, 4);
        combine_kernel<<<eb, 256>>>(p_x, p_part, f2b + i * 768, g2 + i * 768, 4);

        if (i == 4 || i == 10) copy_kernel<<<eb, 256>>>(p_loc, p_x, NE);

        if (i == 2 || i == 5 || i == 8 || i == 11) {
            const float* loc = (i == 5 || i == 11) ? p_loc : p_x;
            emit_kernel<<<1152, 256>>>(loc, p_x, fnw, fnb, out + (size_t)outidx * 1769472);
            if (i == 11) cam_kernel<<<2, 256>>>(loc, p_x, out + 4ull * 1769472);
            outidx++;
        }
    }
}

// round 8
// speedup vs baseline: 3.8928x; 1.1119x over previous
#include <cuda_runtime.h>
#include <cuda_bf16.h>
#include <cuda_fp16.h>
#include <math.h>
#include <stdint.h>

#define T_TOT 1154
#define C_DIM 768
#define NHEAD 12
#define NE (T_TOT * C_DIM)
#define QKV_PART_STRIDE 2658816     // 1154*2304

// weight split offsets (elements)
#define W_QKV_OFF 0
#define W_PROJ_OFF 21233664
#define W_FC1_OFF  28311552
#define W_FC2_OFF  56623104
#define W_TOTAL    84934656

// ---------------- device scratch ----------------
__device__ float g_x[NE];
__device__ float g_loc[NE];
__device__ float g_part[2 * QKV_PART_STRIDE];
__device__ __nv_bfloat16 g_wh[W_TOTAL];
__device__ __nv_bfloat16 g_wl[W_TOTAL];
__device__ __nv_bfloat16 g_sh[NE];
__device__ __nv_bfloat16 g_sl[NE];
__device__ __nv_bfloat16 g_mh[NE * 4];
__device__ __nv_bfloat16 g_ml[NE * 4];
__device__ __half g_qh[NHEAD * T_TOT * 64];
__device__ __half g_ql[NHEAD * T_TOT * 64];
__device__ __half g_kh[NHEAD * T_TOT * 64];
__device__ __half g_vh[NHEAD * T_TOT * 64];

// ---------------- helpers ----------------
__device__ __forceinline__ float block_sum_256(float v, float* sh) {
    #pragma unroll
    for (int off = 16; off; off >>= 1) v += __shfl_xor_sync(0xffffffffu, v, off);
    __syncthreads();
    if ((threadIdx.x & 31) == 0) sh[threadIdx.x >> 5] = v;
    __syncthreads();
    float r = 0.f;
    #pragma unroll
    for (int i = 0; i < 8; i++) r += sh[i];
    return r;
}

__device__ __forceinline__ uint32_t smem_u32(const void* p) {
    uint32_t a;
    asm("{ .reg .u64 t; cvta.to.shared.u64 t, %1; cvt.u32.u64 %0, t; }" : "=r"(a) : "l"(p));
    return a;
}

__device__ __forceinline__ void ldm4(uint32_t* r, uint32_t addr) {
    asm volatile("ldmatrix.sync.aligned.m8n8.x4.shared.b16 {%0,%1,%2,%3}, [%4];"
                 : "=r"(r[0]), "=r"(r[1]), "=r"(r[2]), "=r"(r[3]) : "r"(addr));
}

__device__ __forceinline__ void ldm4t(uint32_t* r, uint32_t addr) {
    asm volatile("ldmatrix.sync.aligned.m8n8.x4.trans.shared.b16 {%0,%1,%2,%3}, [%4];"
                 : "=r"(r[0]), "=r"(r[1]), "=r"(r[2]), "=r"(r[3]) : "r"(addr));
}

__device__ __forceinline__ void mma_bf(float* d, const uint32_t* a, uint32_t b0, uint32_t b1) {
    asm volatile(
        "mma.sync.aligned.m16n8k16.row.col.f32.bf16.bf16.f32 "
        "{%0,%1,%2,%3}, {%4,%5,%6,%7}, {%8,%9}, {%0,%1,%2,%3};"
        : "+f"(d[0]), "+f"(d[1]), "+f"(d[2]), "+f"(d[3])
        : "r"(a[0]), "r"(a[1]), "r"(a[2]), "r"(a[3]), "r"(b0), "r"(b1));
}

__device__ __forceinline__ void mma_hf(float* d, const uint32_t* a, uint32_t b0, uint32_t b1) {
    asm volatile(
        "mma.sync.aligned.m16n8k16.row.col.f32.f16.f16.f32 "
        "{%0,%1,%2,%3}, {%4,%5,%6,%7}, {%8,%9}, {%0,%1,%2,%3};"
        : "+f"(d[0]), "+f"(d[1]), "+f"(d[2]), "+f"(d[3])
        : "r"(a[0]), "r"(a[1]), "r"(a[2]), "r"(a[3]), "r"(b0), "r"(b1));
}

__device__ __forceinline__ uint32_t pack_bf2(float a, float b) {
    __nv_bfloat16 ha = __float2bfloat16_rn(a), hb = __float2bfloat16_rn(b);
    return (uint32_t)__bfloat16_as_ushort(ha) | ((uint32_t)__bfloat16_as_ushort(hb) << 16);
}

__device__ __forceinline__ uint32_t pack_hf2(float a, float b) {
    __half ha = __float2half_rn(a), hb = __float2half_rn(b);
    return (uint32_t)__half_as_ushort(ha) | ((uint32_t)__half_as_ushort(hb) << 16);
}

// ---------------- weight split conversion ----------------
__global__ void convall_kernel(const float* __restrict__ qkv_w, const float* __restrict__ pw,
                               const float* __restrict__ f1w, const float* __restrict__ f2w,
                               __nv_bfloat16* __restrict__ dh, __nv_bfloat16* __restrict__ dl) {
    int i = blockIdx.x * 256 + threadIdx.x;
    if (i >= W_TOTAL / 4) return;
    const float* src;
    int local;
    if (i < W_PROJ_OFF / 4)      { src = qkv_w; local = i; }
    else if (i < W_FC1_OFF / 4)  { src = pw;    local = i - W_PROJ_OFF / 4; }
    else if (i < W_FC2_OFF / 4)  { src = f1w;   local = i - W_FC1_OFF / 4; }
    else                         { src = f2w;   local = i - W_FC2_OFF / 4; }
    float4 x = ((const float4*)src)[local];
    __nv_bfloat16 h0 = __float2bfloat16_rn(x.x), h1 = __float2bfloat16_rn(x.y);
    __nv_bfloat16 h2 = __float2bfloat16_rn(x.z), h3 = __float2bfloat16_rn(x.w);
    uint2 hv, lv;
    hv.x = (uint32_t)__bfloat16_as_ushort(h0) | ((uint32_t)__bfloat16_as_ushort(h1) << 16);
    hv.y = (uint32_t)__bfloat16_as_ushort(h2) | ((uint32_t)__bfloat16_as_ushort(h3) << 16);
    lv.x = pack_bf2(x.x - __bfloat162float(h0), x.y - __bfloat162float(h1));
    lv.y = pack_bf2(x.z - __bfloat162float(h2), x.w - __bfloat162float(h3));
    ((uint2*)dh)[i] = hv;
    ((uint2*)dl)[i] = lv;
}

// ---------------- init ----------------
__global__ void init_x_kernel(const float* __restrict__ xin, const float* __restrict__ cam) {
    int i = blockIdx.x * 256 + threadIdx.x;
    if (i >= NE) return;
    int t = i / C_DIM, c = i - t * C_DIM;
    float v;
    if (t == 0) v = cam[c];
    else if (t == 577) v = cam[C_DIM + c];
    else v = xin[i];
    g_x[i] = v;
}

// ---------------- LayerNorm (standalone; layer 0 only) ----------------
__global__ __launch_bounds__(256) void ln_kernel(const float* __restrict__ x,
                                                 __nv_bfloat16* __restrict__ yh, __nv_bfloat16* __restrict__ yl,
                                                 const float* __restrict__ w, const float* __restrict__ b) {
    __shared__ float sh[8];
    int t = blockIdx.x, tid = threadIdx.x;
    const float* xr = x + (size_t)t * C_DIM;
    float v0 = xr[tid], v1 = xr[tid + 256], v2 = xr[tid + 512];
    float mean = block_sum_256(v0 + v1 + v2, sh) * (1.f / 768.f);
    float d0 = v0 - mean, d1 = v1 - mean, d2 = v2 - mean;
    float var = block_sum_256(d0 * d0 + d1 * d1 + d2 * d2, sh) * (1.f / 768.f);
    float rstd = rsqrtf(var + 1e-6f);
    float o0 = d0 * rstd * w[tid]       + b[tid];
    float o1 = d1 * rstd * w[tid + 256] + b[tid + 256];
    float o2 = d2 * rstd * w[tid + 512] + b[tid + 512];
    size_t base = (size_t)t * C_DIM + tid;
    __nv_bfloat16 h0 = __float2bfloat16_rn(o0);
    __nv_bfloat16 h1 = __float2bfloat16_rn(o1);
    __nv_bfloat16 h2 = __float2bfloat16_rn(o2);
    yh[base] = h0;       yl[base]       = __float2bfloat16_rn(o0 - __bfloat162float(h0));
    yh[base + 256] = h1; yl[base + 256] = __float2bfloat16_rn(o1 - __bfloat162float(h1));
    yh[base + 512] = h2; yl[base + 512] = __float2bfloat16_rn(o2 - __bfloat162float(h2));
}

// ---------------- fused: x += gamma*(sum(part)+bias); LN(x) -> split bf16; optional loc copy ----------------
__global__ __launch_bounds__(256) void combine_ln_kernel(
    float* __restrict__ x, const float* __restrict__ part,
    const float* __restrict__ bias, const float* __restrict__ gamma, int ns,
    const float* __restrict__ w, const float* __restrict__ b,
    __nv_bfloat16* __restrict__ yh, __nv_bfloat16* __restrict__ yl,
    float* __restrict__ loc)
{
    __shared__ float sh[8];
    int t = blockIdx.x, tid = threadIdx.x;
    float v[3];
    #pragma unroll
    for (int j = 0; j < 3; j++) {
        int c = tid + j * 256;
        size_t idx = (size_t)t * C_DIM + c;
        float s = part[idx];
        if (ns > 1) s += part[NE + idx];
        if (ns > 2) s += part[2 * (size_t)NE + idx] + part[3 * (size_t)NE + idx];
        float xv = x[idx] + gamma[c] * (s + bias[c]);
        x[idx] = xv;
        if (loc) loc[idx] = xv;
        v[j] = xv;
    }
    float mean = block_sum_256(v[0] + v[1] + v[2], sh) * (1.f / 768.f);
    float d0 = v[0] - mean, d1 = v[1] - mean, d2 = v[2] - mean;
    float var = block_sum_256(d0 * d0 + d1 * d1 + d2 * d2, sh) * (1.f / 768.f);
    float rstd = rsqrtf(var + 1e-6f);
    float o0 = d0 * rstd * w[tid]       + b[tid];
    float o1 = d1 * rstd * w[tid + 256] + b[tid + 256];
    float o2 = d2 * rstd * w[tid + 512] + b[tid + 512];
    size_t base = (size_t)t * C_DIM + tid;
    __nv_bfloat16 h0 = __float2bfloat16_rn(o0);
    __nv_bfloat16 h1 = __float2bfloat16_rn(o1);
    __nv_bfloat16 h2 = __float2bfloat16_rn(o2);
    yh[base] = h0;       yl[base]       = __float2bfloat16_rn(o0 - __bfloat162float(h0));
    yh[base + 256] = h1; yl[base + 256] = __float2bfloat16_rn(o1 - __bfloat162float(h1));
    yh[base + 512] = h2; yl[base + 512] = __float2bfloat16_rn(o2 - __bfloat162float(h2));
}

// ---------------- plain combine (layer 11 fc2) ----------------
__global__ void combine_kernel(float* __restrict__ x, const float* __restrict__ part,
                               const float* __restrict__ bias, const float* __restrict__ gamma,
                               int ns) {
    int i = blockIdx.x * 256 + threadIdx.x;
    if (i >= NE) return;
    int c = i % C_DIM;
    float s = part[i];
    if (ns > 1) s += part[NE + i];
    if (ns > 2) s += part[2 * NE + i] + part[3 * NE + i];
    x[i] += gamma[c] * (s + bias[c]);
}

// ---------------- mma.sync split-bf16 GEMM ----------------
#define SM_STRIDE 40
#define STAGE_ELE 20480
#define GEMM_SMEM 81920

__global__ __launch_bounds__(256, 2) void gemm_mma(
    const __nv_bfloat16* __restrict__ Ah, const __nv_bfloat16* __restrict__ Al,
    const __nv_bfloat16* __restrict__ Wh, const __nv_bfloat16* __restrict__ Wl,
    const float* __restrict__ bias,
    float* __restrict__ Cf, __nv_bfloat16* __restrict__ Ch, __nv_bfloat16* __restrict__ Cl,
    float* __restrict__ part,
    int M, int Nn, int K, int act, int nsplit)
{
    extern __shared__ __align__(16) uint16_t sm[];
    const int tid = threadIdx.x;
    const int wid = tid >> 5, lane = tid & 31;
    const int warpM = wid >> 1, warpN = wid & 1;
    const int bm = blockIdx.y * 128, bn = blockIdx.x * 128;
    const int kz = blockIdx.z;
    const int Kp = K / nsplit;
    const int kz0 = kz * Kp;
    const uint32_t sbase = smem_u32(sm);

    float acc[2][8][4];
    #pragma unroll
    for (int i = 0; i < 2; i++)
        #pragma unroll
        for (int j = 0; j < 8; j++)
            #pragma unroll
            for (int k = 0; k < 4; k++) acc[i][j][k] = 0.f;

    const int a_row = warpM * 32 + (lane & 15);
    const int a_kc  = (lane >> 4) * 8;
    const int b_row = warpN * 64 + ((lane >> 4) & 1) * 8 + (lane & 7);
    const int b_kc  = ((lane >> 3) & 1) * 8;

    const int NC = Kp >> 5;

    auto issue = [&](int c) {
        const int s = c & 1, k0 = kz0 + (c << 5);
        const uint32_t sb = sbase + (uint32_t)s * (STAGE_ELE * 2);
        #pragma unroll
        for (int it = 0; it < 8; it++) {
            int tsk = tid + (it << 8);
            int mat = tsk >> 9;
            int v = tsk & 511;
            int r = v >> 2, seg = (v & 3) << 3;
            uint32_t sa = sb + (uint32_t)(mat * 5120 + r * SM_STRIDE + seg) * 2;
            const __nv_bfloat16* gp;
            int sz = 16;
            if (mat < 2) {
                int gr = bm + r;
                if (gr >= M) { sz = 0; gr = M - 1; }
                gp = (mat == 0 ? Ah : Al) + (size_t)gr * K + k0 + seg;
            } else {
                gp = (mat == 2 ? Wh : Wl) + (size_t)(bn + r) * K + k0 + seg;
            }
            asm volatile("cp.async.cg.shared.global [%0], [%1], 16, %2;"
                         :: "r"(sa), "l"(gp), "r"(sz));
        }
        asm volatile("cp.async.commit_group;" ::: "memory");
    };

    issue(0);
    for (int c = 0; c < NC; c++) {
        if (c + 1 < NC) {
            issue(c + 1);
            asm volatile("cp.async.wait_group 1;" ::: "memory");
        } else {
            asm volatile("cp.async.wait_group 0;" ::: "memory");
        }
        __syncthreads();

        const uint32_t st = sbase + (uint32_t)(c & 1) * (STAGE_ELE * 2);
        #pragma unroll
        for (int ks = 0; ks < 2; ks++) {
            uint32_t ah[2][4], al[2][4], bb[4][4];
            #pragma unroll
            for (int mt = 0; mt < 2; mt++) {
                uint32_t off = (uint32_t)((a_row + mt * 16) * SM_STRIDE + ks * 16 + a_kc) * 2;
                ldm4(ah[mt], st + off);
                ldm4(al[mt], st + 10240 + off);
            }
            #pragma unroll
            for (int bt = 0; bt < 4; bt++) {
                uint32_t off = (uint32_t)((b_row + bt * 16) * SM_STRIDE + ks * 16 + b_kc) * 2;
                ldm4(bb[bt], st + 20480 + off);
            }
            #pragma unroll
            for (int mt = 0; mt < 2; mt++)
                #pragma unroll
                for (int nt = 0; nt < 8; nt++) {
                    mma_bf(acc[mt][nt], ah[mt], bb[nt >> 1][(nt & 1) * 2], bb[nt >> 1][(nt & 1) * 2 + 1]);
                    mma_bf(acc[mt][nt], al[mt], bb[nt >> 1][(nt & 1) * 2], bb[nt >> 1][(nt & 1) * 2 + 1]);
                }
            #pragma unroll
            for (int bt = 0; bt < 4; bt++) {
                uint32_t off = (uint32_t)((b_row + bt * 16) * SM_STRIDE + ks * 16 + b_kc) * 2;
                ldm4(bb[bt], st + 30720 + off);
            }
            #pragma unroll
            for (int mt = 0; mt < 2; mt++)
                #pragma unroll
                for (int nt = 0; nt < 8; nt++)
                    mma_bf(acc[mt][nt], ah[mt], bb[nt >> 1][(nt & 1) * 2], bb[nt >> 1][(nt & 1) * 2 + 1]);
        }
        __syncthreads();
    }

    #pragma unroll
    for (int mt = 0; mt < 2; mt++) {
        int rb = bm + warpM * 32 + mt * 16 + (lane >> 2);
        #pragma unroll
        for (int half = 0; half < 2; half++) {
            int rr = rb + half * 8;
            if (rr >= M) continue;
            #pragma unroll
            for (int nt = 0; nt < 8; nt++) {
                int col = bn + warpN * 64 + nt * 8 + ((lane & 3) << 1);
                size_t o = (size_t)rr * Nn + col;
                if (nsplit > 1) {
                    *(float2*)(part + (size_t)kz * ((size_t)M * Nn) + o) =
                        make_float2(acc[mt][nt][half * 2 + 0], acc[mt][nt][half * 2 + 1]);
                    continue;
                }
                float v0 = acc[mt][nt][half * 2 + 0] + bias[col];
                float v1 = acc[mt][nt][half * 2 + 1] + bias[col + 1];
                if (act) { v0 = v0 * normcdff(v0); v1 = v1 * normcdff(v1); }
                if (Ch) {
                    __nv_bfloat16 h0 = __float2bfloat16_rn(v0), h1 = __float2bfloat16_rn(v1);
                    uint32_t hp = (uint32_t)__bfloat16_as_ushort(h0) | ((uint32_t)__bfloat16_as_ushort(h1) << 16);
                    uint32_t lp = pack_bf2(v0 - __bfloat162float(h0), v1 - __bfloat162float(h1));
                    *(uint32_t*)(Ch + o) = hp;
                    *(uint32_t*)(Cl + o) = lp;
                } else {
                    *(float2*)(Cf + o) = make_float2(v0, v1);
                }
            }
        }
    }
}

// ---------------- QKV post: combine 2 partials + bias, RMS norm + RoPE; emits fp16 ----------------
__global__ void qkvpost_kernel(const float* __restrict__ part, const float* __restrict__ qb,
                               const float* __restrict__ qn, const float* __restrict__ kn,
                               const float* __restrict__ rc, const float* __restrict__ rs,
                               __half* __restrict__ Qh, __half* __restrict__ Ql,
                               __half* __restrict__ Kh, __half* __restrict__ Vh,
                               int posmod)
{
    int gw = (blockIdx.x * blockDim.x + threadIdx.x) >> 5;
    int lane = threadIdx.x & 31;
    int t = gw / NHEAD, h = gw - (gw / NHEAD) * NHEAD;
    if (t >= T_TOT) return;
    const float* r0 = part + (size_t)t * 2304 + h * 64;
    const float* r1 = r0 + QKV_PART_STRIDE;
    const float* bb = qb + h * 64;
    float q0 = r0[lane] + r1[lane] + bb[lane];
    float q1 = r0[lane + 32] + r1[lane + 32] + bb[lane + 32];
    float k0 = r0[768 + lane] + r1[768 + lane] + qb[768 + h * 64 + lane];
    float k1 = r0[768 + lane + 32] + r1[768 + lane + 32] + qb[768 + h * 64 + lane + 32];
    float v0 = r0[1536 + lane] + r1[1536 + lane] + qb[1536 + h * 64 + lane];
    float v1 = r0[1536 + lane + 32] + r1[1536 + lane + 32] + qb[1536 + h * 64 + lane + 32];
    float sq = q0 * q0 + q1 * q1, sk = k0 * k0 + k1 * k1;
    #pragma unroll
    for (int off = 16; off; off >>= 1) {
        sq += __shfl_xor_sync(0xffffffffu, sq, off);
        sk += __shfl_xor_sync(0xffffffffu, sk, off);
    }
    float rq = rsqrtf(sq * (1.f / 64.f) + 1e-6f);
    float rk = rsqrtf(sk * (1.f / 64.f) + 1e-6f);
    q0 *= rq * qn[lane]; q1 *= rq * qn[lane + 32];
    k0 *= rk * kn[lane]; k1 *= rk * kn[lane + 32];
    int pos = t % posmod;
    const float* cr = rc + (size_t)pos * 64;
    const float* sr = rs + (size_t)pos * 64;
    float c0 = cr[lane], c1 = cr[lane + 32];
    float s0 = sr[lane], s1 = sr[lane + 32];
    float sgn = (lane < 16) ? -1.f : 1.f;
    float qp0 = __shfl_xor_sync(0xffffffffu, q0, 16);
    float qp1 = __shfl_xor_sync(0xffffffffu, q1, 16);
    float kp0 = __shfl_xor_sync(0xffffffffu, k0, 16);
    float kp1 = __shfl_xor_sync(0xffffffffu, k1, 16);
    float qo0 = (q0 * c0 + sgn * qp0 * s0) * 0.125f;
    float qo1 = (q1 * c1 + sgn * qp1 * s1) * 0.125f;
    float ko0 = k0 * c0 + sgn * kp0 * s0;
    float ko1 = k1 * c1 + sgn * kp1 * s1;
    size_t base = ((size_t)h * T_TOT + t) * 64;
    __half hh;
    hh = __float2half_rn(qo0); Qh[base + lane] = hh;      Ql[base + lane]      = __float2half_rn(qo0 - __half2float(hh));
    hh = __float2half_rn(qo1); Qh[base + 32 + lane] = hh; Ql[base + 32 + lane] = __float2half_rn(qo1 - __half2float(hh));
    Kh[base + lane]      = __float2half_rn(ko0);
    Kh[base + 32 + lane] = __float2half_rn(ko1);
    Vh[base + lane]      = __float2half_rn(v0);
    Vh[base + 32 + lane] = __float2half_rn(v1);
}

// ---------------- fp16 tensor-core flash attention ----------------
// CTA: 64 q x 1 head; 4 warps x 16 q. 64-key tiles, double-buffered. QK: qh*k+ql*k; PV: ph*v+pl*v.
#define ATT_STRIDE 72
#define A_QH 0
#define A_QL 4608
#define A_STG 9216
#define A_STG_ELE 9216            // K(4608) + V(4608) per stage
#define ATT_SMEM (27648 * 2)      // 55296 bytes

__global__ __launch_bounds__(128) void attn_mma(
    const __half* __restrict__ Qh, const __half* __restrict__ Ql,
    const __half* __restrict__ Kh, const __half* __restrict__ Vh,
    const float* __restrict__ kvmask,
    __nv_bfloat16* __restrict__ Oh, __nv_bfloat16* __restrict__ Ol, int nq)
{
    extern __shared__ __align__(16) uint16_t smA[];
    const int tid = threadIdx.x, wid = tid >> 5, lane = tid & 31;
    const int qt = blockIdx.x, h = blockIdx.y, z = blockIdx.z;
    const int t0 = z * nq;
    const size_t hb = (size_t)h * T_TOT * 64;
    const uint32_t sbase = smem_u32(smA);
    const float* kvrow = kvmask + (size_t)z * nq;

    // load Q tile (hi/lo fp16)
    for (int i = tid; i < 512; i += 128) {
        int r = i >> 3, sg = i & 7;
        int qrow = qt * 64 + r;
        uint4 vh = make_uint4(0, 0, 0, 0), vl = make_uint4(0, 0, 0, 0);
        if (qrow < nq) {
            size_t go = hb + (size_t)(t0 + qrow) * 64 + sg * 8;
            vh = *(const uint4*)(Qh + go);
            vl = *(const uint4*)(Ql + go);
        }
        *(uint4*)((char*)smA + (A_QH + r * ATT_STRIDE + sg * 8) * 2) = vh;
        *(uint4*)((char*)smA + (A_QL + r * ATT_STRIDE + sg * 8) * 2) = vl;
    }
    __syncthreads();

    uint32_t qhf[4][4], qlf[4][4];
    {
        int arow = wid * 16 + (lane & 15);
        int akc = (lane >> 4) * 8;
        #pragma unroll
        for (int kc = 0; kc < 4; kc++) {
            uint32_t off = (uint32_t)(arow * ATT_STRIDE + kc * 16 + akc) * 2;
            ldm4(qhf[kc], sbase + A_QH * 2 + off);
            ldm4(qlf[kc], sbase + A_QL * 2 + off);
        }
    }

    auto stage_load = [&](int kt) {
        int s = kt & 1;
        uint32_t sb = sbase + (uint32_t)(A_STG + s * A_STG_ELE) * 2;
        int kbase = kt * 64;
        #pragma unroll
        for (int it = 0; it < 8; it++) {
            int i = tid + it * 128;
            int m = i >> 9, v = i & 511, r = v >> 3, sg = v & 7;
            int key = kbase + r;
            int sz = 16;
            if (key >= nq) { sz = 0; key = nq - 1; }
            const __half* gp = (m == 0 ? Kh : Vh) + hb + (size_t)(t0 + key) * 64 + sg * 8;
            uint32_t da = sb + (uint32_t)(m * 4608 + r * ATT_STRIDE + sg * 8) * 2;
            asm volatile("cp.async.cg.shared.global [%0], [%1], 16, %2;"
                         :: "r"(da), "l"(gp), "r"(sz));
        }
        asm volatile("cp.async.commit_group;" ::: "memory");
    };

    float o[8][4];
    #pragma unroll
    for (int i = 0; i < 8; i++)
        #pragma unroll
        for (int j = 0; j < 4; j++) o[i][j] = 0.f;
    float m0 = -1e30f, m1 = -1e30f, l0 = 0.f, l1 = 0.f;

    const int nkt = (nq + 63) >> 6;
    const int brow = ((lane >> 4) & 1) * 8 + (lane & 7);
    const int bkc = ((lane >> 3) & 1) * 8;
    const int vr0 = ((lane >> 3) & 1) * 8 + (lane & 7);
    const int vc0 = (lane >> 4) * 8;

    stage_load(0);
    for (int kt = 0; kt < nkt; kt++) {
        if (kt + 1 < nkt) {
            stage_load(kt + 1);
            asm volatile("cp.async.wait_group 1;" ::: "memory");
        } else {
            asm volatile("cp.async.wait_group 0;" ::: "memory");
        }
        __syncthreads();
        uint32_t sb = sbase + (uint32_t)(A_STG + (kt & 1) * A_STG_ELE) * 2;
        int kbase = kt * 64;

        float s_[8][4];
        #pragma unroll
        for (int nt = 0; nt < 8; nt++) {
            int key = kbase + nt * 8 + ((lane & 3) << 1);
            float b0 = (key < nq) ? (1.f - kvrow[key]) * -10000.f : -1e30f;
            float b1 = (key + 1 < nq) ? (1.f - kvrow[key + 1]) * -10000.f : -1e30f;
            s_[nt][0] = b0; s_[nt][1] = b1; s_[nt][2] = b0; s_[nt][3] = b1;
        }
        // QK^T: 2 terms
        #pragma unroll
        for (int np = 0; np < 4; np++) {
            #pragma unroll
            for (int kc = 0; kc < 4; kc++) {
                uint32_t off = (uint32_t)((np * 16 + brow) * ATT_STRIDE + kc * 16 + bkc) * 2;
                uint32_t kh4[4];
                ldm4(kh4, sb + off);
                mma_hf(s_[2 * np],     qhf[kc], kh4[0], kh4[1]);
                mma_hf(s_[2 * np + 1], qhf[kc], kh4[2], kh4[3]);
                mma_hf(s_[2 * np],     qlf[kc], kh4[0], kh4[1]);
                mma_hf(s_[2 * np + 1], qlf[kc], kh4[2], kh4[3]);
            }
        }
        // online softmax
        float mx0 = -1e30f, mx1 = -1e30f;
        #pragma unroll
        for (int nt = 0; nt < 8; nt++) {
            mx0 = fmaxf(mx0, fmaxf(s_[nt][0], s_[nt][1]));
            mx1 = fmaxf(mx1, fmaxf(s_[nt][2], s_[nt][3]));
        }
        mx0 = fmaxf(mx0, __shfl_xor_sync(0xffffffffu, mx0, 1));
        mx0 = fmaxf(mx0, __shfl_xor_sync(0xffffffffu, mx0, 2));
        mx1 = fmaxf(mx1, __shfl_xor_sync(0xffffffffu, mx1, 1));
        mx1 = fmaxf(mx1, __shfl_xor_sync(0xffffffffu, mx1, 2));
        float mn0 = fmaxf(m0, mx0), mn1 = fmaxf(m1, mx1);
        float sc0 = __expf(m0 - mn0), sc1 = __expf(m1 - mn1);
        m0 = mn0; m1 = mn1;
        float ps0 = 0.f, ps1 = 0.f;
        #pragma unroll
        for (int nt = 0; nt < 8; nt++) {
            s_[nt][0] = __expf(s_[nt][0] - mn0); ps0 += s_[nt][0];
            s_[nt][1] = __expf(s_[nt][1] - mn0); ps0 += s_[nt][1];
            s_[nt][2] = __expf(s_[nt][2] - mn1); ps1 += s_[nt][2];
            s_[nt][3] = __expf(s_[nt][3] - mn1); ps1 += s_[nt][3];
        }
        ps0 += __shfl_xor_sync(0xffffffffu, ps0, 1);
        ps0 += __shfl_xor_sync(0xffffffffu, ps0, 2);
        ps1 += __shfl_xor_sync(0xffffffffu, ps1, 1);
        ps1 += __shfl_xor_sync(0xffffffffu, ps1, 2);
        l0 = l0 * sc0 + ps0;
        l1 = l1 * sc1 + ps1;
        #pragma unroll
        for (int nt = 0; nt < 8; nt++) {
            o[nt][0] *= sc0; o[nt][1] *= sc0; o[nt][2] *= sc1; o[nt][3] *= sc1;
        }
        // P fragments fp16 (hi/lo)
        uint32_t pfh[4][4], pfl[4][4];
        #pragma unroll
        for (int kc = 0; kc < 4; kc++) {
            #pragma unroll
            for (int q = 0; q < 4; q++) {
                float a = s_[2 * kc + (q >> 1)][(q & 1) * 2];
                float b = s_[2 * kc + (q >> 1)][(q & 1) * 2 + 1];
                __half ha = __float2half_rn(a), hb2 = __float2half_rn(b);
                pfh[kc][q] = (uint32_t)__half_as_ushort(ha) | ((uint32_t)__half_as_ushort(hb2) << 16);
                pfl[kc][q] = pack_hf2(a - __half2float(ha), b - __half2float(hb2));
            }
        }
        // P·V: 2 terms
        #pragma unroll
        for (int kc = 0; kc < 4; kc++) {
            #pragma unroll
            for (int dp = 0; dp < 4; dp++) {
                uint32_t off = (uint32_t)((kc * 16 + vr0) * ATT_STRIDE + dp * 16 + vc0) * 2;
                uint32_t vh4[4];
                ldm4t(vh4, sb + 4608 * 2 + off);
                mma_hf(o[2 * dp],     pfh[kc], vh4[0], vh4[1]);
                mma_hf(o[2 * dp + 1], pfh[kc], vh4[2], vh4[3]);
                mma_hf(o[2 * dp],     pfl[kc], vh4[0], vh4[1]);
                mma_hf(o[2 * dp + 1], pfl[kc], vh4[2], vh4[3]);
            }
        }
        __syncthreads();
    }

    float inv0 = 1.f / l0, inv1 = 1.f / l1;
    int r = lane >> 2;
    int q0row = qt * 64 + wid * 16 + r;
    int q1row = q0row + 8;
    #pragma unroll
    for (int nt = 0; nt < 8; nt++) {
        int d = nt * 8 + ((lane & 3) << 1);
        if (q0row < nq) {
            float a = o[nt][0] * inv0, b = o[nt][1] * inv0;
            size_t ob = (size_t)(t0 + q0row) * C_DIM + h * 64 + d;
            __nv_bfloat16 ha = __float2bfloat16_rn(a), hb2 = __float2bfloat16_rn(b);
            *(uint32_t*)(Oh + ob) = (uint32_t)__bfloat16_as_ushort(ha) | ((uint32_t)__bfloat16_as_ushort(hb2) << 16);
            *(uint32_t*)(Ol + ob) = pack_bf2(a - __bfloat162float(ha), b - __bfloat162float(hb2));
        }
        if (q1row < nq) {
            float a = o[nt][2] * inv1, b = o[nt][3] * inv1;
            size_t ob = (size_t)(t0 + q1row) * C_DIM + h * 64 + d;
            __nv_bfloat16 ha = __float2bfloat16_rn(a), hb2 = __float2bfloat16_rn(b);
            *(uint32_t*)(Oh + ob) = (uint32_t)__bfloat16_as_ushort(ha) | ((uint32_t)__bfloat16_as_ushort(hb2) << 16);
            *(uint32_t*)(Ol + ob) = pack_bf2(a - __bfloat162float(ha), b - __bfloat162float(hb2));
        }
    }
}

// ---------------- emit output ----------------
__global__ __launch_bounds__(256) void emit_kernel(const float* __restrict__ xloc, const float* __restrict__ xg,
                                                   const float* __restrict__ fw, const float* __restrict__ fb,
                                                   float* __restrict__ out)
{
    __shared__ float sh[8];
    int row = blockIdx.x;
    int s = row / 576, n = row - s * 576 + 1;
    int t = s * 577 + n;
    int tid = threadIdx.x;
    const float* xr = xg + (size_t)t * C_DIM;
    float v0 = xr[tid], v1 = xr[tid + 256], v2 = xr[tid + 512];
    float mean = block_sum_256(v0 + v1 + v2, sh) * (1.f / 768.f);
    float d0 = v0 - mean, d1 = v1 - mean, d2 = v2 - mean;
    float var = block_sum_256(d0 * d0 + d1 * d1 + d2 * d2, sh) * (1.f / 768.f);
    float rstd = rsqrtf(var + 1e-6f);
    const float* lr = xloc + (size_t)t * C_DIM;
    float* orow = out + (size_t)row * 1536;
    orow[tid]       = lr[tid];
    orow[tid + 256] = lr[tid + 256];
    orow[tid + 512] = lr[tid + 512];
    orow[768 + tid]       = d0 * rstd * fw[tid]       + fb[tid];
    orow[768 + tid + 256] = d1 * rstd * fw[tid + 256] + fb[tid + 256];
    orow[768 + tid + 512] = d2 * rstd * fw[tid + 512] + fb[tid + 512];
}

__global__ void cam_kernel(const float* __restrict__ xloc, const float* __restrict__ xg,
                           float* __restrict__ out) {
    int s = blockIdx.x;
    int t = s * 577;
    for (int c = threadIdx.x; c < C_DIM; c += 256) {
        out[s * 1536 + c]       = xloc[(size_t)t * C_DIM + c];
        out[s * 1536 + 768 + c] = xg[(size_t)t * C_DIM + c];
    }
}

// ---------------- host orchestration ----------------
extern "C" void kernel_launch(void* const* d_in, const int* in_sizes, int n_in,
                              void* d_out, int out_size)
{
    const float* x_in  = (const float*)d_in[0];
    const float* rc_l  = (const float*)d_in[1];
    const float* rs_l  = (const float*)d_in[2];
    const float* rc_g  = (const float*)d_in[3];
    const float* rs_g  = (const float*)d_in[4];
    const float* kv_l  = (const float*)d_in[5];
    const float* kv_g  = (const float*)d_in[6];
    const float* cam   = (const float*)d_in[7];
    const float* qkv_w = (const float*)d_in[8];
    const float* qkv_b = (const float*)d_in[9];
    const float* qn_w  = (const float*)d_in[10];
    const float* kn_w  = (const float*)d_in[11];
    const float* pw    = (const float*)d_in[12];
    const float* pb    = (const float*)d_in[13];
    const float* g1    = (const float*)d_in[14];
    const float* g2    = (const float*)d_in[15];
    const float* n1w   = (const float*)d_in[16];
    const float* n1b   = (const float*)d_in[17];
    const float* n2w   = (const float*)d_in[18];
    const float* n2b   = (const float*)d_in[19];
    const float* f1w   = (const float*)d_in[20];
    const float* f1b   = (const float*)d_in[21];
    const float* f2w   = (const float*)d_in[22];
    const float* f2b   = (const float*)d_in[23];
    const float* fnw   = (const float*)d_in[24];
    const float* fnb   = (const float*)d_in[25];
    float* out = (float*)d_out;

    float *p_x, *p_loc, *p_part;
    __nv_bfloat16 *p_wh, *p_wl, *p_sh, *p_sl, *p_mh, *p_ml;
    __half *p_qh, *p_ql, *p_kh, *p_vh;
    cudaGetSymbolAddress((void**)&p_x,   g_x);
    cudaGetSymbolAddress((void**)&p_loc, g_loc);
    cudaGetSymbolAddress((void**)&p_part, g_part);
    cudaGetSymbolAddress((void**)&p_wh,  g_wh);
    cudaGetSymbolAddress((void**)&p_wl,  g_wl);
    cudaGetSymbolAddress((void**)&p_sh,  g_sh);
    cudaGetSymbolAddress((void**)&p_sl,  g_sl);
    cudaGetSymbolAddress((void**)&p_mh,  g_mh);
    cudaGetSymbolAddress((void**)&p_ml,  g_ml);
    cudaGetSymbolAddress((void**)&p_qh,  g_qh);
    cudaGetSymbolAddress((void**)&p_ql,  g_ql);
    cudaGetSymbolAddress((void**)&p_kh,  g_kh);
    cudaGetSymbolAddress((void**)&p_vh,  g_vh);

    cudaFuncSetAttribute(gemm_mma, cudaFuncAttributeMaxDynamicSharedMemorySize, GEMM_SMEM);
    cudaFuncSetAttribute(attn_mma, cudaFuncAttributeMaxDynamicSharedMemorySize, ATT_SMEM);

    const int eb = (NE + 255) / 256;
    convall_kernel<<<(W_TOTAL / 4 + 255) / 256, 256>>>(qkv_w, pw, f1w, f2w, p_wh, p_wl);
    init_x_kernel<<<eb, 256>>>(x_in, cam);

    int outidx = 0;
    for (int i = 0; i < 12; i++) {
        bool isg = (i & 1);
        int nb = isg ? 1 : 2;
        int nq = isg ? 1154 : 577;
        const float* rc = isg ? rc_g : rc_l;
        const float* rs = isg ? rs_g : rs_l;
        const float* kv = isg ? kv_g : kv_l;

        if (i == 0)
            ln_kernel<<<T_TOT, 256>>>(p_x, p_sh, p_sl, n1w, n1b);
        // QKV: split-K=2; combine+bias folded into qkvpost
        gemm_mma<<<dim3(18, 10, 2), 256, GEMM_SMEM>>>(
            p_sh, p_sl, p_wh + W_QKV_OFF + (size_t)i * 2304 * 768, p_wl + W_QKV_OFF + (size_t)i * 2304 * 768,
            nullptr, nullptr, nullptr, nullptr, p_part, T_TOT, 2304, 768, 0, 2);
        qkvpost_kernel<<<(T_TOT * NHEAD * 32 + 127) / 128, 128>>>(
            p_part, qkv_b + i * 2304, qn_w + i * 64, kn_w + i * 64, rc, rs,
            p_qh, p_ql, p_kh, p_vh, nq);
        attn_mma<<<dim3((nq + 63) / 64, NHEAD, nb), 128, ATT_SMEM>>>(
            p_qh, p_ql, p_kh, p_vh, kv, p_sh, p_sl, nq);
        // proj: split-K=2 -> fused combine + LN2
        gemm_mma<<<dim3(6, 10, 2), 256, GEMM_SMEM>>>(
            p_sh, p_sl, p_wh + W_PROJ_OFF + (size_t)i * 768 * 768, p_wl + W_PROJ_OFF + (size_t)i * 768 * 768,
            nullptr, nullptr, nullptr, nullptr, p_part, T_TOT, 768, 768, 0, 2);
        combine_ln_kernel<<<T_TOT, 256>>>(p_x, p_part, pb + i * 768, g1 + i * 768, 2,
                                          n2w + i * 768, n2b + i * 768, p_sh, p_sl, nullptr);
        // fc1: direct epilogue (bias+GELU+split)
        gemm_mma<<<dim3(24, 10, 1), 256, GEMM_SMEM>>>(
            p_sh, p_sl, p_wh + W_FC1_OFF + (size_t)i * 3072 * 768, p_wl + W_FC1_OFF + (size_t)i * 3072 * 768,
            f1b + i * 3072, nullptr, p_mh, p_ml, nullptr, T_TOT, 3072, 768, 1, 1);
        // fc2: split-K=4 -> fused combine + next-layer LN1 (or plain combine at layer 11)
        gemm_mma<<<dim3(6, 10, 4), 256, GEMM_SMEM>>>(
            p_mh, p_ml, p_wh + W_FC2_OFF + (size_t)i * 768 * 3072, p_wl + W_FC2_OFF + (size_t)i * 768 * 3072,
            nullptr, nullptr, nullptr, nullptr, p_part, T_TOT, 768, 3072, 0, 4);
        if (i < 11) {
            float* locp = (i == 4 || i == 10) ? p_loc : nullptr;
            combine_ln_kernel<<<T_TOT, 256>>>(p_x, p_part, f2b + i * 768, g2 + i * 768, 4,
                                              n1w + (i + 1) * 768, n1b + (i + 1) * 768, p_sh, p_sl, locp);
        } else {
            combine_kernel<<<eb, 256>>>(p_x, p_part, f2b + i * 768, g2 + i * 768, 4);
        }

        if (i == 2 || i == 5 || i == 8 || i == 11) {
            const float* loc = (i == 5 || i == 11) ? p_loc : p_x;
            emit_kernel<<<1152, 256>>>(loc, p_x, fnw, fnb, out + (size_t)outidx * 1769472);
            if (i == 11) cam_kernel<<<2, 256>>>(loc, p_x, out + 4ull * 1769472);
            outidx++;
        }
    }
}

// round 9
// speedup vs baseline: 4.9596x; 1.2741x over previous
#include <cuda_runtime.h>
#include <cuda_fp16.h>
#include <math.h>
#include <stdint.h>

#define T_TOT 1154
#define C_DIM 768
#define NHEAD 12
#define NE (T_TOT * C_DIM)
#define QKV_PART_STRIDE 2658816     // 1154*2304

// weight offsets (elements)
#define W_QKV_OFF 0
#define W_PROJ_OFF 21233664
#define W_FC1_OFF  28311552
#define W_FC2_OFF  56623104
#define W_TOTAL    84934656

// ---------------- device scratch ----------------
__device__ float g_x[NE];
__device__ float g_loc[NE];
__device__ float g_part[2 * QKV_PART_STRIDE];
__device__ __half g_w[W_TOTAL];          // weights: single fp16
__device__ __half g_sh[NE];              // activation hi
__device__ __half g_sl[NE];              // activation lo
__device__ __half g_mh[NE * 4];
__device__ __half g_ml[NE * 4];
__device__ __half g_qh[NHEAD * T_TOT * 64];
__device__ __half g_ql[NHEAD * T_TOT * 64];
__device__ __half g_kh[NHEAD * T_TOT * 64];
__device__ __half g_vh[NHEAD * T_TOT * 64];

// ---------------- helpers ----------------
__device__ __forceinline__ float block_sum_256(float v, float* sh) {
    #pragma unroll
    for (int off = 16; off; off >>= 1) v += __shfl_xor_sync(0xffffffffu, v, off);
    __syncthreads();
    if ((threadIdx.x & 31) == 0) sh[threadIdx.x >> 5] = v;
    __syncthreads();
    float r = 0.f;
    #pragma unroll
    for (int i = 0; i < 8; i++) r += sh[i];
    return r;
}

__device__ __forceinline__ uint32_t smem_u32(const void* p) {
    uint32_t a;
    asm("{ .reg .u64 t; cvta.to.shared.u64 t, %1; cvt.u32.u64 %0, t; }" : "=r"(a) : "l"(p));
    return a;
}

__device__ __forceinline__ void ldm4(uint32_t* r, uint32_t addr) {
    asm volatile("ldmatrix.sync.aligned.m8n8.x4.shared.b16 {%0,%1,%2,%3}, [%4];"
                 : "=r"(r[0]), "=r"(r[1]), "=r"(r[2]), "=r"(r[3]) : "r"(addr));
}

__device__ __forceinline__ void ldm4t(uint32_t* r, uint32_t addr) {
    asm volatile("ldmatrix.sync.aligned.m8n8.x4.trans.shared.b16 {%0,%1,%2,%3}, [%4];"
                 : "=r"(r[0]), "=r"(r[1]), "=r"(r[2]), "=r"(r[3]) : "r"(addr));
}

__device__ __forceinline__ void mma_hf(float* d, const uint32_t* a, uint32_t b0, uint32_t b1) {
    asm volatile(
        "mma.sync.aligned.m16n8k16.row.col.f32.f16.f16.f32 "
        "{%0,%1,%2,%3}, {%4,%5,%6,%7}, {%8,%9}, {%0,%1,%2,%3};"
        : "+f"(d[0]), "+f"(d[1]), "+f"(d[2]), "+f"(d[3])
        : "r"(a[0]), "r"(a[1]), "r"(a[2]), "r"(a[3]), "r"(b0), "r"(b1));
}

__device__ __forceinline__ uint32_t pack_hf2(float a, float b) {
    __half ha = __float2half_rn(a), hb = __float2half_rn(b);
    return (uint32_t)__half_as_ushort(ha) | ((uint32_t)__half_as_ushort(hb) << 16);
}

// ---------------- weight conversion: fp32 -> single fp16 ----------------
__global__ void convall_kernel(const float* __restrict__ qkv_w, const float* __restrict__ pw,
                               const float* __restrict__ f1w, const float* __restrict__ f2w,
                               __half* __restrict__ dw) {
    int i = blockIdx.x * 256 + threadIdx.x;
    if (i >= W_TOTAL / 4) return;
    const float* src;
    int local;
    if (i < W_PROJ_OFF / 4)      { src = qkv_w; local = i; }
    else if (i < W_FC1_OFF / 4)  { src = pw;    local = i - W_PROJ_OFF / 4; }
    else if (i < W_FC2_OFF / 4)  { src = f1w;   local = i - W_FC1_OFF / 4; }
    else                         { src = f2w;   local = i - W_FC2_OFF / 4; }
    float4 x = ((const float4*)src)[local];
    uint2 hv;
    hv.x = pack_hf2(x.x, x.y);
    hv.y = pack_hf2(x.z, x.w);
    ((uint2*)dw)[i] = hv;
}

// ---------------- init ----------------
__global__ void init_x_kernel(const float* __restrict__ xin, const float* __restrict__ cam) {
    int i = blockIdx.x * 256 + threadIdx.x;
    if (i >= NE) return;
    int t = i / C_DIM, c = i - t * C_DIM;
    float v;
    if (t == 0) v = cam[c];
    else if (t == 577) v = cam[C_DIM + c];
    else v = xin[i];
    g_x[i] = v;
}

// ---------------- LayerNorm (standalone; layer 0 only), emits split fp16 ----------------
__global__ __launch_bounds__(256) void ln_kernel(const float* __restrict__ x,
                                                 __half* __restrict__ yh, __half* __restrict__ yl,
                                                 const float* __restrict__ w, const float* __restrict__ b) {
    __shared__ float sh[8];
    int t = blockIdx.x, tid = threadIdx.x;
    const float* xr = x + (size_t)t * C_DIM;
    float v0 = xr[tid], v1 = xr[tid + 256], v2 = xr[tid + 512];
    float mean = block_sum_256(v0 + v1 + v2, sh) * (1.f / 768.f);
    float d0 = v0 - mean, d1 = v1 - mean, d2 = v2 - mean;
    float var = block_sum_256(d0 * d0 + d1 * d1 + d2 * d2, sh) * (1.f / 768.f);
    float rstd = rsqrtf(var + 1e-6f);
    float o0 = d0 * rstd * w[tid]       + b[tid];
    float o1 = d1 * rstd * w[tid + 256] + b[tid + 256];
    float o2 = d2 * rstd * w[tid + 512] + b[tid + 512];
    size_t base = (size_t)t * C_DIM + tid;
    __half h0 = __float2half_rn(o0);
    __half h1 = __float2half_rn(o1);
    __half h2 = __float2half_rn(o2);
    yh[base] = h0;       yl[base]       = __float2half_rn(o0 - __half2float(h0));
    yh[base + 256] = h1; yl[base + 256] = __float2half_rn(o1 - __half2float(h1));
    yh[base + 512] = h2; yl[base + 512] = __float2half_rn(o2 - __half2float(h2));
}

// ---------------- fused: combine + residual + LN -> split fp16; optional loc copy ----------------
__global__ __launch_bounds__(256) void combine_ln_kernel(
    float* __restrict__ x, const float* __restrict__ part,
    const float* __restrict__ bias, const float* __restrict__ gamma, int ns,
    const float* __restrict__ w, const float* __restrict__ b,
    __half* __restrict__ yh, __half* __restrict__ yl,
    float* __restrict__ loc)
{
    __shared__ float sh[8];
    int t = blockIdx.x, tid = threadIdx.x;
    float v[3];
    #pragma unroll
    for (int j = 0; j < 3; j++) {
        int c = tid + j * 256;
        size_t idx = (size_t)t * C_DIM + c;
        float s = part[idx];
        if (ns > 1) s += part[NE + idx];
        if (ns > 2) s += part[2 * (size_t)NE + idx] + part[3 * (size_t)NE + idx];
        float xv = x[idx] + gamma[c] * (s + bias[c]);
        x[idx] = xv;
        if (loc) loc[idx] = xv;
        v[j] = xv;
    }
    float mean = block_sum_256(v[0] + v[1] + v[2], sh) * (1.f / 768.f);
    float d0 = v[0] - mean, d1 = v[1] - mean, d2 = v[2] - mean;
    float var = block_sum_256(d0 * d0 + d1 * d1 + d2 * d2, sh) * (1.f / 768.f);
    float rstd = rsqrtf(var + 1e-6f);
    float o0 = d0 * rstd * w[tid]       + b[tid];
    float o1 = d1 * rstd * w[tid + 256] + b[tid + 256];
    float o2 = d2 * rstd * w[tid + 512] + b[tid + 512];
    size_t base = (size_t)t * C_DIM + tid;
    __half h0 = __float2half_rn(o0);
    __half h1 = __float2half_rn(o1);
    __half h2 = __float2half_rn(o2);
    yh[base] = h0;       yl[base]       = __float2half_rn(o0 - __half2float(h0));
    yh[base + 256] = h1; yl[base + 256] = __float2half_rn(o1 - __half2float(h1));
    yh[base + 512] = h2; yl[base + 512] = __float2half_rn(o2 - __half2float(h2));
}

// ---------------- plain combine (layer 11 fc2) ----------------
__global__ void combine_kernel(float* __restrict__ x, const float* __restrict__ part,
                               const float* __restrict__ bias, const float* __restrict__ gamma,
                               int ns) {
    int i = blockIdx.x * 256 + threadIdx.x;
    if (i >= NE) return;
    int c = i % C_DIM;
    float s = part[i];
    if (ns > 1) s += part[NE + i];
    if (ns > 2) s += part[2 * NE + i] + part[3 * NE + i];
    x[i] += gamma[c] * (s + bias[c]);
}

// ---------------- fp16 2-term GEMM: (Ah+Al) @ W^T, fp32 accum ----------------
// smem stage: Ah(5120) Al(5120) W(5120) halves; 2 stages
#define SM_STRIDE 40
#define STAGE_ELE 15360
#define GEMM_SMEM 61440

__global__ __launch_bounds__(256, 2) void gemm_mma(
    const __half* __restrict__ Ah, const __half* __restrict__ Al,
    const __half* __restrict__ W,
    const float* __restrict__ bias,
    float* __restrict__ Cf, __half* __restrict__ Ch, __half* __restrict__ Cl,
    float* __restrict__ part,
    int M, int Nn, int K, int act, int nsplit)
{
    extern __shared__ __align__(16) uint16_t sm[];
    const int tid = threadIdx.x;
    const int wid = tid >> 5, lane = tid & 31;
    const int warpM = wid >> 1, warpN = wid & 1;
    const int bm = blockIdx.y * 128, bn = blockIdx.x * 128;
    const int kz = blockIdx.z;
    const int Kp = K / nsplit;
    const int kz0 = kz * Kp;
    const uint32_t sbase = smem_u32(sm);

    float acc[2][8][4];
    #pragma unroll
    for (int i = 0; i < 2; i++)
        #pragma unroll
        for (int j = 0; j < 8; j++)
            #pragma unroll
            for (int k = 0; k < 4; k++) acc[i][j][k] = 0.f;

    const int a_row = warpM * 32 + (lane & 15);
    const int a_kc  = (lane >> 4) * 8;
    const int b_row = warpN * 64 + ((lane >> 4) & 1) * 8 + (lane & 7);
    const int b_kc  = ((lane >> 3) & 1) * 8;

    const int NC = Kp >> 5;

    auto issue = [&](int c) {
        const int s = c & 1, k0 = kz0 + (c << 5);
        const uint32_t sb = sbase + (uint32_t)s * (STAGE_ELE * 2);
        #pragma unroll
        for (int it = 0; it < 6; it++) {
            int tsk = tid + (it << 8);
            int mat = tsk >> 9;
            int v = tsk & 511;
            int r = v >> 2, seg = (v & 3) << 3;
            uint32_t sa = sb + (uint32_t)(mat * 5120 + r * SM_STRIDE + seg) * 2;
            const __half* gp;
            int sz = 16;
            if (mat < 2) {
                int gr = bm + r;
                if (gr >= M) { sz = 0; gr = M - 1; }
                gp = (mat == 0 ? Ah : Al) + (size_t)gr * K + k0 + seg;
            } else {
                gp = W + (size_t)(bn + r) * K + k0 + seg;
            }
            asm volatile("cp.async.cg.shared.global [%0], [%1], 16, %2;"
                         :: "r"(sa), "l"(gp), "r"(sz));
        }
        asm volatile("cp.async.commit_group;" ::: "memory");
    };

    issue(0);
    for (int c = 0; c < NC; c++) {
        if (c + 1 < NC) {
            issue(c + 1);
            asm volatile("cp.async.wait_group 1;" ::: "memory");
        } else {
            asm volatile("cp.async.wait_group 0;" ::: "memory");
        }
        __syncthreads();

        const uint32_t st = sbase + (uint32_t)(c & 1) * (STAGE_ELE * 2);
        #pragma unroll
        for (int ks = 0; ks < 2; ks++) {
            uint32_t ah[2][4], al[2][4], bb[4][4];
            #pragma unroll
            for (int mt = 0; mt < 2; mt++) {
                uint32_t off = (uint32_t)((a_row + mt * 16) * SM_STRIDE + ks * 16 + a_kc) * 2;
                ldm4(ah[mt], st + off);
                ldm4(al[mt], st + 10240 + off);
            }
            #pragma unroll
            for (int bt = 0; bt < 4; bt++) {
                uint32_t off = (uint32_t)((b_row + bt * 16) * SM_STRIDE + ks * 16 + b_kc) * 2;
                ldm4(bb[bt], st + 20480 + off);
            }
            #pragma unroll
            for (int mt = 0; mt < 2; mt++)
                #pragma unroll
                for (int nt = 0; nt < 8; nt++) {
                    mma_hf(acc[mt][nt], ah[mt], bb[nt >> 1][(nt & 1) * 2], bb[nt >> 1][(nt & 1) * 2 + 1]);
                    mma_hf(acc[mt][nt], al[mt], bb[nt >> 1][(nt & 1) * 2], bb[nt >> 1][(nt & 1) * 2 + 1]);
                }
        }
        __syncthreads();
    }

    #pragma unroll
    for (int mt = 0; mt < 2; mt++) {
        int rb = bm + warpM * 32 + mt * 16 + (lane >> 2);
        #pragma unroll
        for (int half = 0; half < 2; half++) {
            int rr = rb + half * 8;
            if (rr >= M) continue;
            #pragma unroll
            for (int nt = 0; nt < 8; nt++) {
                int col = bn + warpN * 64 + nt * 8 + ((lane & 3) << 1);
                size_t o = (size_t)rr * Nn + col;
                if (nsplit > 1) {
                    *(float2*)(part + (size_t)kz * ((size_t)M * Nn) + o) =
                        make_float2(acc[mt][nt][half * 2 + 0], acc[mt][nt][half * 2 + 1]);
                    continue;
                }
                float v0 = acc[mt][nt][half * 2 + 0] + bias[col];
                float v1 = acc[mt][nt][half * 2 + 1] + bias[col + 1];
                if (act) { v0 = v0 * normcdff(v0); v1 = v1 * normcdff(v1); }
                if (Ch) {
                    __half h0 = __float2half_rn(v0), h1 = __float2half_rn(v1);
                    *(uint32_t*)(Ch + o) = (uint32_t)__half_as_ushort(h0) | ((uint32_t)__half_as_ushort(h1) << 16);
                    *(uint32_t*)(Cl + o) = pack_hf2(v0 - __half2float(h0), v1 - __half2float(h1));
                } else {
                    *(float2*)(Cf + o) = make_float2(v0, v1);
                }
            }
        }
    }
}

// ---------------- QKV post ----------------
__global__ void qkvpost_kernel(const float* __restrict__ part, const float* __restrict__ qb,
                               const float* __restrict__ qn, const float* __restrict__ kn,
                               const float* __restrict__ rc, const float* __restrict__ rs,
                               __half* __restrict__ Qh, __half* __restrict__ Ql,
                               __half* __restrict__ Kh, __half* __restrict__ Vh,
                               int posmod)
{
    int gw = (blockIdx.x * blockDim.x + threadIdx.x) >> 5;
    int lane = threadIdx.x & 31;
    int t = gw / NHEAD, h = gw - (gw / NHEAD) * NHEAD;
    if (t >= T_TOT) return;
    const float* r0 = part + (size_t)t * 2304 + h * 64;
    const float* r1 = r0 + QKV_PART_STRIDE;
    const float* bb = qb + h * 64;
    float q0 = r0[lane] + r1[lane] + bb[lane];
    float q1 = r0[lane + 32] + r1[lane + 32] + bb[lane + 32];
    float k0 = r0[768 + lane] + r1[768 + lane] + qb[768 + h * 64 + lane];
    float k1 = r0[768 + lane + 32] + r1[768 + lane + 32] + qb[768 + h * 64 + lane + 32];
    float v0 = r0[1536 + lane] + r1[1536 + lane] + qb[1536 + h * 64 + lane];
    float v1 = r0[1536 + lane + 32] + r1[1536 + lane + 32] + qb[1536 + h * 64 + lane + 32];
    float sq = q0 * q0 + q1 * q1, sk = k0 * k0 + k1 * k1;
    #pragma unroll
    for (int off = 16; off; off >>= 1) {
        sq += __shfl_xor_sync(0xffffffffu, sq, off);
        sk += __shfl_xor_sync(0xffffffffu, sk, off);
    }
    float rq = rsqrtf(sq * (1.f / 64.f) + 1e-6f);
    float rk = rsqrtf(sk * (1.f / 64.f) + 1e-6f);
    q0 *= rq * qn[lane]; q1 *= rq * qn[lane + 32];
    k0 *= rk * kn[lane]; k1 *= rk * kn[lane + 32];
    int pos = t % posmod;
    const float* cr = rc + (size_t)pos * 64;
    const float* sr = rs + (size_t)pos * 64;
    float c0 = cr[lane], c1 = cr[lane + 32];
    float s0 = sr[lane], s1 = sr[lane + 32];
    float sgn = (lane < 16) ? -1.f : 1.f;
    float qp0 = __shfl_xor_sync(0xffffffffu, q0, 16);
    float qp1 = __shfl_xor_sync(0xffffffffu, q1, 16);
    float kp0 = __shfl_xor_sync(0xffffffffu, k0, 16);
    float kp1 = __shfl_xor_sync(0xffffffffu, k1, 16);
    float qo0 = (q0 * c0 + sgn * qp0 * s0) * 0.125f;
    float qo1 = (q1 * c1 + sgn * qp1 * s1) * 0.125f;
    float ko0 = k0 * c0 + sgn * kp0 * s0;
    float ko1 = k1 * c1 + sgn * kp1 * s1;
    size_t base = ((size_t)h * T_TOT + t) * 64;
    __half hh;
    hh = __float2half_rn(qo0); Qh[base + lane] = hh;      Ql[base + lane]      = __float2half_rn(qo0 - __half2float(hh));
    hh = __float2half_rn(qo1); Qh[base + 32 + lane] = hh; Ql[base + 32 + lane] = __float2half_rn(qo1 - __half2float(hh));
    Kh[base + lane]      = __float2half_rn(ko0);
    Kh[base + 32 + lane] = __float2half_rn(ko1);
    Vh[base + lane]      = __float2half_rn(v0);
    Vh[base + 32 + lane] = __float2half_rn(v1);
}

// ---------------- fp16 tensor-core flash attention ----------------
#define ATT_STRIDE 72
#define A_QH 0
#define A_QL 4608
#define A_STG 9216
#define A_STG_ELE 9216
#define ATT_SMEM (27648 * 2)

__global__ __launch_bounds__(128) void attn_mma(
    const __half* __restrict__ Qh, const __half* __restrict__ Ql,
    const __half* __restrict__ Kh, const __half* __restrict__ Vh,
    const float* __restrict__ kvmask,
    __half* __restrict__ Oh, __half* __restrict__ Ol, int nq)
{
    extern __shared__ __align__(16) uint16_t smA[];
    const int tid = threadIdx.x, wid = tid >> 5, lane = tid & 31;
    const int qt = blockIdx.x, h = blockIdx.y, z = blockIdx.z;
    const int t0 = z * nq;
    const size_t hb = (size_t)h * T_TOT * 64;
    const uint32_t sbase = smem_u32(smA);
    const float* kvrow = kvmask + (size_t)z * nq;

    for (int i = tid; i < 512; i += 128) {
        int r = i >> 3, sg = i & 7;
        int qrow = qt * 64 + r;
        uint4 vh = make_uint4(0, 0, 0, 0), vl = make_uint4(0, 0, 0, 0);
        if (qrow < nq) {
            size_t go = hb + (size_t)(t0 + qrow) * 64 + sg * 8;
            vh = *(const uint4*)(Qh + go);
            vl = *(const uint4*)(Ql + go);
        }
        *(uint4*)((char*)smA + (A_QH + r * ATT_STRIDE + sg * 8) * 2) = vh;
        *(uint4*)((char*)smA + (A_QL + r * ATT_STRIDE + sg * 8) * 2) = vl;
    }
    __syncthreads();

    uint32_t qhf[4][4], qlf[4][4];
    {
        int arow = wid * 16 + (lane & 15);
        int akc = (lane >> 4) * 8;
        #pragma unroll
        for (int kc = 0; kc < 4; kc++) {
            uint32_t off = (uint32_t)(arow * ATT_STRIDE + kc * 16 + akc) * 2;
            ldm4(qhf[kc], sbase + A_QH * 2 + off);
            ldm4(qlf[kc], sbase + A_QL * 2 + off);
        }
    }

    auto stage_load = [&](int kt) {
        int s = kt & 1;
        uint32_t sb = sbase + (uint32_t)(A_STG + s * A_STG_ELE) * 2;
        int kbase = kt * 64;
        #pragma unroll
        for (int it = 0; it < 8; it++) {
            int i = tid + it * 128;
            int m = i >> 9, v = i & 511, r = v >> 3, sg = v & 7;
            int key = kbase + r;
            int sz = 16;
            if (key >= nq) { sz = 0; key = nq - 1; }
            const __half* gp = (m == 0 ? Kh : Vh) + hb + (size_t)(t0 + key) * 64 + sg * 8;
            uint32_t da = sb + (uint32_t)(m * 4608 + r * ATT_STRIDE + sg * 8) * 2;
            asm volatile("cp.async.cg.shared.global [%0], [%1], 16, %2;"
                         :: "r"(da), "l"(gp), "r"(sz));
        }
        asm volatile("cp.async.commit_group;" ::: "memory");
    };

    float o[8][4];
    #pragma unroll
    for (int i = 0; i < 8; i++)
        #pragma unroll
        for (int j = 0; j < 4; j++) o[i][j] = 0.f;
    float m0 = -1e30f, m1 = -1e30f, l0 = 0.f, l1 = 0.f;

    const int nkt = (nq + 63) >> 6;
    const int brow = ((lane >> 4) & 1) * 8 + (lane & 7);
    const int bkc = ((lane >> 3) & 1) * 8;
    const int vr0 = ((lane >> 3) & 1) * 8 + (lane & 7);
    const int vc0 = (lane >> 4) * 8;

    stage_load(0);
    for (int kt = 0; kt < nkt; kt++) {
        if (kt + 1 < nkt) {
            stage_load(kt + 1);
            asm volatile("cp.async.wait_group 1;" ::: "memory");
        } else {
            asm volatile("cp.async.wait_group 0;" ::: "memory");
        }
        __syncthreads();
        uint32_t sb = sbase + (uint32_t)(A_STG + (kt & 1) * A_STG_ELE) * 2;
        int kbase = kt * 64;

        float s_[8][4];
        #pragma unroll
        for (int nt = 0; nt < 8; nt++) {
            int key = kbase + nt * 8 + ((lane & 3) << 1);
            float b0 = (key < nq) ? (1.f - kvrow[key]) * -10000.f : -1e30f;
            float b1 = (key + 1 < nq) ? (1.f - kvrow[key + 1]) * -10000.f : -1e30f;
            s_[nt][0] = b0; s_[nt][1] = b1; s_[nt][2] = b0; s_[nt][3] = b1;
        }
        #pragma unroll
        for (int np = 0; np < 4; np++) {
            #pragma unroll
            for (int kc = 0; kc < 4; kc++) {
                uint32_t off = (uint32_t)((np * 16 + brow) * ATT_STRIDE + kc * 16 + bkc) * 2;
                uint32_t kh4[4];
                ldm4(kh4, sb + off);
                mma_hf(s_[2 * np],     qhf[kc], kh4[0], kh4[1]);
                mma_hf(s_[2 * np + 1], qhf[kc], kh4[2], kh4[3]);
                mma_hf(s_[2 * np],     qlf[kc], kh4[0], kh4[1]);
                mma_hf(s_[2 * np + 1], qlf[kc], kh4[2], kh4[3]);
            }
        }
        float mx0 = -1e30f, mx1 = -1e30f;
        #pragma unroll
        for (int nt = 0; nt < 8; nt++) {
            mx0 = fmaxf(mx0, fmaxf(s_[nt][0], s_[nt][1]));
            mx1 = fmaxf(mx1, fmaxf(s_[nt][2], s_[nt][3]));
        }
        mx0 = fmaxf(mx0, __shfl_xor_sync(0xffffffffu, mx0, 1));
        mx0 = fmaxf(mx0, __shfl_xor_sync(0xffffffffu, mx0, 2));
        mx1 = fmaxf(mx1, __shfl_xor_sync(0xffffffffu, mx1, 1));
        mx1 = fmaxf(mx1, __shfl_xor_sync(0xffffffffu, mx1, 2));
        float mn0 = fmaxf(m0, mx0), mn1 = fmaxf(m1, mx1);
        float sc0 = __expf(m0 - mn0), sc1 = __expf(m1 - mn1);
        m0 = mn0; m1 = mn1;
        float ps0 = 0.f, ps1 = 0.f;
        #pragma unroll
        for (int nt = 0; nt < 8; nt++) {
            s_[nt][0] = __expf(s_[nt][0] - mn0); ps0 += s_[nt][0];
            s_[nt][1] = __expf(s_[nt][1] - mn0); ps0 += s_[nt][1];
            s_[nt][2] = __expf(s_[nt][2] - mn1); ps1 += s_[nt][2];
            s_[nt][3] = __expf(s_[nt][3] - mn1); ps1 += s_[nt][3];
        }
        ps0 += __shfl_xor_sync(0xffffffffu, ps0, 1);
        ps0 += __shfl_xor_sync(0xffffffffu, ps0, 2);
        ps1 += __shfl_xor_sync(0xffffffffu, ps1, 1);
        ps1 += __shfl_xor_sync(0xffffffffu, ps1, 2);
        l0 = l0 * sc0 + ps0;
        l1 = l1 * sc1 + ps1;
        #pragma unroll
        for (int nt = 0; nt < 8; nt++) {
            o[nt][0] *= sc0; o[nt][1] *= sc0; o[nt][2] *= sc1; o[nt][3] *= sc1;
        }
        uint32_t pfh[4][4], pfl[4][4];
        #pragma unroll
        for (int kc = 0; kc < 4; kc++) {
            #pragma unroll
            for (int q = 0; q < 4; q++) {
                float a = s_[2 * kc + (q >> 1)][(q & 1) * 2];
                float b = s_[2 * kc + (q >> 1)][(q & 1) * 2 + 1];
                __half ha = __float2half_rn(a), hb2 = __float2half_rn(b);
                pfh[kc][q] = (uint32_t)__half_as_ushort(ha) | ((uint32_t)__half_as_ushort(hb2) << 16);
                pfl[kc][q] = pack_hf2(a - __half2float(ha), b - __half2float(hb2));
            }
        }
        #pragma unroll
        for (int kc = 0; kc < 4; kc++) {
            #pragma unroll
            for (int dp = 0; dp < 4; dp++) {
                uint32_t off = (uint32_t)((kc * 16 + vr0) * ATT_STRIDE + dp * 16 + vc0) * 2;
                uint32_t vh4[4];
                ldm4t(vh4, sb + 4608 * 2 + off);
                mma_hf(o[2 * dp],     pfh[kc], vh4[0], vh4[1]);
                mma_hf(o[2 * dp + 1], pfh[kc], vh4[2], vh4[3]);
                mma_hf(o[2 * dp],     pfl[kc], vh4[0], vh4[1]);
                mma_hf(o[2 * dp + 1], pfl[kc], vh4[2], vh4[3]);
            }
        }
        __syncthreads();
    }

    float inv0 = 1.f / l0, inv1 = 1.f / l1;
    int r = lane >> 2;
    int q0row = qt * 64 + wid * 16 + r;
    int q1row = q0row + 8;
    #pragma unroll
    for (int nt = 0; nt < 8; nt++) {
        int d = nt * 8 + ((lane & 3) << 1);
        if (q0row < nq) {
            float a = o[nt][0] * inv0, b = o[nt][1] * inv0;
            size_t ob = (size_t)(t0 + q0row) * C_DIM + h * 64 + d;
            __half ha = __float2half_rn(a), hb2 = __float2half_rn(b);
            *(uint32_t*)(Oh + ob) = (uint32_t)__half_as_ushort(ha) | ((uint32_t)__half_as_ushort(hb2) << 16);
            *(uint32_t*)(Ol + ob) = pack_hf2(a - __half2float(ha), b - __half2float(hb2));
        }
        if (q1row < nq) {
            float a = o[nt][2] * inv1, b = o[nt][3] * inv1;
            size_t ob = (size_t)(t0 + q1row) * C_DIM + h * 64 + d;
            __half ha = __float2half_rn(a), hb2 = __float2half_rn(b);
            *(uint32_t*)(Oh + ob) = (uint32_t)__half_as_ushort(ha) | ((uint32_t)__half_as_ushort(hb2) << 16);
            *(uint32_t*)(Ol + ob) = pack_hf2(a - __half2float(ha), b - __half2float(hb2));
        }
    }
}

// ---------------- emit output ----------------
__global__ __launch_bounds__(256) void emit_kernel(const float* __restrict__ xloc, const float* __restrict__ xg,
                                                   const float* __restrict__ fw, const float* __restrict__ fb,
                                                   float* __restrict__ out)
{
    __shared__ float sh[8];
    int row = blockIdx.x;
    int s = row / 576, n = row - s * 576 + 1;
    int t = s * 577 + n;
    int tid = threadIdx.x;
    const float* xr = xg + (size_t)t * C_DIM;
    float v0 = xr[tid], v1 = xr[tid + 256], v2 = xr[tid + 512];
    float mean = block_sum_256(v0 + v1 + v2, sh) * (1.f / 768.f);
    float d0 = v0 - mean, d1 = v1 - mean, d2 = v2 - mean;
    float var = block_sum_256(d0 * d0 + d1 * d1 + d2 * d2, sh) * (1.f / 768.f);
    float rstd = rsqrtf(var + 1e-6f);
    const float* lr = xloc + (size_t)t * C_DIM;
    float* orow = out + (size_t)row * 1536;
    orow[tid]       = lr[tid];
    orow[tid + 256] = lr[tid + 256];
    orow[tid + 512] = lr[tid + 512];
    orow[768 + tid]       = d0 * rstd * fw[tid]       + fb[tid];
    orow[768 + tid + 256] = d1 * rstd * fw[tid + 256] + fb[tid + 256];
    orow[768 + tid + 512] = d2 * rstd * fw[tid + 512] + fb[tid + 512];
}

__global__ void cam_kernel(const float* __restrict__ xloc, const float* __restrict__ xg,
                           float* __restrict__ out) {
    int s = blockIdx.x;
    int t = s * 577;
    for (int c = threadIdx.x; c < C_DIM; c += 256) {
        out[s * 1536 + c]       = xloc[(size_t)t * C_DIM + c];
        out[s * 1536 + 768 + c] = xg[(size_t)t * C_DIM + c];
    }
}

// ---------------- host orchestration ----------------
extern "C" void kernel_launch(void* const* d_in, const int* in_sizes, int n_in,
                              void* d_out, int out_size)
{
    const float* x_in  = (const float*)d_in[0];
    const float* rc_l  = (const float*)d_in[1];
    const float* rs_l  = (const float*)d_in[2];
    const float* rc_g  = (const float*)d_in[3];
    const float* rs_g  = (const float*)d_in[4];
    const float* kv_l  = (const float*)d_in[5];
    const float* kv_g  = (const float*)d_in[6];
    const float* cam   = (const float*)d_in[7];
    const float* qkv_w = (const float*)d_in[8];
    const float* qkv_b = (const float*)d_in[9];
    const float* qn_w  = (const float*)d_in[10];
    const float* kn_w  = (const float*)d_in[11];
    const float* pw    = (const float*)d_in[12];
    const float* pb    = (const float*)d_in[13];
    const float* g1    = (const float*)d_in[14];
    const float* g2    = (const float*)d_in[15];
    const float* n1w   = (const float*)d_in[16];
    const float* n1b   = (const float*)d_in[17];
    const float* n2w   = (const float*)d_in[18];
    const float* n2b   = (const float*)d_in[19];
    const float* f1w   = (const float*)d_in[20];
    const float* f1b   = (const float*)d_in[21];
    const float* f2w   = (const float*)d_in[22];
    const float* f2b   = (const float*)d_in[23];
    const float* fnw   = (const float*)d_in[24];
    const float* fnb   = (const float*)d_in[25];
    float* out = (float*)d_out;

    float *p_x, *p_loc, *p_part;
    __half *p_w, *p_sh, *p_sl, *p_mh, *p_ml, *p_qh, *p_ql, *p_kh, *p_vh;
    cudaGetSymbolAddress((void**)&p_x,   g_x);
    cudaGetSymbolAddress((void**)&p_loc, g_loc);
    cudaGetSymbolAddress((void**)&p_part, g_part);
    cudaGetSymbolAddress((void**)&p_w,   g_w);
    cudaGetSymbolAddress((void**)&p_sh,  g_sh);
    cudaGetSymbolAddress((void**)&p_sl,  g_sl);
    cudaGetSymbolAddress((void**)&p_mh,  g_mh);
    cudaGetSymbolAddress((void**)&p_ml,  g_ml);
    cudaGetSymbolAddress((void**)&p_qh,  g_qh);
    cudaGetSymbolAddress((void**)&p_ql,  g_ql);
    cudaGetSymbolAddress((void**)&p_kh,  g_kh);
    cudaGetSymbolAddress((void**)&p_vh,  g_vh);

    cudaFuncSetAttribute(gemm_mma, cudaFuncAttributeMaxDynamicSharedMemorySize, GEMM_SMEM);
    cudaFuncSetAttribute(attn_mma, cudaFuncAttributeMaxDynamicSharedMemorySize, ATT_SMEM);

    const int eb = (NE + 255) / 256;
    convall_kernel<<<(W_TOTAL / 4 + 255) / 256, 256>>>(qkv_w, pw, f1w, f2w, p_w);
    init_x_kernel<<<eb, 256>>>(x_in, cam);

    int outidx = 0;
    for (int i = 0; i < 12; i++) {
        bool isg = (i & 1);
        int nb = isg ? 1 : 2;
        int nq = isg ? 1154 : 577;
        const float* rc = isg ? rc_g : rc_l;
        const float* rs = isg ? rs_g : rs_l;
        const float* kv = isg ? kv_g : kv_l;

        if (i == 0)
            ln_kernel<<<T_TOT, 256>>>(p_x, p_sh, p_sl, n1w, n1b);
        gemm_mma<<<dim3(18, 10, 2), 256, GEMM_SMEM>>>(
            p_sh, p_sl, p_w + W_QKV_OFF + (size_t)i * 2304 * 768,
            nullptr, nullptr, nullptr, nullptr, p_part, T_TOT, 2304, 768, 0, 2);
        qkvpost_kernel<<<(T_TOT * NHEAD * 32 + 127) / 128, 128>>>(
            p_part, qkv_b + i * 2304, qn_w + i * 64, kn_w + i * 64, rc, rs,
            p_qh, p_ql, p_kh, p_vh, nq);
        attn_mma<<<dim3((nq + 63) / 64, NHEAD, nb), 128, ATT_SMEM>>>(
            p_qh, p_ql, p_kh, p_vh, kv, p_sh, p_sl, nq);
        gemm_mma<<<dim3(6, 10, 2), 256, GEMM_SMEM>>>(
            p_sh, p_sl, p_w + W_PROJ_OFF + (size_t)i * 768 * 768,
            nullptr, nullptr, nullptr, nullptr, p_part, T_TOT, 768, 768, 0, 2);
        combine_ln_kernel<<<T_TOT, 256>>>(p_x, p_part, pb + i * 768, g1 + i * 768, 2,
                                          n2w + i * 768, n2b + i * 768, p_sh, p_sl, nullptr);
        gemm_mma<<<dim3(24, 10, 1), 256, GEMM_SMEM>>>(
            p_sh, p_sl, p_w + W_FC1_OFF + (size_t)i * 3072 * 768,
            f1b + i * 3072, nullptr, p_mh, p_ml, nullptr, T_TOT, 3072, 768, 1, 1);
        gemm_mma<<<dim3(6, 10, 4), 256, GEMM_SMEM>>>(
            p_mh, p_ml, p_w + W_FC2_OFF + (size_t)i * 768 * 3072,
            nullptr, nullptr, nullptr, nullptr, p_part, T_TOT, 768, 3072, 0, 4);
        if (i < 11) {
            float* locp = (i == 4 || i == 10) ? p_loc : nullptr;
            combine_ln_kernel<<<T_TOT, 256>>>(p_x, p_part, f2b + i * 768, g2 + i * 768, 4,
                                              n1w + (i + 1) * 768, n1b + (i + 1) * 768, p_sh, p_sl, locp);
        } else {
            combine_kernel<<<eb, 256>>>(p_x, p_part, f2b + i * 768, g2 + i * 768, 4);
        }

        if (i == 2 || i == 5 || i == 8 || i == 11) {
            const float* loc = (i == 5 || i == 11) ? p_loc : p_x;
            emit_kernel<<<1152, 256>>>(loc, p_x, fnw, fnb, out + (size_t)outidx * 1769472);
            if (i == 11) cam_kernel<<<2, 256>>>(loc, p_x, out + 4ull * 1769472);
            outidx++;
        }
    }
}